// round 1
// baseline (speedup 1.0000x reference)
#include <cuda_runtime.h>
#include <math.h>

#define NB 2
#define NS 1024
#define ND 1024
#define NH 16
#define NHD 64
#define NE 8
#define NF 4096
#define NT 2048

// ---------------- scratch (device globals; no allocations allowed) ----------
__device__ float g_q[NT * ND];
__device__ float g_k[NT * ND];
__device__ float g_v[NT * ND];
__device__ float g_scalef[NB * NH * NS];
__device__ float g_attn[NT * ND];
__device__ float g_gated[NT * ND];
__device__ float g_xres[NT * ND];
__device__ float g_x[NT * ND];
__device__ float g_z[NT * ND];
__device__ float g_h[(size_t)NT * NF];
__device__ int g_esel[NT];
__device__ int g_perm[NT];
__device__ int g_eid[NT];
__device__ int g_off[NE];
__device__ int g_cnt[NE];

// ---------------- shared 64x64 tiled fp32 GEMM core -------------------------
// acc[4][4] per thread, 256 threads (tx=tid&15, ty=tid>>4), K step 16.
// rowsIdx != nullptr: gathered A rows (shared array of 64 ints, -1 = zero row).
__device__ __forceinline__ void gemm64(const float* __restrict__ A,
                                       const float* __restrict__ Bm,
                                       int Mvalid, int K, int N,
                                       int row0, int col0,
                                       const int* __restrict__ rowsIdx,
                                       float acc[4][4])
{
    __shared__ float As[64][17];
    __shared__ float Bs[16][64];
    const int tx = threadIdx.x & 15;
    const int ty = threadIdx.x >> 4;
    for (int k0 = 0; k0 < K; k0 += 16) {
#pragma unroll
        for (int l = 0; l < 4; l++) {
            int lin = threadIdx.x + l * 256;
            int m = lin >> 4, kk = lin & 15;
            float v = 0.f;
            if (rowsIdx) {
                int r = rowsIdx[m];
                if (r >= 0) v = A[(size_t)r * K + k0 + kk];
            } else {
                int r = row0 + m;
                if (r < Mvalid) v = A[(size_t)r * K + k0 + kk];
            }
            As[m][kk] = v;
        }
#pragma unroll
        for (int l = 0; l < 4; l++) {
            int lin = threadIdx.x + l * 256;
            int kk = lin >> 6, n = lin & 63;
            Bs[kk][n] = Bm[(size_t)(k0 + kk) * N + col0 + n];
        }
        __syncthreads();
#pragma unroll
        for (int kk = 0; kk < 16; kk++) {
            float a0 = As[ty * 4 + 0][kk];
            float a1 = As[ty * 4 + 1][kk];
            float a2 = As[ty * 4 + 2][kk];
            float a3 = As[ty * 4 + 3][kk];
            float4 bv = *(const float4*)&Bs[kk][tx * 4];
            acc[0][0] += a0 * bv.x; acc[0][1] += a0 * bv.y; acc[0][2] += a0 * bv.z; acc[0][3] += a0 * bv.w;
            acc[1][0] += a1 * bv.x; acc[1][1] += a1 * bv.y; acc[1][2] += a1 * bv.z; acc[1][3] += a1 * bv.w;
            acc[2][0] += a2 * bv.x; acc[2][1] += a2 * bv.y; acc[2][2] += a2 * bv.z; acc[2][3] += a2 * bv.w;
            acc[3][0] += a3 * bv.x; acc[3][1] += a3 * bv.y; acc[3][2] += a3 * bv.z; acc[3][3] += a3 * bv.w;
        }
        __syncthreads();
    }
}

// ---------------- block reduction (sum pair) ---------------------------------
__device__ __forceinline__ void blk_reduce2(float& s, float& q)
{
    __shared__ float ss[8], sq[8];
#pragma unroll
    for (int o = 16; o; o >>= 1) {
        s += __shfl_xor_sync(0xffffffffu, s, o);
        q += __shfl_xor_sync(0xffffffffu, q, o);
    }
    int w = threadIdx.x >> 5, l = threadIdx.x & 31;
    if (l == 0) { ss[w] = s; sq[w] = q; }
    __syncthreads();
    s = (l < 8) ? ss[l] : 0.f;
    q = (l < 8) ? sq[l] : 0.f;
#pragma unroll
    for (int o = 4; o; o >>= 1) {
        s += __shfl_xor_sync(0xffffffffu, s, o);
        q += __shfl_xor_sync(0xffffffffu, q, o);
    }
    s = __shfl_sync(0xffffffffu, s, 0);
    q = __shfl_sync(0xffffffffu, q, 0);
}

// ---------------- kernels ----------------------------------------------------

__global__ __launch_bounds__(256) void k_gemm_qkv(const float* __restrict__ src,
                                                  const float* __restrict__ qw,
                                                  const float* __restrict__ kw,
                                                  const float* __restrict__ vw)
{
    const float* W = (blockIdx.z == 0) ? qw : (blockIdx.z == 1) ? kw : vw;
    float* C = (blockIdx.z == 0) ? g_q : (blockIdx.z == 1) ? g_k : g_v;
    int row0 = blockIdx.y * 64, col0 = blockIdx.x * 64;
    float acc[4][4] = {};
    gemm64(src, W, NT, ND, ND, row0, col0, nullptr, acc);
    int tx = threadIdx.x & 15, ty = threadIdx.x >> 4;
#pragma unroll
    for (int i = 0; i < 4; i++)
#pragma unroll
        for (int j = 0; j < 4; j++)
            C[(size_t)(row0 + ty * 4 + i) * ND + col0 + tx * 4 + j] = acc[i][j];
}

// per-(token,head) scale factor: 0.125 * 2 * sigmoid(q . scale_w[h])
__global__ __launch_bounds__(256) void k_qscale(const float* __restrict__ sw)
{
    int wid = blockIdx.x * 8 + (threadIdx.x >> 5);
    int lane = threadIdx.x & 31;
    int h = wid & (NH - 1), t = wid >> 4;
    float s = g_q[(size_t)t * ND + h * 64 + lane] * sw[h * 64 + lane]
            + g_q[(size_t)t * ND + h * 64 + lane + 32] * sw[h * 64 + lane + 32];
#pragma unroll
    for (int o = 16; o; o >>= 1) s += __shfl_xor_sync(0xffffffffu, s, o);
    if (lane == 0) {
        float sig = 1.f / (1.f + expf(-s));
        int b = t >> 10, si = t & (NS - 1);
        g_scalef[(b * NH + h) * NS + si] = 0.25f * sig;  // 0.125 * 2 * sigmoid
    }
}

// flash attention: 64 queries x 32-key tiles, online softmax, HD=64.
__global__ __launch_bounds__(256) void k_flash()
{
    __shared__ float Qs[64][65];
    __shared__ float Ks[32][65];  // also reused to hold P^T (32 keys x 64 rows)
    __shared__ float Vs[32][65];
    int bh = blockIdx.y;
    int b = bh >> 4, h = bh & 15;
    int row0 = blockIdx.x * 64;
    int tx = threadIdx.x & 15, ty = threadIdx.x >> 4;

    // load Q tile scaled by 0.125 * 2 * sigmoid(...)
#pragma unroll
    for (int l = 0; l < 16; l++) {
        int lin = threadIdx.x + l * 256;
        int m = lin >> 6, d = lin & 63;
        float sc = g_scalef[bh * NS + row0 + m];
        Qs[m][d] = g_q[(size_t)(b * NS + row0 + m) * ND + h * 64 + d] * sc;
    }

    float mi[4], li[4], o[4][4];
#pragma unroll
    for (int i = 0; i < 4; i++) {
        mi[i] = -1e30f; li[i] = 0.f;
#pragma unroll
        for (int j = 0; j < 4; j++) o[i][j] = 0.f;
    }

    for (int jt = 0; jt < NS / 32; jt++) {
        __syncthreads();  // protect Ks/Vs from previous iteration readers
#pragma unroll
        for (int l = 0; l < 8; l++) {
            int lin = threadIdx.x + l * 256;
            int nn = lin >> 6, d = lin & 63;
            Ks[nn][d] = g_k[(size_t)(b * NS + jt * 32 + nn) * ND + h * 64 + d];
            Vs[nn][d] = g_v[(size_t)(b * NS + jt * 32 + nn) * ND + h * 64 + d];
        }
        __syncthreads();

        // S tile: rows ty*4+i, cols tx*2+jj
        float s[4][2] = {};
#pragma unroll
        for (int d = 0; d < 64; d++) {
            float a0 = Qs[ty * 4 + 0][d];
            float a1 = Qs[ty * 4 + 1][d];
            float a2 = Qs[ty * 4 + 2][d];
            float a3 = Qs[ty * 4 + 3][d];
            float k0 = Ks[tx * 2 + 0][d];
            float k1 = Ks[tx * 2 + 1][d];
            s[0][0] += a0 * k0; s[0][1] += a0 * k1;
            s[1][0] += a1 * k0; s[1][1] += a1 * k1;
            s[2][0] += a2 * k0; s[2][1] += a2 * k1;
            s[3][0] += a3 * k0; s[3][1] += a3 * k1;
        }

        float p[4][2];
        float rm[4], rs[4];
#pragma unroll
        for (int i = 0; i < 4; i++) {
            rm[i] = fmaxf(s[i][0], s[i][1]);
#pragma unroll
            for (int off = 8; off; off >>= 1)
                rm[i] = fmaxf(rm[i], __shfl_xor_sync(0xffffffffu, rm[i], off));
            float mnew = fmaxf(mi[i], rm[i]);
            float alpha = expf(mi[i] - mnew);
            p[i][0] = expf(s[i][0] - mnew);
            p[i][1] = expf(s[i][1] - mnew);
            rs[i] = p[i][0] + p[i][1];
#pragma unroll
            for (int off = 8; off; off >>= 1)
                rs[i] += __shfl_xor_sync(0xffffffffu, rs[i], off);
            li[i] = li[i] * alpha + rs[i];
            mi[i] = mnew;
#pragma unroll
            for (int j = 0; j < 4; j++) o[i][j] *= alpha;
        }

        __syncthreads();  // all threads done reading Ks for S
        // store P transposed into Ks: Ks[key][row]
#pragma unroll
        for (int i = 0; i < 4; i++) {
            Ks[tx * 2 + 0][ty * 4 + i] = p[i][0];
            Ks[tx * 2 + 1][ty * 4 + i] = p[i][1];
        }
        __syncthreads();

        // O += P @ V   (cols now = head dim, tx*4+j)
#pragma unroll
        for (int n = 0; n < 32; n++) {
            float a0 = Ks[n][ty * 4 + 0];
            float a1 = Ks[n][ty * 4 + 1];
            float a2 = Ks[n][ty * 4 + 2];
            float a3 = Ks[n][ty * 4 + 3];
            float v0 = Vs[n][tx * 4 + 0];
            float v1 = Vs[n][tx * 4 + 1];
            float v2 = Vs[n][tx * 4 + 2];
            float v3 = Vs[n][tx * 4 + 3];
            o[0][0] += a0 * v0; o[0][1] += a0 * v1; o[0][2] += a0 * v2; o[0][3] += a0 * v3;
            o[1][0] += a1 * v0; o[1][1] += a1 * v1; o[1][2] += a1 * v2; o[1][3] += a1 * v3;
            o[2][0] += a2 * v0; o[2][1] += a2 * v1; o[2][2] += a2 * v2; o[2][3] += a2 * v3;
            o[3][0] += a3 * v0; o[3][1] += a3 * v1; o[3][2] += a3 * v2; o[3][3] += a3 * v3;
        }
    }

#pragma unroll
    for (int i = 0; i < 4; i++) {
        float inv = 1.f / li[i];
#pragma unroll
        for (int j = 0; j < 4; j++)
            g_attn[(size_t)(b * NS + row0 + ty * 4 + i) * ND + h * 64 + tx * 4 + j] = o[i][j] * inv;
    }
}

__global__ __launch_bounds__(256) void k_gemm_gate(const float* __restrict__ gw,
                                                    const float* __restrict__ gb)
{
    int row0 = blockIdx.y * 64, col0 = blockIdx.x * 64;
    float acc[4][4] = {};
    gemm64(g_attn, gw, NT, ND, ND, row0, col0, nullptr, acc);
    int tx = threadIdx.x & 15, ty = threadIdx.x >> 4;
#pragma unroll
    for (int i = 0; i < 4; i++)
#pragma unroll
        for (int j = 0; j < 4; j++) {
            int c = col0 + tx * 4 + j;
            size_t idx = (size_t)(row0 + ty * 4 + i) * ND + c;
            float g = 1.f / (1.f + expf(-(acc[i][j] + gb[c])));
            g_gated[idx] = g_attn[idx] * g;
        }
}

__global__ __launch_bounds__(256) void k_gemm_ow(const float* __restrict__ oww,
                                                  const float* __restrict__ src)
{
    int row0 = blockIdx.y * 64, col0 = blockIdx.x * 64;
    float acc[4][4] = {};
    gemm64(g_gated, oww, NT, ND, ND, row0, col0, nullptr, acc);
    int tx = threadIdx.x & 15, ty = threadIdx.x >> 4;
#pragma unroll
    for (int i = 0; i < 4; i++)
#pragma unroll
        for (int j = 0; j < 4; j++) {
            size_t idx = (size_t)(row0 + ty * 4 + i) * ND + col0 + tx * 4 + j;
            g_xres[idx] = src[idx] + acc[i][j];
        }
}

__device__ __forceinline__ void ln1024(const float* __restrict__ in,
                                       float* __restrict__ out,
                                       const float* __restrict__ g,
                                       const float* __restrict__ b)
{
    float x[4];
    float s = 0.f, q = 0.f;
#pragma unroll
    for (int l = 0; l < 4; l++) {
        x[l] = in[threadIdx.x + l * 256];
        s += x[l]; q += x[l] * x[l];
    }
    blk_reduce2(s, q);
    float mean = s * (1.f / ND);
    float var = q * (1.f / ND) - mean * mean;
    float rstd = rsqrtf(var + 1e-5f);
#pragma unroll
    for (int l = 0; l < 4; l++) {
        int c = threadIdx.x + l * 256;
        out[c] = (x[l] - mean) * rstd * g[c] + b[c];
    }
}

__global__ __launch_bounds__(256) void k_ln1(const float* __restrict__ g,
                                              const float* __restrict__ b)
{
    size_t r = blockIdx.x;
    ln1024(g_xres + r * ND, g_x + r * ND, g, b);
}

__global__ __launch_bounds__(256) void k_ln_out(const float* __restrict__ g,
                                                 const float* __restrict__ b,
                                                 float* __restrict__ out)
{
    size_t r = blockIdx.x;
    ln1024(g_z + r * ND, out + r * ND, g, b);
}

// routing: logits = x @ moe_gate_w + b (E=8); e_sel = max(index of top-2)
__global__ __launch_bounds__(256) void k_route(const float* __restrict__ gw,
                                                const float* __restrict__ gb)
{
    __shared__ float lg[NE];
    int t = blockIdx.x;
    int w = threadIdx.x >> 5, lane = threadIdx.x & 31;
    const float* x = g_x + (size_t)t * ND;
    float s = 0.f;
    for (int d = lane; d < ND; d += 32) s += x[d] * gw[d * NE + w];
#pragma unroll
    for (int o = 16; o; o >>= 1) s += __shfl_xor_sync(0xffffffffu, s, o);
    if (lane == 0) lg[w] = s + gb[w];
    __syncthreads();
    if (threadIdx.x == 0) {
        int i1 = 0; float v1 = lg[0];
#pragma unroll
        for (int e = 1; e < NE; e++) if (lg[e] > v1) { v1 = lg[e]; i1 = e; }
        int i2 = -1; float v2 = -1e30f;
#pragma unroll
        for (int e = 0; e < NE; e++) if (e != i1 && lg[e] > v2) { v2 = lg[e]; i2 = e; }
        g_esel[t] = (i1 > i2) ? i1 : i2;
    }
}

__global__ void k_scatter()
{
    __shared__ int scnt[NE], soff[NE], scur[NE];
    int tid = threadIdx.x;
    if (tid < NE) scnt[tid] = 0;
    __syncthreads();
    for (int t = tid; t < NT; t += 1024) atomicAdd(&scnt[g_esel[t]], 1);
    __syncthreads();
    if (tid == 0) {
        int r = 0;
        for (int e = 0; e < NE; e++) { soff[e] = r; r += scnt[e]; }
    }
    __syncthreads();
    if (tid < NE) { scur[tid] = soff[tid]; g_off[tid] = soff[tid]; g_cnt[tid] = scnt[tid]; }
    __syncthreads();
    for (int t = tid; t < NT; t += 1024) {
        int e = g_esel[t];
        int pos = atomicAdd(&scur[e], 1);
        g_perm[pos] = t;
        g_eid[pos] = e;
    }
}

__global__ __launch_bounds__(256) void k_ffn1(const float* __restrict__ w1,
                                               const float* __restrict__ b1)
{
    int e = blockIdx.z;
    int cnt = g_cnt[e], off = g_off[e];
    int row0 = blockIdx.y * 64, col0 = blockIdx.x * 64;
    if (row0 >= cnt) return;
    __shared__ int rloc[64];
    if (threadIdx.x < 64) {
        int gr = row0 + threadIdx.x;
        rloc[threadIdx.x] = (gr < cnt) ? g_perm[off + gr] : -1;
    }
    __syncthreads();
    float acc[4][4] = {};
    gemm64(g_x, w1 + (size_t)e * ND * NF, 0, ND, NF, 0, col0, rloc, acc);
    int tx = threadIdx.x & 15, ty = threadIdx.x >> 4;
#pragma unroll
    for (int i = 0; i < 4; i++) {
        int gr = row0 + ty * 4 + i;
        if (gr < cnt) {
#pragma unroll
            for (int j = 0; j < 4; j++) {
                int c = col0 + tx * 4 + j;
                g_h[(size_t)(off + gr) * NF + c] = acc[i][j] + b1[e * NF + c];
            }
        }
    }
}

__global__ __launch_bounds__(256) void k_lngelu(const float* __restrict__ lng,
                                                 const float* __restrict__ lnb)
{
    int row = blockIdx.x;
    int e = g_eid[row];
    float* hp = g_h + (size_t)row * NF;
    float x[16];
    float s = 0.f, q = 0.f;
#pragma unroll
    for (int l = 0; l < 16; l++) {
        x[l] = hp[threadIdx.x + l * 256];
        s += x[l]; q += x[l] * x[l];
    }
    blk_reduce2(s, q);
    float mean = s * (1.f / NF);
    float var = q * (1.f / NF) - mean * mean;
    float rstd = rsqrtf(var + 1e-5f);
    const float* g = lng + (size_t)e * NF;
    const float* b = lnb + (size_t)e * NF;
#pragma unroll
    for (int l = 0; l < 16; l++) {
        int c = threadIdx.x + l * 256;
        float hn = (x[l] - mean) * rstd * g[c] + b[c];
        hp[c] = 0.5f * hn * (1.f + erff(hn * 0.70710678118654752f));
    }
}

__global__ __launch_bounds__(256) void k_ffn2(const float* __restrict__ w2,
                                               const float* __restrict__ b2,
                                               const float* __restrict__ res)
{
    int e = blockIdx.z;
    int cnt = g_cnt[e], off = g_off[e];
    int row0 = blockIdx.y * 64, col0 = blockIdx.x * 64;
    if (row0 >= cnt) return;
    float acc[4][4] = {};
    gemm64(g_h + (size_t)off * NF, w2 + (size_t)e * NF * ND, cnt, NF, ND, row0, col0, nullptr, acc);
    float rs = res[e];
    int tx = threadIdx.x & 15, ty = threadIdx.x >> 4;
#pragma unroll
    for (int i = 0; i < 4; i++) {
        int gr = row0 + ty * 4 + i;
        if (gr < cnt) {
            int t = g_perm[off + gr];
#pragma unroll
            for (int j = 0; j < 4; j++) {
                int c = col0 + tx * 4 + j;
                // x + moe_out = x + (res*(h@w2+b2) + x) = 2x + res*(h@w2+b2); wsum == 1
                g_z[(size_t)t * ND + c] =
                    2.f * g_x[(size_t)t * ND + c] + rs * (acc[i][j] + b2[e * ND + c]);
            }
        }
    }
}

// ---------------- launch ------------------------------------------------------
extern "C" void kernel_launch(void* const* d_in, const int* in_sizes, int n_in,
                              void* d_out, int out_size)
{
    (void)in_sizes; (void)n_in; (void)out_size;
    const float* src        = (const float*)d_in[0];
    const float* qw         = (const float*)d_in[1];
    const float* kw         = (const float*)d_in[2];
    const float* vw         = (const float*)d_in[3];
    const float* ow         = (const float*)d_in[4];
    const float* gate_w     = (const float*)d_in[5];
    const float* gate_b     = (const float*)d_in[6];
    const float* scale_w    = (const float*)d_in[7];
    const float* n1_g       = (const float*)d_in[8];
    const float* n1_b       = (const float*)d_in[9];
    const float* n2_g       = (const float*)d_in[10];
    const float* n2_b       = (const float*)d_in[11];
    const float* moe_gate_w = (const float*)d_in[12];
    const float* moe_gate_b = (const float*)d_in[13];
    const float* w1         = (const float*)d_in[14];
    const float* b1         = (const float*)d_in[15];
    const float* ln_g       = (const float*)d_in[16];
    const float* ln_b       = (const float*)d_in[17];
    const float* w2         = (const float*)d_in[18];
    const float* b2         = (const float*)d_in[19];
    const float* res_scale  = (const float*)d_in[20];
    float* out = (float*)d_out;

    k_gemm_qkv<<<dim3(ND / 64, NT / 64, 3), 256>>>(src, qw, kw, vw);
    k_qscale<<<(NT * NH) / 8, 256>>>(scale_w);
    k_flash<<<dim3(NS / 64, NB * NH), 256>>>();
    k_gemm_gate<<<dim3(ND / 64, NT / 64), 256>>>(gate_w, gate_b);
    k_gemm_ow<<<dim3(ND / 64, NT / 64), 256>>>(ow, src);
    k_ln1<<<NT, 256>>>(n1_g, n1_b);
    k_route<<<NT, 256>>>(moe_gate_w, moe_gate_b);
    k_scatter<<<1, 1024>>>();
    k_ffn1<<<dim3(NF / 64, NT / 64, NE), 256>>>(w1, b1);
    k_lngelu<<<NT, 256>>>(ln_g, ln_b);
    k_ffn2<<<dim3(ND / 64, NT / 64, NE), 256>>>(w2, b2, res_scale);
    k_ln_out<<<NT, 256>>>(n2_g, n2_b, out);
}

// round 3
// speedup vs baseline: 1.7282x; 1.7282x over previous
#include <cuda_runtime.h>
#include <cuda_bf16.h>
#include <math.h>
#include <stdint.h>

#define NB 2
#define NS 1024
#define ND 1024
#define NH 16
#define NE 8
#define NF 4096
#define NT 2048

#define TM 128
#define TN 128
#define KC 32

// ---------------- scratch ----------------------------------------------------
__device__ __nv_bfloat16 g_sh[NT * ND], g_sl[NT * ND];
__device__ __nv_bfloat16 g_qh[NT * ND], g_ql[NT * ND];
__device__ __nv_bfloat16 g_kh[NT * ND], g_kl[NT * ND];
__device__ __nv_bfloat16 g_vh[NT * ND], g_vl[NT * ND];
__device__ __nv_bfloat16 g_ah[NT * ND], g_al[NT * ND];
__device__ __nv_bfloat16 g_gh[NT * ND], g_gl[NT * ND];
__device__ __nv_bfloat16 g_xh[NT * ND], g_xl[NT * ND];
__device__ __nv_bfloat16 g_hh[(size_t)NT * NF], g_hl[(size_t)NT * NF];
__device__ float g_scalef[NB * NH * NS];
__device__ float g_xres[NT * ND];
__device__ float g_x[NT * ND];
__device__ float g_z[NT * ND];
__device__ float g_h[(size_t)NT * NF];
__device__ int g_esel[NT];
__device__ int g_perm[NT];
__device__ int g_eid[NT];
__device__ int g_off[NE];
__device__ int g_cnt[NE];

// ---------------- helpers ----------------------------------------------------
__device__ __forceinline__ uint32_t s2u(const void* p) {
    uint32_t a;
    asm("{ .reg .u64 t; cvta.to.shared.u64 t, %1; cvt.u32.u64 %0, t; }" : "=r"(a) : "l"(p));
    return a;
}

__device__ __forceinline__ void split2(float x, __nv_bfloat16& h, __nv_bfloat16& l) {
    h = __float2bfloat16(x);
    l = __float2bfloat16(x - __bfloat162float(h));
}

__device__ __forceinline__ void ldm_x4(unsigned* r, uint32_t addr) {
    asm volatile("ldmatrix.sync.aligned.m8n8.x4.shared.b16 {%0,%1,%2,%3}, [%4];"
        : "=r"(r[0]), "=r"(r[1]), "=r"(r[2]), "=r"(r[3]) : "r"(addr));
}
__device__ __forceinline__ void ldm_x4_t(unsigned* r, uint32_t addr) {
    asm volatile("ldmatrix.sync.aligned.m8n8.x4.trans.shared.b16 {%0,%1,%2,%3}, [%4];"
        : "=r"(r[0]), "=r"(r[1]), "=r"(r[2]), "=r"(r[3]) : "r"(addr));
}
__device__ __forceinline__ void mma16816(float* c, const unsigned* a, const unsigned* b) {
    asm volatile(
        "mma.sync.aligned.m16n8k16.row.col.f32.bf16.bf16.f32 "
        "{%0,%1,%2,%3}, {%4,%5,%6,%7}, {%8,%9}, {%0,%1,%2,%3};"
        : "+f"(c[0]), "+f"(c[1]), "+f"(c[2]), "+f"(c[3])
        : "r"(a[0]), "r"(a[1]), "r"(a[2]), "r"(a[3]), "r"(b[0]), "r"(b[1]));
}

// ---------------- mma.sync split-bf16 GEMM ------------------------------------
// C[128,128] tile = A[M,K] @ B[K,N].  A bf16 hi/lo row-major stride K.
// B fp32 [K, ldB] row-major, converted in-tile.
// OP: 0 QKV store bf16 h/l | 1 gate epi | 2 ow (+src fp32) | 3 ffn1 gather +b1 | 4 ffn2
#define A_STRIDE 40   // bf16 elems per row (80B, conflict-free ldmatrix)
#define B_STRIDE 136  // bf16 elems per row (272B, conflict-free trans ldmatrix)

template <int OP>
__global__ void __launch_bounds__(256, 2) k_mm(
    const __nv_bfloat16* __restrict__ Ah, const __nv_bfloat16* __restrict__ Al,
    const float* __restrict__ Bp, int K, int ldB,
    const float* __restrict__ bias, const float* __restrict__ extra,
    const float* __restrict__ extra2,
    __nv_bfloat16* __restrict__ Oh, __nv_bfloat16* __restrict__ Ol,
    float* __restrict__ Of)
{
    __shared__ __align__(16) __nv_bfloat16 As_h[TM * A_STRIDE];
    __shared__ __align__(16) __nv_bfloat16 As_l[TM * A_STRIDE];
    __shared__ __align__(16) __nv_bfloat16 Bs_h[KC * B_STRIDE];
    __shared__ __align__(16) __nv_bfloat16 Bs_l[KC * B_STRIDE];
    __shared__ int rloc[TM];

    const int tid = threadIdx.x;
    const int lane = tid & 31, wid = tid >> 5;
    const int warp_m = wid >> 2, warp_n = wid & 3;  // 2 x 4 warps
    const int row0 = blockIdx.y * TM, col0 = blockIdx.x * TN;
    const int e = blockIdx.z;
    int cnt = 0, off = 0;
    if (OP == 3 || OP == 4) {
        cnt = g_cnt[e]; off = g_off[e];
        if (row0 >= cnt) return;
        Bp += (size_t)e * K * ldB;
    }
    if (OP == 3) {
        if (tid < TM) {
            int gr = row0 + tid;
            rloc[tid] = (gr < cnt) ? g_perm[off + gr] : -1;
        }
        __syncthreads();
    }

    // A load mapping: 2 thr/row, 16 bf16 each
    const int am = tid >> 1, ahalf = tid & 1;
    int arow;
    if (OP == 3) arow = rloc[am];
    else if (OP == 4) arow = min(off + row0 + am, NT - 1);
    else arow = row0 + am;
    const __nv_bfloat16* pAh = (arow >= 0) ? Ah + (size_t)arow * K + ahalf * 16 : nullptr;
    const __nv_bfloat16* pAl = (arow >= 0) ? Al + (size_t)arow * K + ahalf * 16 : nullptr;
    // B load mapping: 8 thr/row(k), 16 floats each along N
    const int bk = tid >> 3, bn0 = (tid & 7) * 16;
    const float* pB = Bp + (size_t)bk * ldB + col0 + bn0;

    const uint32_t uAh = s2u(As_h), uAl = s2u(As_l);
    const uint32_t uBh = s2u(Bs_h), uBl = s2u(Bs_l);

    float acc[16][4];
#pragma unroll
    for (int t = 0; t < 16; t++)
#pragma unroll
        for (int i = 0; i < 4; i++) acc[t][i] = 0.f;

    uint4 ra_h[2], ra_l[2];
    float4 rb[4];

    // prefetch chunk 0
    {
        if (arow >= 0) {
#pragma unroll
            for (int i = 0; i < 2; i++) {
                ra_h[i] = *(const uint4*)(pAh + i * 8);
                ra_l[i] = *(const uint4*)(pAl + i * 8);
            }
        } else {
            ra_h[0] = ra_h[1] = ra_l[0] = ra_l[1] = make_uint4(0, 0, 0, 0);
        }
#pragma unroll
        for (int i = 0; i < 4; i++) rb[i] = *(const float4*)(pB + i * 4);
    }

    const int nch = K / KC;
    for (int c = 0; c < nch; c++) {
        // ---- store regs -> smem ----
        {
            __nv_bfloat16* dsth = As_h + am * A_STRIDE + ahalf * 16;
            __nv_bfloat16* dstl = As_l + am * A_STRIDE + ahalf * 16;
            *(uint4*)(dsth) = ra_h[0]; *(uint4*)(dsth + 8) = ra_h[1];
            *(uint4*)(dstl) = ra_l[0]; *(uint4*)(dstl + 8) = ra_l[1];

            __nv_bfloat16 bh16[16], bl16[16];
            const float* bf = (const float*)rb;
#pragma unroll
            for (int i = 0; i < 16; i++) split2(bf[i], bh16[i], bl16[i]);
            __nv_bfloat16* dbh = Bs_h + bk * B_STRIDE + bn0;
            __nv_bfloat16* dbl = Bs_l + bk * B_STRIDE + bn0;
            *(uint4*)(dbh) = *(uint4*)(bh16); *(uint4*)(dbh + 8) = *(uint4*)(bh16 + 8);
            *(uint4*)(dbl) = *(uint4*)(bl16); *(uint4*)(dbl + 8) = *(uint4*)(bl16 + 8);
        }
        __syncthreads();

        // ---- prefetch next chunk ----
        if (c + 1 < nch) {
            if (arow >= 0) {
#pragma unroll
                for (int i = 0; i < 2; i++) {
                    ra_h[i] = *(const uint4*)(pAh + (c + 1) * KC + i * 8);
                    ra_l[i] = *(const uint4*)(pAl + (c + 1) * KC + i * 8);
                }
            }
#pragma unroll
            for (int i = 0; i < 4; i++)
                rb[i] = *(const float4*)(pB + (size_t)(c + 1) * KC * ldB + i * 4);
        }

        // ---- compute: 2 k16 steps ----
#pragma unroll
        for (int ks = 0; ks < 2; ks++) {
            unsigned bh[2][4], bl[2][4];
#pragma unroll
            for (int nt = 0; nt < 2; nt++) {
                int krow = ks * 16 + (lane & 7) + ((lane >> 3) & 1) * 8;
                int ncol = warp_n * 32 + nt * 16 + (lane >> 4) * 8;
                uint32_t o = (uint32_t)(krow * B_STRIDE + ncol) * 2;
                ldm_x4_t(bh[nt], uBh + o);
                ldm_x4_t(bl[nt], uBl + o);
            }
#pragma unroll
            for (int mt = 0; mt < 4; mt++) {
                unsigned ah[4], al[4];
                int mrow = warp_m * 64 + mt * 16 + (lane & 15);
                int kcol = ks * 16 + (lane >> 4) * 8;
                uint32_t o = (uint32_t)(mrow * A_STRIDE + kcol) * 2;
                ldm_x4(ah, uAh + o);
                ldm_x4(al, uAl + o);
#pragma unroll
                for (int nt = 0; nt < 2; nt++)
#pragma unroll
                    for (int j = 0; j < 2; j++) {
                        float* cc = acc[mt * 4 + nt * 2 + j];
                        mma16816(cc, ah, bh[nt] + j * 2);
                        mma16816(cc, ah, bl[nt] + j * 2);
                        mma16816(cc, al, bh[nt] + j * 2);
                    }
            }
        }
        __syncthreads();
    }

    // ---- epilogue ----
    float rs = 0.f;
    if (OP == 4) rs = extra2[e];
#pragma unroll
    for (int mt = 0; mt < 4; mt++)
#pragma unroll
        for (int nt = 0; nt < 2; nt++)
#pragma unroll
            for (int j = 0; j < 2; j++) {
                float* cc = acc[mt * 4 + nt * 2 + j];
                int lcol = warp_n * 32 + nt * 16 + j * 8 + (lane & 3) * 2;
                int gcol = col0 + lcol;
#pragma unroll
                for (int half = 0; half < 2; half++) {
                    int lrow = warp_m * 64 + mt * 16 + (lane >> 2) + half * 8;
                    int gr = row0 + lrow;
                    float v0 = cc[half * 2], v1 = cc[half * 2 + 1];
                    if (OP == 0) {
                        size_t base = (size_t)gr * ND + gcol;
                        __nv_bfloat16 h0, l0, h1, l1;
                        split2(v0, h0, l0); split2(v1, h1, l1);
                        *(__nv_bfloat162*)(Oh + base) = __nv_bfloat162(h0, h1);
                        *(__nv_bfloat162*)(Ol + base) = __nv_bfloat162(l0, l1);
                    } else if (OP == 1) {
                        size_t base = (size_t)gr * ND + gcol;
                        float g0 = 1.f / (1.f + expf(-(v0 + bias[gcol])));
                        float g1 = 1.f / (1.f + expf(-(v1 + bias[gcol + 1])));
                        float a0 = __bfloat162float(Ah[base]) + __bfloat162float(Al[base]);
                        float a1 = __bfloat162float(Ah[base + 1]) + __bfloat162float(Al[base + 1]);
                        __nv_bfloat16 h0, l0, h1, l1;
                        split2(a0 * g0, h0, l0); split2(a1 * g1, h1, l1);
                        *(__nv_bfloat162*)(Oh + base) = __nv_bfloat162(h0, h1);
                        *(__nv_bfloat162*)(Ol + base) = __nv_bfloat162(l0, l1);
                    } else if (OP == 2) {
                        size_t base = (size_t)gr * ND + gcol;
                        float2 o2;
                        o2.x = extra[base] + v0;
                        o2.y = extra[base + 1] + v1;
                        *(float2*)(Of + base) = o2;
                    } else if (OP == 3) {
                        if (gr < cnt) {
                            size_t base = (size_t)(off + gr) * NF + gcol;
                            float2 o2;
                            o2.x = v0 + bias[e * NF + gcol];
                            o2.y = v1 + bias[e * NF + gcol + 1];
                            *(float2*)(Of + base) = o2;
                        }
                    } else if (OP == 4) {
                        if (gr < cnt) {
                            int t = g_perm[off + gr];
                            size_t bx = (size_t)t * ND + gcol;
                            float2 o2;
                            o2.x = 2.f * extra[bx] + rs * (v0 + bias[e * ND + gcol]);
                            o2.y = 2.f * extra[bx + 1] + rs * (v1 + bias[e * ND + gcol + 1]);
                            *(float2*)(Of + bx) = o2;
                        }
                    }
                }
            }
}

// ---------------- reductions --------------------------------------------------
__device__ __forceinline__ void blk_reduce2(float& s, float& q)
{
    __shared__ float ss[8], sq[8];
#pragma unroll
    for (int o = 16; o; o >>= 1) {
        s += __shfl_xor_sync(0xffffffffu, s, o);
        q += __shfl_xor_sync(0xffffffffu, q, o);
    }
    int w = threadIdx.x >> 5, l = threadIdx.x & 31;
    if (l == 0) { ss[w] = s; sq[w] = q; }
    __syncthreads();
    s = (l < 8) ? ss[l] : 0.f;
    q = (l < 8) ? sq[l] : 0.f;
#pragma unroll
    for (int o = 4; o; o >>= 1) {
        s += __shfl_xor_sync(0xffffffffu, s, o);
        q += __shfl_xor_sync(0xffffffffu, q, o);
    }
    s = __shfl_sync(0xffffffffu, s, 0);
    q = __shfl_sync(0xffffffffu, q, 0);
}

// ---------------- elementwise / attention -------------------------------------
__global__ __launch_bounds__(256) void k_cvt(const float* __restrict__ in,
                                             __nv_bfloat16* __restrict__ oh,
                                             __nv_bfloat16* __restrict__ ol)
{
    int i = blockIdx.x * 256 + threadIdx.x;
    __nv_bfloat16 h, l;
    split2(in[i], h, l);
    oh[i] = h; ol[i] = l;
}

__global__ __launch_bounds__(256) void k_qscale(const float* __restrict__ sw)
{
    int wid = blockIdx.x * 8 + (threadIdx.x >> 5);
    int lane = threadIdx.x & 31;
    int h = wid & (NH - 1), t = wid >> 4;
    size_t i0 = (size_t)t * ND + h * 64 + lane;
    float q0 = __bfloat162float(g_qh[i0]) + __bfloat162float(g_ql[i0]);
    float q1 = __bfloat162float(g_qh[i0 + 32]) + __bfloat162float(g_ql[i0 + 32]);
    float s = q0 * sw[h * 64 + lane] + q1 * sw[h * 64 + lane + 32];
#pragma unroll
    for (int o = 16; o; o >>= 1) s += __shfl_xor_sync(0xffffffffu, s, o);
    if (lane == 0) {
        float sig = 1.f / (1.f + expf(-s));
        int b = t >> 10, si = t & (NS - 1);
        g_scalef[(b * NH + h) * NS + si] = 0.25f * sig;
    }
}

__global__ __launch_bounds__(256) void k_flash()
{
    __shared__ float Qs[64][65];
    __shared__ float Ks[32][65];
    __shared__ float Vs[32][65];
    int bh = blockIdx.y;
    int b = bh >> 4, h = bh & 15;
    int row0 = blockIdx.x * 64;
    int tx = threadIdx.x & 15, ty = threadIdx.x >> 4;

#pragma unroll
    for (int l = 0; l < 16; l++) {
        int lin = threadIdx.x + l * 256;
        int m = lin >> 6, d = lin & 63;
        float sc = g_scalef[bh * NS + row0 + m];
        size_t i = (size_t)(b * NS + row0 + m) * ND + h * 64 + d;
        Qs[m][d] = (__bfloat162float(g_qh[i]) + __bfloat162float(g_ql[i])) * sc;
    }

    float mi[4], li[4], o[4][4];
#pragma unroll
    for (int i = 0; i < 4; i++) {
        mi[i] = -1e30f; li[i] = 0.f;
#pragma unroll
        for (int j = 0; j < 4; j++) o[i][j] = 0.f;
    }

    for (int jt = 0; jt < NS / 32; jt++) {
        __syncthreads();
#pragma unroll
        for (int l = 0; l < 8; l++) {
            int lin = threadIdx.x + l * 256;
            int nn = lin >> 6, d = lin & 63;
            size_t i = (size_t)(b * NS + jt * 32 + nn) * ND + h * 64 + d;
            Ks[nn][d] = __bfloat162float(g_kh[i]) + __bfloat162float(g_kl[i]);
            Vs[nn][d] = __bfloat162float(g_vh[i]) + __bfloat162float(g_vl[i]);
        }
        __syncthreads();

        float s[4][2] = {};
#pragma unroll
        for (int d = 0; d < 64; d++) {
            float a0 = Qs[ty * 4 + 0][d];
            float a1 = Qs[ty * 4 + 1][d];
            float a2 = Qs[ty * 4 + 2][d];
            float a3 = Qs[ty * 4 + 3][d];
            float k0 = Ks[tx * 2 + 0][d];
            float k1 = Ks[tx * 2 + 1][d];
            s[0][0] += a0 * k0; s[0][1] += a0 * k1;
            s[1][0] += a1 * k0; s[1][1] += a1 * k1;
            s[2][0] += a2 * k0; s[2][1] += a2 * k1;
            s[3][0] += a3 * k0; s[3][1] += a3 * k1;
        }

        float p[4][2];
#pragma unroll
        for (int i = 0; i < 4; i++) {
            float rm = fmaxf(s[i][0], s[i][1]);
#pragma unroll
            for (int off = 8; off; off >>= 1)
                rm = fmaxf(rm, __shfl_xor_sync(0xffffffffu, rm, off));
            float mnew = fmaxf(mi[i], rm);
            float alpha = expf(mi[i] - mnew);
            p[i][0] = expf(s[i][0] - mnew);
            p[i][1] = expf(s[i][1] - mnew);
            float rsm = p[i][0] + p[i][1];
#pragma unroll
            for (int off = 8; off; off >>= 1)
                rsm += __shfl_xor_sync(0xffffffffu, rsm, off);
            li[i] = li[i] * alpha + rsm;
            mi[i] = mnew;
#pragma unroll
            for (int j = 0; j < 4; j++) o[i][j] *= alpha;
        }

        __syncthreads();
#pragma unroll
        for (int i = 0; i < 4; i++) {
            Ks[tx * 2 + 0][ty * 4 + i] = p[i][0];
            Ks[tx * 2 + 1][ty * 4 + i] = p[i][1];
        }
        __syncthreads();

#pragma unroll
        for (int n = 0; n < 32; n++) {
            float a0 = Ks[n][ty * 4 + 0];
            float a1 = Ks[n][ty * 4 + 1];
            float a2 = Ks[n][ty * 4 + 2];
            float a3 = Ks[n][ty * 4 + 3];
            float v0 = Vs[n][tx * 4 + 0];
            float v1 = Vs[n][tx * 4 + 1];
            float v2 = Vs[n][tx * 4 + 2];
            float v3 = Vs[n][tx * 4 + 3];
            o[0][0] += a0 * v0; o[0][1] += a0 * v1; o[0][2] += a0 * v2; o[0][3] += a0 * v3;
            o[1][0] += a1 * v0; o[1][1] += a1 * v1; o[1][2] += a1 * v2; o[1][3] += a1 * v3;
            o[2][0] += a2 * v0; o[2][1] += a2 * v1; o[2][2] += a2 * v2; o[2][3] += a2 * v3;
            o[3][0] += a3 * v0; o[3][1] += a3 * v1; o[3][2] += a3 * v2; o[3][3] += a3 * v3;
        }
    }

#pragma unroll
    for (int i = 0; i < 4; i++) {
        float inv = 1.f / li[i];
#pragma unroll
        for (int j = 0; j < 4; j++) {
            size_t idx = (size_t)(b * NS + row0 + ty * 4 + i) * ND + h * 64 + tx * 4 + j;
            __nv_bfloat16 hh, ll;
            split2(o[i][j] * inv, hh, ll);
            g_ah[idx] = hh; g_al[idx] = ll;
        }
    }
}

__global__ __launch_bounds__(256) void k_ln1(const float* __restrict__ g,
                                             const float* __restrict__ b)
{
    size_t r = blockIdx.x;
    const float* in = g_xres + r * ND;
    float x[4];
    float s = 0.f, q = 0.f;
#pragma unroll
    for (int l = 0; l < 4; l++) {
        x[l] = in[threadIdx.x + l * 256];
        s += x[l]; q += x[l] * x[l];
    }
    blk_reduce2(s, q);
    float mean = s * (1.f / ND);
    float var = q * (1.f / ND) - mean * mean;
    float rstd = rsqrtf(var + 1e-5f);
#pragma unroll
    for (int l = 0; l < 4; l++) {
        int c = threadIdx.x + l * 256;
        float v = (x[l] - mean) * rstd * g[c] + b[c];
        g_x[r * ND + c] = v;
        __nv_bfloat16 h, lo;
        split2(v, h, lo);
        g_xh[r * ND + c] = h; g_xl[r * ND + c] = lo;
    }
}

__global__ __launch_bounds__(256) void k_ln_out(const float* __restrict__ g,
                                                const float* __restrict__ b,
                                                float* __restrict__ out)
{
    size_t r = blockIdx.x;
    const float* in = g_z + r * ND;
    float x[4];
    float s = 0.f, q = 0.f;
#pragma unroll
    for (int l = 0; l < 4; l++) {
        x[l] = in[threadIdx.x + l * 256];
        s += x[l]; q += x[l] * x[l];
    }
    blk_reduce2(s, q);
    float mean = s * (1.f / ND);
    float var = q * (1.f / ND) - mean * mean;
    float rstd = rsqrtf(var + 1e-5f);
#pragma unroll
    for (int l = 0; l < 4; l++) {
        int c = threadIdx.x + l * 256;
        out[r * ND + c] = (x[l] - mean) * rstd * g[c] + b[c];
    }
}

__global__ __launch_bounds__(256) void k_route(const float* __restrict__ gw,
                                               const float* __restrict__ gb)
{
    __shared__ float lg[NE];
    int t = blockIdx.x;
    int w = threadIdx.x >> 5, lane = threadIdx.x & 31;
    const float* x = g_x + (size_t)t * ND;
    float s = 0.f;
    for (int d = lane; d < ND; d += 32) s += x[d] * gw[d * NE + w];
#pragma unroll
    for (int o = 16; o; o >>= 1) s += __shfl_xor_sync(0xffffffffu, s, o);
    if (lane == 0) lg[w] = s + gb[w];
    __syncthreads();
    if (threadIdx.x == 0) {
        int i1 = 0; float v1 = lg[0];
#pragma unroll
        for (int e = 1; e < NE; e++) if (lg[e] > v1) { v1 = lg[e]; i1 = e; }
        int i2 = -1; float v2 = -1e30f;
#pragma unroll
        for (int e = 0; e < NE; e++) if (e != i1 && lg[e] > v2) { v2 = lg[e]; i2 = e; }
        g_esel[t] = (i1 > i2) ? i1 : i2;
    }
}

__global__ void k_scatter()
{
    __shared__ int scnt[NE], soff[NE], scur[NE];
    int tid = threadIdx.x;
    if (tid < NE) scnt[tid] = 0;
    __syncthreads();
    for (int t = tid; t < NT; t += 1024) atomicAdd(&scnt[g_esel[t]], 1);
    __syncthreads();
    if (tid == 0) {
        int r = 0;
        for (int e = 0; e < NE; e++) { soff[e] = r; r += scnt[e]; }
    }
    __syncthreads();
    if (tid < NE) { scur[tid] = soff[tid]; g_off[tid] = soff[tid]; g_cnt[tid] = scnt[tid]; }
    __syncthreads();
    for (int t = tid; t < NT; t += 1024) {
        int e = g_esel[t];
        int pos = atomicAdd(&scur[e], 1);
        g_perm[pos] = t;
        g_eid[pos] = e;
    }
}

__global__ __launch_bounds__(256) void k_lngelu(const float* __restrict__ lng,
                                                const float* __restrict__ lnb)
{
    int row = blockIdx.x;
    int e = g_eid[row];
    const float* hp = g_h + (size_t)row * NF;
    float x[16];
    float s = 0.f, q = 0.f;
#pragma unroll
    for (int l = 0; l < 16; l++) {
        x[l] = hp[threadIdx.x + l * 256];
        s += x[l]; q += x[l] * x[l];
    }
    blk_reduce2(s, q);
    float mean = s * (1.f / NF);
    float var = q * (1.f / NF) - mean * mean;
    float rstd = rsqrtf(var + 1e-5f);
    const float* g = lng + (size_t)e * NF;
    const float* b = lnb + (size_t)e * NF;
#pragma unroll
    for (int l = 0; l < 16; l++) {
        int c = threadIdx.x + l * 256;
        float hn = (x[l] - mean) * rstd * g[c] + b[c];
        float gel = 0.5f * hn * (1.f + erff(hn * 0.70710678118654752f));
        __nv_bfloat16 hh, ll;
        split2(gel, hh, ll);
        g_hh[(size_t)row * NF + c] = hh;
        g_hl[(size_t)row * NF + c] = ll;
    }
}

// ---------------- launch ------------------------------------------------------
extern "C" void kernel_launch(void* const* d_in, const int* in_sizes, int n_in,
                              void* d_out, int out_size)
{
    (void)in_sizes; (void)n_in; (void)out_size;
    const float* src        = (const float*)d_in[0];
    const float* qw         = (const float*)d_in[1];
    const float* kw         = (const float*)d_in[2];
    const float* vw         = (const float*)d_in[3];
    const float* ow         = (const float*)d_in[4];
    const float* gate_w     = (const float*)d_in[5];
    const float* gate_b     = (const float*)d_in[6];
    const float* scale_w    = (const float*)d_in[7];
    const float* n1_g       = (const float*)d_in[8];
    const float* n1_b       = (const float*)d_in[9];
    const float* n2_g       = (const float*)d_in[10];
    const float* n2_b       = (const float*)d_in[11];
    const float* moe_gate_w = (const float*)d_in[12];
    const float* moe_gate_b = (const float*)d_in[13];
    const float* w1         = (const float*)d_in[14];
    const float* b1         = (const float*)d_in[15];
    const float* ln_g       = (const float*)d_in[16];
    const float* ln_b       = (const float*)d_in[17];
    const float* w2         = (const float*)d_in[18];
    const float* b2         = (const float*)d_in[19];
    const float* res_scale  = (const float*)d_in[20];
    float* out = (float*)d_out;

    __nv_bfloat16 *sh, *sl, *qh, *ql, *kh, *kl, *vh, *vl, *ah, *al, *gh, *gl, *xh, *xl, *hh, *hl;
    float *xres, *x, *z, *h;
    cudaGetSymbolAddress((void**)&sh, g_sh);  cudaGetSymbolAddress((void**)&sl, g_sl);
    cudaGetSymbolAddress((void**)&qh, g_qh);  cudaGetSymbolAddress((void**)&ql, g_ql);
    cudaGetSymbolAddress((void**)&kh, g_kh);  cudaGetSymbolAddress((void**)&kl, g_kl);
    cudaGetSymbolAddress((void**)&vh, g_vh);  cudaGetSymbolAddress((void**)&vl, g_vl);
    cudaGetSymbolAddress((void**)&ah, g_ah);  cudaGetSymbolAddress((void**)&al, g_al);
    cudaGetSymbolAddress((void**)&gh, g_gh);  cudaGetSymbolAddress((void**)&gl, g_gl);
    cudaGetSymbolAddress((void**)&xh, g_xh);  cudaGetSymbolAddress((void**)&xl, g_xl);
    cudaGetSymbolAddress((void**)&hh, g_hh);  cudaGetSymbolAddress((void**)&hl, g_hl);
    cudaGetSymbolAddress((void**)&xres, g_xres);
    cudaGetSymbolAddress((void**)&x, g_x);
    cudaGetSymbolAddress((void**)&z, g_z);
    cudaGetSymbolAddress((void**)&h, g_h);

    k_cvt<<<NT * ND / 256, 256>>>(src, sh, sl);
    k_mm<0><<<dim3(ND / TN, NT / TM), 256>>>(sh, sl, qw, ND, ND,
        nullptr, nullptr, nullptr, qh, ql, nullptr);
    k_mm<0><<<dim3(ND / TN, NT / TM), 256>>>(sh, sl, kw, ND, ND,
        nullptr, nullptr, nullptr, kh, kl, nullptr);
    k_mm<0><<<dim3(ND / TN, NT / TM), 256>>>(sh, sl, vw, ND, ND,
        nullptr, nullptr, nullptr, vh, vl, nullptr);
    k_qscale<<<(NT * NH) / 8, 256>>>(scale_w);
    k_flash<<<dim3(NS / 64, NB * NH), 256>>>();
    k_mm<1><<<dim3(ND / TN, NT / TM), 256>>>(ah, al, gate_w, ND, ND,
        gate_b, nullptr, nullptr, gh, gl, nullptr);
    k_mm<2><<<dim3(ND / TN, NT / TM), 256>>>(gh, gl, ow, ND, ND,
        nullptr, src, nullptr, nullptr, nullptr, xres);
    k_ln1<<<NT, 256>>>(n1_g, n1_b);
    k_route<<<NT, 256>>>(moe_gate_w, moe_gate_b);
    k_scatter<<<1, 1024>>>();
    k_mm<3><<<dim3(NF / TN, NT / TM, NE), 256>>>(xh, xl, w1, ND, NF,
        b1, nullptr, nullptr, nullptr, nullptr, h);
    k_lngelu<<<NT, 256>>>(ln_g, ln_b);
    k_mm<4><<<dim3(ND / TN, NT / TM, NE), 256>>>(hh, hl, w2, NF, ND,
        b2, x, res_scale, nullptr, nullptr, z);
    k_ln_out<<<NT, 256>>>(n2_g, n2_b, out);
}

// round 4
// speedup vs baseline: 2.1892x; 1.2668x over previous
#include <cuda_runtime.h>
#include <cuda_bf16.h>
#include <math.h>
#include <stdint.h>

#define NB 2
#define NS 1024
#define ND 1024
#define NH 16
#define NE 8
#define NF 4096
#define NT 2048

#define TM 128
#define TN 128
#define KC 32
#define A_STRIDE 40    // bf16 elems per A smem row (80B)
#define B_STRIDE 136   // bf16 elems per B smem row (272B)
#define ST_AH 0
#define ST_AL 10240
#define ST_BH 20480
#define ST_BL 29184
#define STAGE_BYTES 37888
#define GEMM_SMEM (2 * STAGE_BYTES)

#define F_STRIDE 72    // flash smem row stride (144B)
#define F_QH 0
#define F_QL 9216
#define F_KH 18432
#define F_KL 27648
#define F_VH 36864
#define F_VL 46080
#define FLASH_SMEM 55296

// ---------------- scratch ----------------------------------------------------
__device__ __nv_bfloat16 g_sh[NT * ND], g_sl[NT * ND];
__device__ __nv_bfloat16 g_qkvh[3 * NT * ND], g_qkvl[3 * NT * ND];
__device__ __nv_bfloat16 g_ah[NT * ND], g_al[NT * ND];
__device__ __nv_bfloat16 g_gh[NT * ND], g_gl[NT * ND];
__device__ __nv_bfloat16 g_xh[NT * ND], g_xl[NT * ND];
__device__ __nv_bfloat16 g_hh[(size_t)NT * NF], g_hl[(size_t)NT * NF];
__device__ __nv_bfloat16 g_wqkvh[3 * ND * ND], g_wqkvl[3 * ND * ND];
__device__ __nv_bfloat16 g_wgh[ND * ND], g_wgl[ND * ND];
__device__ __nv_bfloat16 g_woh[ND * ND], g_wol[ND * ND];
__device__ __nv_bfloat16 g_w1h[(size_t)NE * ND * NF], g_w1l[(size_t)NE * ND * NF];
__device__ __nv_bfloat16 g_w2h[(size_t)NE * NF * ND], g_w2l[(size_t)NE * NF * ND];
__device__ float g_scalef[NB * NH * NS];
__device__ float g_xres[NT * ND];
__device__ float g_x[NT * ND];
__device__ float g_z[NT * ND];
__device__ float g_h[(size_t)NT * NF];
__device__ int g_esel[NT];
__device__ int g_perm[NT];
__device__ int g_eid[NT];
__device__ int g_off[NE];
__device__ int g_cnt[NE];

// ---------------- helpers ----------------------------------------------------
__device__ __forceinline__ uint32_t s2u(const void* p) {
    uint32_t a;
    asm("{ .reg .u64 t; cvta.to.shared.u64 t, %1; cvt.u32.u64 %0, t; }" : "=r"(a) : "l"(p));
    return a;
}
__device__ __forceinline__ void split2(float x, __nv_bfloat16& h, __nv_bfloat16& l) {
    h = __float2bfloat16(x);
    l = __float2bfloat16(x - __bfloat162float(h));
}
__device__ __forceinline__ unsigned pk_bf2(float lo, float hi) {
    unsigned r;
    asm("cvt.rn.bf16x2.f32 %0, %1, %2;" : "=r"(r) : "f"(hi), "f"(lo));
    return r;
}
// split-pack two fp32 (a=low elem, b=high elem) into bf16x2 hi + bf16x2 lo-residual
__device__ __forceinline__ void sp2(float a, float b, unsigned& h, unsigned& l) {
    __nv_bfloat16 ah = __float2bfloat16(a), bh = __float2bfloat16(b);
    h = (unsigned)__bfloat16_as_ushort(ah) | ((unsigned)__bfloat16_as_ushort(bh) << 16);
    l = pk_bf2(a - __bfloat162float(ah), b - __bfloat162float(bh));
}
__device__ __forceinline__ void ldm_x4(unsigned* r, uint32_t addr) {
    asm volatile("ldmatrix.sync.aligned.m8n8.x4.shared.b16 {%0,%1,%2,%3}, [%4];"
        : "=r"(r[0]), "=r"(r[1]), "=r"(r[2]), "=r"(r[3]) : "r"(addr));
}
__device__ __forceinline__ void ldm_x4_t(unsigned* r, uint32_t addr) {
    asm volatile("ldmatrix.sync.aligned.m8n8.x4.trans.shared.b16 {%0,%1,%2,%3}, [%4];"
        : "=r"(r[0]), "=r"(r[1]), "=r"(r[2]), "=r"(r[3]) : "r"(addr));
}
__device__ __forceinline__ void mma16816(float* c, const unsigned* a, const unsigned* b) {
    asm volatile(
        "mma.sync.aligned.m16n8k16.row.col.f32.bf16.bf16.f32 "
        "{%0,%1,%2,%3}, {%4,%5,%6,%7}, {%8,%9}, {%0,%1,%2,%3};"
        : "+f"(c[0]), "+f"(c[1]), "+f"(c[2]), "+f"(c[3])
        : "r"(a[0]), "r"(a[1]), "r"(a[2]), "r"(a[3]), "r"(b[0]), "r"(b[1]));
}
__device__ __forceinline__ void cpa(uint32_t d, const void* s, int szvalid) {
    asm volatile("cp.async.cg.shared.global [%0], [%1], 16, %2;"
        :: "r"(d), "l"(__cvta_generic_to_global(s)), "r"(szvalid));
}

// ---------------- pipelined mma.sync split-bf16 GEMM --------------------------
// C[128,128] = A[M,K] @ B[K,N]; A,B pre-split bf16 hi/lo. 2-stage cp.async.
// OP: 0 merged QKV (z sel) | 1 gate | 2 ow (+src) | 3 ffn1 gather +b1 | 4 ffn2
template <int OP>
__global__ void __launch_bounds__(256, 2) k_mm(
    const __nv_bfloat16* __restrict__ Ah, const __nv_bfloat16* __restrict__ Al,
    const __nv_bfloat16* __restrict__ Bh, const __nv_bfloat16* __restrict__ Bl,
    int K, int ldB,
    const float* __restrict__ bias, const float* __restrict__ extra,
    const float* __restrict__ extra2,
    __nv_bfloat16* __restrict__ Oh, __nv_bfloat16* __restrict__ Ol,
    float* __restrict__ Of)
{
    extern __shared__ __align__(16) char sm[];
    __shared__ int rloc[TM];

    const int tid = threadIdx.x;
    const int lane = tid & 31, wid = tid >> 5;
    const int warp_m = wid >> 2, warp_n = wid & 3;
    const int row0 = blockIdx.y * TM, col0 = blockIdx.x * TN;
    const int e = blockIdx.z;
    int cnt = 0, off = 0;
    if (OP == 0) {
        size_t zo = (size_t)e * ND * ND;
        Bh += zo; Bl += zo;
        size_t oo = (size_t)e * NT * ND;
        Oh += oo; Ol += oo;
    }
    if (OP == 3 || OP == 4) {
        cnt = g_cnt[e]; off = g_off[e];
        if (row0 >= cnt) return;
        Bh += (size_t)e * K * ldB; Bl += (size_t)e * K * ldB;
    }
    if (OP == 3) {
        if (tid < TM) {
            int gr = row0 + tid;
            rloc[tid] = (gr < cnt) ? g_perm[off + gr] : -1;
        }
        __syncthreads();
    }

    const int am = tid >> 1, ahalf = tid & 1;
    int arow;
    if (OP == 3) arow = rloc[am];
    else if (OP == 4) arow = min(off + row0 + am, NT - 1);
    else arow = row0 + am;
    const int apred = (arow >= 0) ? 16 : 0;
    const int arows = (arow >= 0) ? arow : 0;
    const char* gAh = (const char*)(Ah + (size_t)arows * K + ahalf * 16);
    const char* gAl = (const char*)(Al + (size_t)arows * K + ahalf * 16);
    const int bk = tid >> 3, bseg = tid & 7;
    const char* gBh = (const char*)(Bh + (size_t)bk * ldB + col0 + bseg * 16);
    const char* gBl = (const char*)(Bl + (size_t)bk * ldB + col0 + bseg * 16);

    const uint32_t ub = s2u(sm);
    const uint32_t aDst = ub + am * 80 + ahalf * 32;
    const uint32_t bDst = ub + bk * 272 + bseg * 32;

    auto issue = [&](int stage, int c) {
        uint32_t sb = stage * STAGE_BYTES;
        size_t ao = (size_t)c * KC * 2;
        size_t bo = (size_t)c * KC * ldB * 2;
        cpa(aDst + sb + ST_AH,      gAh + ao,      apred);
        cpa(aDst + sb + ST_AH + 16, gAh + ao + 16, apred);
        cpa(aDst + sb + ST_AL,      gAl + ao,      apred);
        cpa(aDst + sb + ST_AL + 16, gAl + ao + 16, apred);
        cpa(bDst + sb + ST_BH,      gBh + bo,      16);
        cpa(bDst + sb + ST_BH + 16, gBh + bo + 16, 16);
        cpa(bDst + sb + ST_BL,      gBl + bo,      16);
        cpa(bDst + sb + ST_BL + 16, gBl + bo + 16, 16);
        asm volatile("cp.async.commit_group;");
    };

    float acc[16][4];
#pragma unroll
    for (int t = 0; t < 16; t++)
#pragma unroll
        for (int i = 0; i < 4; i++) acc[t][i] = 0.f;

    const int nch = K / KC;
    issue(0, 0);
    issue(1, 1);

    for (int c = 0; c < nch; c++) {
        asm volatile("cp.async.wait_group 1;");
        __syncthreads();
        uint32_t sb = ub + (c & 1) * STAGE_BYTES;
        uint32_t uAh_ = sb + ST_AH, uAl_ = sb + ST_AL;
        uint32_t uBh_ = sb + ST_BH, uBl_ = sb + ST_BL;
#pragma unroll
        for (int ks = 0; ks < 2; ks++) {
            unsigned bh_[2][4], bl_[2][4];
#pragma unroll
            for (int nt = 0; nt < 2; nt++) {
                int krow = ks * 16 + (lane & 7) + ((lane >> 3) & 1) * 8;
                int ncol = warp_n * 32 + nt * 16 + (lane >> 4) * 8;
                uint32_t o = (uint32_t)(krow * B_STRIDE + ncol) * 2;
                ldm_x4_t(bh_[nt], uBh_ + o);
                ldm_x4_t(bl_[nt], uBl_ + o);
            }
#pragma unroll
            for (int mt = 0; mt < 4; mt++) {
                unsigned ah_[4], al_[4];
                int mrow = warp_m * 64 + mt * 16 + (lane & 15);
                int kcol = ks * 16 + (lane >> 4) * 8;
                uint32_t o = (uint32_t)(mrow * A_STRIDE + kcol) * 2;
                ldm_x4(ah_, uAh_ + o);
                ldm_x4(al_, uAl_ + o);
#pragma unroll
                for (int nt = 0; nt < 2; nt++)
#pragma unroll
                    for (int j = 0; j < 2; j++) {
                        float* cc = acc[mt * 4 + nt * 2 + j];
                        mma16816(cc, ah_, bh_[nt] + j * 2);
                        mma16816(cc, ah_, bl_[nt] + j * 2);
                        mma16816(cc, al_, bh_[nt] + j * 2);
                    }
            }
        }
        __syncthreads();
        if (c + 2 < nch) issue(c & 1, c + 2);
        else asm volatile("cp.async.commit_group;");
    }

    // ---- epilogue ----
    float rs = 0.f;
    if (OP == 4) rs = extra2[e];
#pragma unroll
    for (int mt = 0; mt < 4; mt++)
#pragma unroll
        for (int nt = 0; nt < 2; nt++)
#pragma unroll
            for (int j = 0; j < 2; j++) {
                float* cc = acc[mt * 4 + nt * 2 + j];
                int lcol = warp_n * 32 + nt * 16 + j * 8 + (lane & 3) * 2;
                int gcol = col0 + lcol;
#pragma unroll
                for (int half = 0; half < 2; half++) {
                    int lrow = warp_m * 64 + mt * 16 + (lane >> 2) + half * 8;
                    int gr = row0 + lrow;
                    float v0 = cc[half * 2], v1 = cc[half * 2 + 1];
                    if (OP == 0) {
                        size_t base = (size_t)gr * ND + gcol;
                        unsigned h, l;
                        sp2(v0, v1, h, l);
                        *(unsigned*)(Oh + base) = h;
                        *(unsigned*)(Ol + base) = l;
                    } else if (OP == 1) {
                        size_t base = (size_t)gr * ND + gcol;
                        float g0 = 1.f / (1.f + expf(-(v0 + bias[gcol])));
                        float g1 = 1.f / (1.f + expf(-(v1 + bias[gcol + 1])));
                        float a0 = __bfloat162float(Ah[base]) + __bfloat162float(Al[base]);
                        float a1 = __bfloat162float(Ah[base + 1]) + __bfloat162float(Al[base + 1]);
                        unsigned h, l;
                        sp2(a0 * g0, a1 * g1, h, l);
                        *(unsigned*)(Oh + base) = h;
                        *(unsigned*)(Ol + base) = l;
                    } else if (OP == 2) {
                        size_t base = (size_t)gr * ND + gcol;
                        float2 o2;
                        o2.x = extra[base] + v0;
                        o2.y = extra[base + 1] + v1;
                        *(float2*)(Of + base) = o2;
                    } else if (OP == 3) {
                        if (gr < cnt) {
                            size_t base = (size_t)(off + gr) * NF + gcol;
                            float2 o2;
                            o2.x = v0 + bias[e * NF + gcol];
                            o2.y = v1 + bias[e * NF + gcol + 1];
                            *(float2*)(Of + base) = o2;
                        }
                    } else if (OP == 4) {
                        if (gr < cnt) {
                            int t = g_perm[off + gr];
                            size_t bx = (size_t)t * ND + gcol;
                            float2 o2;
                            o2.x = 2.f * extra[bx] + rs * (v0 + bias[e * ND + gcol]);
                            o2.y = 2.f * extra[bx + 1] + rs * (v1 + bias[e * ND + gcol + 1]);
                            *(float2*)(Of + bx) = o2;
                        }
                    }
                }
            }
}

// ---------------- mma.sync flash attention ------------------------------------
// CTA: 64 queries x all keys (64/iter), 4 warps x 16 query rows, HD=64.
__global__ void __launch_bounds__(128, 3) k_flash()
{
    extern __shared__ __align__(16) char fsm[];
    const int tid = threadIdx.x, lane = tid & 31, warpm = tid >> 5;
    const int bh = blockIdx.y, b = bh >> 4, h = bh & 15;
    const int row0 = blockIdx.x * 64;

    const __nv_bfloat16* Qh = g_qkvh;
    const __nv_bfloat16* Ql = g_qkvl;
    const __nv_bfloat16* Kh = g_qkvh + (size_t)NT * ND;
    const __nv_bfloat16* Kl = g_qkvl + (size_t)NT * ND;
    const __nv_bfloat16* Vh = g_qkvh + (size_t)2 * NT * ND;
    const __nv_bfloat16* Vl = g_qkvl + (size_t)2 * NT * ND;

    // load Q tile (scale applied, re-split)
    {
        int m = tid >> 1, half = tid & 1;
        float sc = g_scalef[bh * NS + row0 + m];
        const __nv_bfloat16* sh_ = Qh + (size_t)(b * NS + row0 + m) * ND + h * 64 + half * 32;
        const __nv_bfloat16* sl_ = Ql + (size_t)(b * NS + row0 + m) * ND + h * 64 + half * 32;
        char* dh = fsm + F_QH + m * 144 + half * 64;
        char* dl = fsm + F_QL + m * 144 + half * 64;
#pragma unroll
        for (int i = 0; i < 4; i++) {
            __nv_bfloat16 hb[8], lb[8], oh[8], ol[8];
            *(uint4*)hb = *(const uint4*)(sh_ + i * 8);
            *(uint4*)lb = *(const uint4*)(sl_ + i * 8);
#pragma unroll
            for (int j = 0; j < 8; j++) {
                float f = (__bfloat162float(hb[j]) + __bfloat162float(lb[j])) * sc;
                split2(f, oh[j], ol[j]);
            }
            *(uint4*)(dh + i * 16) = *(uint4*)oh;
            *(uint4*)(dl + i * 16) = *(uint4*)ol;
        }
    }

    const uint32_t ubase = s2u(fsm);
    const uint32_t uQh = ubase + F_QH, uQl = ubase + F_QL;
    const uint32_t uKh = ubase + F_KH, uKl = ubase + F_KL;
    const uint32_t uVh = ubase + F_VH, uVl = ubase + F_VL;

    const uint32_t qa_off = ((warpm * 16 + (lane & 15)) * F_STRIDE + ((lane >> 4) & 1) * 8) * 2;
    const uint32_t ka_off = (((lane & 7) + ((lane >> 4) << 3)) * F_STRIDE + ((lane >> 3) & 1) * 8) * 2;
    const uint32_t va_off = (((lane & 7) + ((lane >> 3) & 1) * 8) * F_STRIDE + ((lane >> 4) & 1) * 8) * 2;

    float oacc[8][4];
#pragma unroll
    for (int t = 0; t < 8; t++)
#pragma unroll
        for (int i = 0; i < 4; i++) oacc[t][i] = 0.f;
    float mi0 = -1e30f, mi1 = -1e30f, li0 = 0.f, li1 = 0.f;

    for (int jt = 0; jt < NS / 64; jt++) {
        __syncthreads();
        {
            int m = tid >> 1, half = tid & 1;
            size_t gsrc = (size_t)(b * NS + jt * 64 + m) * ND + h * 64 + half * 32;
            char* dkh = fsm + F_KH + m * 144 + half * 64;
            char* dkl = fsm + F_KL + m * 144 + half * 64;
            char* dvh = fsm + F_VH + m * 144 + half * 64;
            char* dvl = fsm + F_VL + m * 144 + half * 64;
#pragma unroll
            for (int i = 0; i < 4; i++) {
                *(uint4*)(dkh + i * 16) = *(const uint4*)((const char*)(Kh + gsrc) + i * 16);
                *(uint4*)(dkl + i * 16) = *(const uint4*)((const char*)(Kl + gsrc) + i * 16);
                *(uint4*)(dvh + i * 16) = *(const uint4*)((const char*)(Vh + gsrc) + i * 16);
                *(uint4*)(dvl + i * 16) = *(const uint4*)((const char*)(Vl + gsrc) + i * 16);
            }
        }
        __syncthreads();

        // S = Q K^T  (16 rows x 64 keys per warp)
        float sacc[8][4];
#pragma unroll
        for (int t = 0; t < 8; t++)
#pragma unroll
            for (int i = 0; i < 4; i++) sacc[t][i] = 0.f;
#pragma unroll
        for (int ks = 0; ks < 4; ks++) {
            unsigned qh4[4], ql4[4];
            ldm_x4(qh4, uQh + qa_off + ks * 32);
            ldm_x4(ql4, uQl + qa_off + ks * 32);
#pragma unroll
            for (int np = 0; np < 4; np++) {
                unsigned kh4[4], kl4[4];
                uint32_t o = ka_off + (uint32_t)(np * 16 * F_STRIDE + ks * 16) * 2;
                ldm_x4(kh4, uKh + o);
                ldm_x4(kl4, uKl + o);
                mma16816(sacc[2 * np],     qh4, kh4);
                mma16816(sacc[2 * np],     qh4, kl4);
                mma16816(sacc[2 * np],     ql4, kh4);
                mma16816(sacc[2 * np + 1], qh4, kh4 + 2);
                mma16816(sacc[2 * np + 1], qh4, kl4 + 2);
                mma16816(sacc[2 * np + 1], ql4, kh4 + 2);
            }
        }

        // online softmax (rows r = lane>>2 and r+8)
        float rm0 = -1e30f, rm1 = -1e30f;
#pragma unroll
        for (int j = 0; j < 8; j++) {
            rm0 = fmaxf(rm0, fmaxf(sacc[j][0], sacc[j][1]));
            rm1 = fmaxf(rm1, fmaxf(sacc[j][2], sacc[j][3]));
        }
        rm0 = fmaxf(rm0, __shfl_xor_sync(0xffffffffu, rm0, 1));
        rm0 = fmaxf(rm0, __shfl_xor_sync(0xffffffffu, rm0, 2));
        rm1 = fmaxf(rm1, __shfl_xor_sync(0xffffffffu, rm1, 1));
        rm1 = fmaxf(rm1, __shfl_xor_sync(0xffffffffu, rm1, 2));
        float mn0 = fmaxf(mi0, rm0), mn1 = fmaxf(mi1, rm1);
        float al0 = expf(mi0 - mn0), al1 = expf(mi1 - mn1);
        float rs0 = 0.f, rs1 = 0.f;
#pragma unroll
        for (int j = 0; j < 8; j++) {
            sacc[j][0] = expf(sacc[j][0] - mn0); rs0 += sacc[j][0];
            sacc[j][1] = expf(sacc[j][1] - mn0); rs0 += sacc[j][1];
            sacc[j][2] = expf(sacc[j][2] - mn1); rs1 += sacc[j][2];
            sacc[j][3] = expf(sacc[j][3] - mn1); rs1 += sacc[j][3];
        }
        rs0 += __shfl_xor_sync(0xffffffffu, rs0, 1);
        rs0 += __shfl_xor_sync(0xffffffffu, rs0, 2);
        rs1 += __shfl_xor_sync(0xffffffffu, rs1, 1);
        rs1 += __shfl_xor_sync(0xffffffffu, rs1, 2);
        li0 = li0 * al0 + rs0; li1 = li1 * al1 + rs1;
        mi0 = mn0; mi1 = mn1;
#pragma unroll
        for (int t = 0; t < 8; t++) {
            oacc[t][0] *= al0; oacc[t][1] *= al0;
            oacc[t][2] *= al1; oacc[t][3] *= al1;
        }

        // O += P V
#pragma unroll
        for (int kb = 0; kb < 4; kb++) {
            unsigned pah[4], pal[4];
            sp2(sacc[2 * kb][0],     sacc[2 * kb][1],     pah[0], pal[0]);
            sp2(sacc[2 * kb][2],     sacc[2 * kb][3],     pah[1], pal[1]);
            sp2(sacc[2 * kb + 1][0], sacc[2 * kb + 1][1], pah[2], pal[2]);
            sp2(sacc[2 * kb + 1][2], sacc[2 * kb + 1][3], pah[3], pal[3]);
#pragma unroll
            for (int ndp = 0; ndp < 4; ndp++) {
                unsigned vh4[4], vl4[4];
                uint32_t o = va_off + (uint32_t)(kb * 16 * F_STRIDE + ndp * 16) * 2;
                ldm_x4_t(vh4, uVh + o);
                ldm_x4_t(vl4, uVl + o);
                mma16816(oacc[2 * ndp],     pah, vh4);
                mma16816(oacc[2 * ndp],     pah, vl4);
                mma16816(oacc[2 * ndp],     pal, vh4);
                mma16816(oacc[2 * ndp + 1], pah, vh4 + 2);
                mma16816(oacc[2 * ndp + 1], pah, vl4 + 2);
                mma16816(oacc[2 * ndp + 1], pal, vh4 + 2);
            }
        }
    }

    float inv0 = 1.f / li0, inv1 = 1.f / li1;
    int r = row0 + warpm * 16 + (lane >> 2);
    int cbase = h * 64 + (lane & 3) * 2;
#pragma unroll
    for (int dt = 0; dt < 8; dt++) {
        unsigned ph, pl;
        sp2(oacc[dt][0] * inv0, oacc[dt][1] * inv0, ph, pl);
        size_t idx = (size_t)(b * NS + r) * ND + cbase + dt * 8;
        *(unsigned*)(g_ah + idx) = ph;
        *(unsigned*)(g_al + idx) = pl;
        sp2(oacc[dt][2] * inv1, oacc[dt][3] * inv1, ph, pl);
        idx += (size_t)8 * ND;
        *(unsigned*)(g_ah + idx) = ph;
        *(unsigned*)(g_al + idx) = pl;
    }
}

// ---------------- reductions --------------------------------------------------
__device__ __forceinline__ void blk_reduce2(float& s, float& q)
{
    __shared__ float ss[8], sq[8];
#pragma unroll
    for (int o = 16; o; o >>= 1) {
        s += __shfl_xor_sync(0xffffffffu, s, o);
        q += __shfl_xor_sync(0xffffffffu, q, o);
    }
    int w = threadIdx.x >> 5, l = threadIdx.x & 31;
    if (l == 0) { ss[w] = s; sq[w] = q; }
    __syncthreads();
    s = (l < 8) ? ss[l] : 0.f;
    q = (l < 8) ? sq[l] : 0.f;
#pragma unroll
    for (int o = 4; o; o >>= 1) {
        s += __shfl_xor_sync(0xffffffffu, s, o);
        q += __shfl_xor_sync(0xffffffffu, q, o);
    }
    s = __shfl_sync(0xffffffffu, s, 0);
    q = __shfl_sync(0xffffffffu, q, 0);
}

// ---------------- elementwise -------------------------------------------------
__global__ __launch_bounds__(256) void k_cvt(const float* __restrict__ in,
                                             __nv_bfloat16* __restrict__ oh,
                                             __nv_bfloat16* __restrict__ ol)
{
    size_t i = (size_t)blockIdx.x * 256 + threadIdx.x;
    __nv_bfloat16 h, l;
    split2(in[i], h, l);
    oh[i] = h; ol[i] = l;
}

__global__ __launch_bounds__(256) void k_qscale(const float* __restrict__ sw)
{
    int wid = blockIdx.x * 8 + (threadIdx.x >> 5);
    int lane = threadIdx.x & 31;
    int h = wid & (NH - 1), t = wid >> 4;
    size_t i0 = (size_t)t * ND + h * 64 + lane;
    float q0 = __bfloat162float(g_qkvh[i0]) + __bfloat162float(g_qkvl[i0]);
    float q1 = __bfloat162float(g_qkvh[i0 + 32]) + __bfloat162float(g_qkvl[i0 + 32]);
    float s = q0 * sw[h * 64 + lane] + q1 * sw[h * 64 + lane + 32];
#pragma unroll
    for (int o = 16; o; o >>= 1) s += __shfl_xor_sync(0xffffffffu, s, o);
    if (lane == 0) {
        float sig = 1.f / (1.f + expf(-s));
        int b = t >> 10, si = t & (NS - 1);
        g_scalef[(b * NH + h) * NS + si] = 0.25f * sig;
    }
}

__global__ __launch_bounds__(256) void k_ln1(const float* __restrict__ g,
                                             const float* __restrict__ b)
{
    size_t r = blockIdx.x;
    const float* in = g_xres + r * ND;
    float x[4];
    float s = 0.f, q = 0.f;
#pragma unroll
    for (int l = 0; l < 4; l++) {
        x[l] = in[threadIdx.x + l * 256];
        s += x[l]; q += x[l] * x[l];
    }
    blk_reduce2(s, q);
    float mean = s * (1.f / ND);
    float var = q * (1.f / ND) - mean * mean;
    float rstd = rsqrtf(var + 1e-5f);
#pragma unroll
    for (int l = 0; l < 4; l++) {
        int c = threadIdx.x + l * 256;
        float v = (x[l] - mean) * rstd * g[c] + b[c];
        g_x[r * ND + c] = v;
        __nv_bfloat16 h, lo;
        split2(v, h, lo);
        g_xh[r * ND + c] = h; g_xl[r * ND + c] = lo;
    }
}

__global__ __launch_bounds__(256) void k_ln_out(const float* __restrict__ g,
                                                const float* __restrict__ b,
                                                float* __restrict__ out)
{
    size_t r = blockIdx.x;
    const float* in = g_z + r * ND;
    float x[4];
    float s = 0.f, q = 0.f;
#pragma unroll
    for (int l = 0; l < 4; l++) {
        x[l] = in[threadIdx.x + l * 256];
        s += x[l]; q += x[l] * x[l];
    }
    blk_reduce2(s, q);
    float mean = s * (1.f / ND);
    float var = q * (1.f / ND) - mean * mean;
    float rstd = rsqrtf(var + 1e-5f);
#pragma unroll
    for (int l = 0; l < 4; l++) {
        int c = threadIdx.x + l * 256;
        out[r * ND + c] = (x[l] - mean) * rstd * g[c] + b[c];
    }
}

__global__ __launch_bounds__(256) void k_route(const float* __restrict__ gw,
                                               const float* __restrict__ gb)
{
    __shared__ float lg[NE];
    int t = blockIdx.x;
    int w = threadIdx.x >> 5, lane = threadIdx.x & 31;
    const float* x = g_x + (size_t)t * ND;
    float s = 0.f;
    for (int d = lane; d < ND; d += 32) s += x[d] * gw[d * NE + w];
#pragma unroll
    for (int o = 16; o; o >>= 1) s += __shfl_xor_sync(0xffffffffu, s, o);
    if (lane == 0) lg[w] = s + gb[w];
    __syncthreads();
    if (threadIdx.x == 0) {
        int i1 = 0; float v1 = lg[0];
#pragma unroll
        for (int e = 1; e < NE; e++) if (lg[e] > v1) { v1 = lg[e]; i1 = e; }
        int i2 = -1; float v2 = -1e30f;
#pragma unroll
        for (int e = 0; e < NE; e++) if (e != i1 && lg[e] > v2) { v2 = lg[e]; i2 = e; }
        g_esel[t] = (i1 > i2) ? i1 : i2;
    }
}

__global__ void k_scatter()
{
    __shared__ int scnt[NE], soff[NE], scur[NE];
    int tid = threadIdx.x;
    if (tid < NE) scnt[tid] = 0;
    __syncthreads();
    for (int t = tid; t < NT; t += 1024) atomicAdd(&scnt[g_esel[t]], 1);
    __syncthreads();
    if (tid == 0) {
        int r = 0;
        for (int e = 0; e < NE; e++) { soff[e] = r; r += scnt[e]; }
    }
    __syncthreads();
    if (tid < NE) { scur[tid] = soff[tid]; g_off[tid] = soff[tid]; g_cnt[tid] = scnt[tid]; }
    __syncthreads();
    for (int t = tid; t < NT; t += 1024) {
        int e = g_esel[t];
        int pos = atomicAdd(&scur[e], 1);
        g_perm[pos] = t;
        g_eid[pos] = e;
    }
}

__global__ __launch_bounds__(256) void k_lngelu(const float* __restrict__ lng,
                                                const float* __restrict__ lnb)
{
    int row = blockIdx.x;
    int e = g_eid[row];
    const float* hp = g_h + (size_t)row * NF;
    float x[16];
    float s = 0.f, q = 0.f;
#pragma unroll
    for (int l = 0; l < 16; l++) {
        x[l] = hp[threadIdx.x + l * 256];
        s += x[l]; q += x[l] * x[l];
    }
    blk_reduce2(s, q);
    float mean = s * (1.f / NF);
    float var = q * (1.f / NF) - mean * mean;
    float rstd = rsqrtf(var + 1e-5f);
    const float* g = lng + (size_t)e * NF;
    const float* b = lnb + (size_t)e * NF;
#pragma unroll
    for (int l = 0; l < 16; l++) {
        int c = threadIdx.x + l * 256;
        float hn = (x[l] - mean) * rstd * g[c] + b[c];
        float gel = 0.5f * hn * (1.f + erff(hn * 0.70710678118654752f));
        __nv_bfloat16 hh, ll;
        split2(gel, hh, ll);
        g_hh[(size_t)row * NF + c] = hh;
        g_hl[(size_t)row * NF + c] = ll;
    }
}

// ---------------- launch ------------------------------------------------------
extern "C" void kernel_launch(void* const* d_in, const int* in_sizes, int n_in,
                              void* d_out, int out_size)
{
    (void)in_sizes; (void)n_in; (void)out_size;
    const float* src        = (const float*)d_in[0];
    const float* qw         = (const float*)d_in[1];
    const float* kw         = (const float*)d_in[2];
    const float* vw         = (const float*)d_in[3];
    const float* ow         = (const float*)d_in[4];
    const float* gate_w     = (const float*)d_in[5];
    const float* gate_b     = (const float*)d_in[6];
    const float* scale_w    = (const float*)d_in[7];
    const float* n1_g       = (const float*)d_in[8];
    const float* n1_b       = (const float*)d_in[9];
    const float* n2_g       = (const float*)d_in[10];
    const float* n2_b       = (const float*)d_in[11];
    const float* moe_gate_w = (const float*)d_in[12];
    const float* moe_gate_b = (const float*)d_in[13];
    const float* w1         = (const float*)d_in[14];
    const float* b1         = (const float*)d_in[15];
    const float* ln_g       = (const float*)d_in[16];
    const float* ln_b       = (const float*)d_in[17];
    const float* w2         = (const float*)d_in[18];
    const float* b2         = (const float*)d_in[19];
    const float* res_scale  = (const float*)d_in[20];
    float* out = (float*)d_out;

    static int attr_done = 0;
    cudaFuncSetAttribute(k_mm<0>, cudaFuncAttributeMaxDynamicSharedMemorySize, GEMM_SMEM);
    cudaFuncSetAttribute(k_mm<1>, cudaFuncAttributeMaxDynamicSharedMemorySize, GEMM_SMEM);
    cudaFuncSetAttribute(k_mm<2>, cudaFuncAttributeMaxDynamicSharedMemorySize, GEMM_SMEM);
    cudaFuncSetAttribute(k_mm<3>, cudaFuncAttributeMaxDynamicSharedMemorySize, GEMM_SMEM);
    cudaFuncSetAttribute(k_mm<4>, cudaFuncAttributeMaxDynamicSharedMemorySize, GEMM_SMEM);
    cudaFuncSetAttribute(k_flash, cudaFuncAttributeMaxDynamicSharedMemorySize, FLASH_SMEM);
    (void)attr_done;

    __nv_bfloat16 *sh, *sl, *qkvh, *qkvl, *ah, *al, *gh, *gl, *xh, *xl, *hh, *hl;
    __nv_bfloat16 *wqkvh, *wqkvl, *wgh, *wgl, *woh, *wol, *w1h, *w1l, *w2h, *w2l;
    float *xres, *x, *z, *hbuf;
    cudaGetSymbolAddress((void**)&sh, g_sh);       cudaGetSymbolAddress((void**)&sl, g_sl);
    cudaGetSymbolAddress((void**)&qkvh, g_qkvh);   cudaGetSymbolAddress((void**)&qkvl, g_qkvl);
    cudaGetSymbolAddress((void**)&ah, g_ah);       cudaGetSymbolAddress((void**)&al, g_al);
    cudaGetSymbolAddress((void**)&gh, g_gh);       cudaGetSymbolAddress((void**)&gl, g_gl);
    cudaGetSymbolAddress((void**)&xh, g_xh);       cudaGetSymbolAddress((void**)&xl, g_xl);
    cudaGetSymbolAddress((void**)&hh, g_hh);       cudaGetSymbolAddress((void**)&hl, g_hl);
    cudaGetSymbolAddress((void**)&wqkvh, g_wqkvh); cudaGetSymbolAddress((void**)&wqkvl, g_wqkvl);
    cudaGetSymbolAddress((void**)&wgh, g_wgh);     cudaGetSymbolAddress((void**)&wgl, g_wgl);
    cudaGetSymbolAddress((void**)&woh, g_woh);     cudaGetSymbolAddress((void**)&wol, g_wol);
    cudaGetSymbolAddress((void**)&w1h, g_w1h);     cudaGetSymbolAddress((void**)&w1l, g_w1l);
    cudaGetSymbolAddress((void**)&w2h, g_w2h);     cudaGetSymbolAddress((void**)&w2l, g_w2l);
    cudaGetSymbolAddress((void**)&xres, g_xres);
    cudaGetSymbolAddress((void**)&x, g_x);
    cudaGetSymbolAddress((void**)&z, g_z);
    cudaGetSymbolAddress((void**)&hbuf, g_h);

    // pre-split conversions
    k_cvt<<<NT * ND / 256, 256>>>(src, sh, sl);
    k_cvt<<<ND * ND / 256, 256>>>(qw, wqkvh, wqkvl);
    k_cvt<<<ND * ND / 256, 256>>>(kw, wqkvh + ND * ND, wqkvl + ND * ND);
    k_cvt<<<ND * ND / 256, 256>>>(vw, wqkvh + 2 * ND * ND, wqkvl + 2 * ND * ND);
    k_cvt<<<ND * ND / 256, 256>>>(gate_w, wgh, wgl);
    k_cvt<<<ND * ND / 256, 256>>>(ow, woh, wol);
    k_cvt<<<(int)((size_t)NE * ND * NF / 256), 256>>>(w1, w1h, w1l);
    k_cvt<<<(int)((size_t)NE * NF * ND / 256), 256>>>(w2, w2h, w2l);

    k_mm<0><<<dim3(ND / TN, NT / TM, 3), 256, GEMM_SMEM>>>(sh, sl, wqkvh, wqkvl, ND, ND,
        nullptr, nullptr, nullptr, qkvh, qkvl, nullptr);
    k_qscale<<<(NT * NH) / 8, 256>>>(scale_w);
    k_flash<<<dim3(NS / 64, NB * NH), 128, FLASH_SMEM>>>();
    k_mm<1><<<dim3(ND / TN, NT / TM), 256, GEMM_SMEM>>>(ah, al, wgh, wgl, ND, ND,
        gate_b, nullptr, nullptr, gh, gl, nullptr);
    k_mm<2><<<dim3(ND / TN, NT / TM), 256, GEMM_SMEM>>>(gh, gl, woh, wol, ND, ND,
        nullptr, src, nullptr, nullptr, nullptr, xres);
    k_ln1<<<NT, 256>>>(n1_g, n1_b);
    k_route<<<NT, 256>>>(moe_gate_w, moe_gate_b);
    k_scatter<<<1, 1024>>>();
    k_mm<3><<<dim3(NF / TN, NT / TM, NE), 256, GEMM_SMEM>>>(xh, xl, w1h, w1l, ND, NF,
        b1, nullptr, nullptr, nullptr, nullptr, hbuf);
    k_lngelu<<<NT, 256>>>(ln_g, ln_b);
    k_mm<4><<<dim3(ND / TN, NT / TM, NE), 256, GEMM_SMEM>>>(hh, hl, w2h, w2l, NF, ND,
        b2, x, res_scale, nullptr, nullptr, z);
    k_ln_out<<<NT, 256>>>(n2_g, n2_b, out);
}

// round 5
// speedup vs baseline: 2.3232x; 1.0612x over previous
#include <cuda_runtime.h>
#include <cuda_bf16.h>
#include <math.h>
#include <stdint.h>

#define NB 2
#define NS 1024
#define ND 1024
#define NH 16
#define NE 8
#define NF 4096
#define NT 2048

#define TM 128
#define TN 128
#define KC 32
#define A_STRIDE 40    // bf16 elems per A smem row (80B)
#define B_STRIDE 136   // bf16 elems per B smem row (272B)

// layout for BF16-B variant (pre-split B)
#define ST_AH 0
#define ST_AL 10240
#define ST_BH 20480
#define ST_BL 29184
#define STAGE_BYTES 37888
#define GEMM_SMEM (2 * STAGE_BYTES)

// layout for FP32-B variant (in-kernel split)
#define S2_AH 0
#define S2_AL 10240
#define S2_B32 20480
#define S2_STAGE 36864
#define S2_BH (2 * S2_STAGE)
#define S2_BL (S2_BH + 8704)
#define GEMM_SMEM2 (S2_BL + 8704)

#define F_STRIDE 72    // flash smem row stride (144B)
#define F_QH 0
#define F_QL 9216
#define F_KH 18432
#define F_KL 27648
#define F_VH 36864
#define F_VL 46080
#define FLASH_SMEM 55296

// ---------------- scratch ----------------------------------------------------
__device__ __nv_bfloat16 g_sh[NT * ND], g_sl[NT * ND];
__device__ __nv_bfloat16 g_qkvh[3 * NT * ND], g_qkvl[3 * NT * ND];
__device__ __nv_bfloat16 g_ah[NT * ND], g_al[NT * ND];
__device__ __nv_bfloat16 g_gh[NT * ND], g_gl[NT * ND];
__device__ __nv_bfloat16 g_xh[NT * ND], g_xl[NT * ND];
__device__ __nv_bfloat16 g_hh[(size_t)NT * NF], g_hl[(size_t)NT * NF];
__device__ __nv_bfloat16 g_wqkvh[3 * ND * ND], g_wqkvl[3 * ND * ND];
__device__ __nv_bfloat16 g_wgh[ND * ND], g_wgl[ND * ND];
__device__ __nv_bfloat16 g_woh[ND * ND], g_wol[ND * ND];
__device__ float g_scalef[NB * NH * NS];
__device__ float g_xres[NT * ND];
__device__ float g_x[NT * ND];
__device__ float g_z[NT * ND];
__device__ float g_h[(size_t)NT * NF];
__device__ int g_esel[NT];
__device__ int g_perm[NT];
__device__ int g_eid[NT];
__device__ int g_off[NE];
__device__ int g_cnt[NE];

// ---------------- helpers ----------------------------------------------------
__device__ __forceinline__ uint32_t s2u(const void* p) {
    uint32_t a;
    asm("{ .reg .u64 t; cvta.to.shared.u64 t, %1; cvt.u32.u64 %0, t; }" : "=r"(a) : "l"(p));
    return a;
}
__device__ __forceinline__ void split2(float x, __nv_bfloat16& h, __nv_bfloat16& l) {
    h = __float2bfloat16(x);
    l = __float2bfloat16(x - __bfloat162float(h));
}
__device__ __forceinline__ unsigned pk_bf2(float lo, float hi) {
    unsigned r;
    asm("cvt.rn.bf16x2.f32 %0, %1, %2;" : "=r"(r) : "f"(hi), "f"(lo));
    return r;
}
__device__ __forceinline__ void sp2(float a, float b, unsigned& h, unsigned& l) {
    __nv_bfloat16 ah = __float2bfloat16(a), bh = __float2bfloat16(b);
    h = (unsigned)__bfloat16_as_ushort(ah) | ((unsigned)__bfloat16_as_ushort(bh) << 16);
    l = pk_bf2(a - __bfloat162float(ah), b - __bfloat162float(bh));
}
__device__ __forceinline__ void ldm_x4(unsigned* r, uint32_t addr) {
    asm volatile("ldmatrix.sync.aligned.m8n8.x4.shared.b16 {%0,%1,%2,%3}, [%4];"
        : "=r"(r[0]), "=r"(r[1]), "=r"(r[2]), "=r"(r[3]) : "r"(addr));
}
__device__ __forceinline__ void ldm_x4_t(unsigned* r, uint32_t addr) {
    asm volatile("ldmatrix.sync.aligned.m8n8.x4.trans.shared.b16 {%0,%1,%2,%3}, [%4];"
        : "=r"(r[0]), "=r"(r[1]), "=r"(r[2]), "=r"(r[3]) : "r"(addr));
}
__device__ __forceinline__ void mma16816(float* c, const unsigned* a, const unsigned* b) {
    asm volatile(
        "mma.sync.aligned.m16n8k16.row.col.f32.bf16.bf16.f32 "
        "{%0,%1,%2,%3}, {%4,%5,%6,%7}, {%8,%9}, {%0,%1,%2,%3};"
        : "+f"(c[0]), "+f"(c[1]), "+f"(c[2]), "+f"(c[3])
        : "r"(a[0]), "r"(a[1]), "r"(a[2]), "r"(a[3]), "r"(b[0]), "r"(b[1]));
}
__device__ __forceinline__ void cpa(uint32_t d, const void* s, int szvalid) {
    asm volatile("cp.async.cg.shared.global [%0], [%1], 16, %2;"
        :: "r"(d), "l"(__cvta_generic_to_global(s)), "r"(szvalid));
}

// ---------------- pipelined mma.sync split-bf16 GEMM --------------------------
// C[128,128] = A[M,K] @ B[K,N]; A pre-split bf16 hi/lo.
// BF32 == 0: B pre-split bf16 hi/lo.  BF32 == 1: B fp32, split in-kernel.
// OP: 0 merged QKV | 1 gate | 2 ow (+src) | 3 ffn1 gather +b1 | 4 ffn2
template <int OP, int BF32>
__global__ void __launch_bounds__(256, 2) k_mm(
    const __nv_bfloat16* __restrict__ Ah, const __nv_bfloat16* __restrict__ Al,
    const __nv_bfloat16* __restrict__ Bh, const __nv_bfloat16* __restrict__ Bl,
    const float* __restrict__ B32, int K, int ldB,
    const float* __restrict__ bias, const float* __restrict__ extra,
    const float* __restrict__ extra2,
    __nv_bfloat16* __restrict__ Oh, __nv_bfloat16* __restrict__ Ol,
    float* __restrict__ Of)
{
    extern __shared__ __align__(16) char sm[];
    __shared__ int rloc[TM];

    const int tid = threadIdx.x;
    const int lane = tid & 31, wid = tid >> 5;
    const int warp_m = wid >> 2, warp_n = wid & 3;
    const int row0 = blockIdx.y * TM, col0 = blockIdx.x * TN;
    const int e = blockIdx.z;
    int cnt = 0, off = 0;
    if (OP == 0) {
        size_t zo = (size_t)e * ND * ND;
        Bh += zo; Bl += zo;
        size_t oo = (size_t)e * NT * ND;
        Oh += oo; Ol += oo;
    }
    if (OP == 3 || OP == 4) {
        cnt = g_cnt[e]; off = g_off[e];
        if (row0 >= cnt) return;
        B32 += (size_t)e * K * ldB;
    }
    if (OP == 3) {
        if (tid < TM) {
            int gr = row0 + tid;
            rloc[tid] = (gr < cnt) ? g_perm[off + gr] : -1;
        }
        __syncthreads();
    }

    const int am = tid >> 1, ahalf = tid & 1;
    int arow;
    if (OP == 3) arow = rloc[am];
    else if (OP == 4) arow = min(off + row0 + am, NT - 1);
    else arow = row0 + am;
    const int apred = (arow >= 0) ? 16 : 0;
    const int arows = (arow >= 0) ? arow : 0;
    const char* gAh = (const char*)(Ah + (size_t)arows * K + ahalf * 16);
    const char* gAl = (const char*)(Al + (size_t)arows * K + ahalf * 16);
    const int bk = tid >> 3, bseg = tid & 7;
    const char* gBh = nullptr;
    const char* gBl = nullptr;
    const char* gB32 = nullptr;
    if (BF32) {
        gB32 = (const char*)(B32 + (size_t)bk * ldB + col0 + bseg * 16);
    } else {
        gBh = (const char*)(Bh + (size_t)bk * ldB + col0 + bseg * 16);
        gBl = (const char*)(Bl + (size_t)bk * ldB + col0 + bseg * 16);
    }

    const uint32_t ub = s2u(sm);
    const int stageBytes = BF32 ? S2_STAGE : STAGE_BYTES;
    const uint32_t aDst = ub + am * 80 + ahalf * 32;
    const uint32_t bDst = BF32 ? (ub + S2_B32 + bk * 512 + bseg * 64)
                               : (ub + ST_BH + bk * 272 + bseg * 32);

    auto issue = [&](int stage, int c) {
        uint32_t sb = stage * stageBytes;
        size_t ao = (size_t)c * KC * 2;
        cpa(aDst + sb,           gAh + ao,      apred);
        cpa(aDst + sb + 16,      gAh + ao + 16, apred);
        cpa(aDst + sb + ST_AL,      gAl + ao,      apred);
        cpa(aDst + sb + ST_AL + 16, gAl + ao + 16, apred);
        if (BF32) {
            size_t bo = (size_t)c * KC * ldB * 4;
#pragma unroll
            for (int i = 0; i < 4; i++)
                cpa(bDst + sb + i * 16, gB32 + bo + i * 16, 16);
        } else {
            size_t bo = (size_t)c * KC * ldB * 2;
            cpa(bDst + sb,                      gBh + bo,      16);
            cpa(bDst + sb + 16,                 gBh + bo + 16, 16);
            cpa(bDst + sb + (ST_BL - ST_BH),      gBl + bo,      16);
            cpa(bDst + sb + (ST_BL - ST_BH) + 16, gBl + bo + 16, 16);
        }
        asm volatile("cp.async.commit_group;");
    };

    float acc[16][4];
#pragma unroll
    for (int t = 0; t < 16; t++)
#pragma unroll
        for (int i = 0; i < 4; i++) acc[t][i] = 0.f;

    const int nch = K / KC;
    issue(0, 0);
    issue(1, 1);

    for (int c = 0; c < nch; c++) {
        asm volatile("cp.async.wait_group 1;");
        __syncthreads();
        uint32_t sb = ub + (c & 1) * stageBytes;
        uint32_t uAh_ = sb + S2_AH, uAl_ = sb + ST_AL;
        uint32_t uBh_, uBl_;
        if (BF32) {
            // convert fp32 B stage -> shared single-buffer bf16 hi/lo
            const float* bsrc = (const float*)(sm + (c & 1) * S2_STAGE + S2_B32) + bk * 128 + bseg * 16;
            unsigned hh8[8], ll8[8];
#pragma unroll
            for (int j = 0; j < 8; j++) sp2(bsrc[2 * j], bsrc[2 * j + 1], hh8[j], ll8[j]);
            char* dbh = sm + S2_BH + bk * 272 + bseg * 32;
            char* dbl = sm + S2_BL + bk * 272 + bseg * 32;
            *(uint4*)dbh = *(uint4*)hh8; *(uint4*)(dbh + 16) = *(uint4*)(hh8 + 4);
            *(uint4*)dbl = *(uint4*)ll8; *(uint4*)(dbl + 16) = *(uint4*)(ll8 + 4);
            __syncthreads();
            uBh_ = ub + S2_BH; uBl_ = ub + S2_BL;
        } else {
            uBh_ = sb + ST_BH; uBl_ = sb + ST_BL;
        }
#pragma unroll
        for (int ks = 0; ks < 2; ks++) {
            unsigned bh_[2][4], bl_[2][4];
#pragma unroll
            for (int nt = 0; nt < 2; nt++) {
                int krow = ks * 16 + (lane & 7) + ((lane >> 3) & 1) * 8;
                int ncol = warp_n * 32 + nt * 16 + (lane >> 4) * 8;
                uint32_t o = (uint32_t)(krow * B_STRIDE + ncol) * 2;
                ldm_x4_t(bh_[nt], uBh_ + o);
                ldm_x4_t(bl_[nt], uBl_ + o);
            }
#pragma unroll
            for (int mt = 0; mt < 4; mt++) {
                unsigned ah_[4], al_[4];
                int mrow = warp_m * 64 + mt * 16 + (lane & 15);
                int kcol = ks * 16 + (lane >> 4) * 8;
                uint32_t o = (uint32_t)(mrow * A_STRIDE + kcol) * 2;
                ldm_x4(ah_, uAh_ + o);
                ldm_x4(al_, uAl_ + o);
#pragma unroll
                for (int nt = 0; nt < 2; nt++)
#pragma unroll
                    for (int j = 0; j < 2; j++) {
                        float* cc = acc[mt * 4 + nt * 2 + j];
                        mma16816(cc, ah_, bh_[nt] + j * 2);
                        mma16816(cc, ah_, bl_[nt] + j * 2);
                        mma16816(cc, al_, bh_[nt] + j * 2);
                    }
            }
        }
        __syncthreads();
        if (c + 2 < nch) issue(c & 1, c + 2);
        else asm volatile("cp.async.commit_group;");
    }

    // ---- epilogue ----
    float rs = 0.f;
    if (OP == 4) rs = extra2[e];
#pragma unroll
    for (int mt = 0; mt < 4; mt++)
#pragma unroll
        for (int nt = 0; nt < 2; nt++)
#pragma unroll
            for (int j = 0; j < 2; j++) {
                float* cc = acc[mt * 4 + nt * 2 + j];
                int lcol = warp_n * 32 + nt * 16 + j * 8 + (lane & 3) * 2;
                int gcol = col0 + lcol;
#pragma unroll
                for (int half = 0; half < 2; half++) {
                    int lrow = warp_m * 64 + mt * 16 + (lane >> 2) + half * 8;
                    int gr = row0 + lrow;
                    float v0 = cc[half * 2], v1 = cc[half * 2 + 1];
                    if (OP == 0) {
                        size_t base = (size_t)gr * ND + gcol;
                        unsigned h, l;
                        sp2(v0, v1, h, l);
                        *(unsigned*)(Oh + base) = h;
                        *(unsigned*)(Ol + base) = l;
                    } else if (OP == 1) {
                        size_t base = (size_t)gr * ND + gcol;
                        float g0 = 1.f / (1.f + expf(-(v0 + bias[gcol])));
                        float g1 = 1.f / (1.f + expf(-(v1 + bias[gcol + 1])));
                        float a0 = __bfloat162float(Ah[base]) + __bfloat162float(Al[base]);
                        float a1 = __bfloat162float(Ah[base + 1]) + __bfloat162float(Al[base + 1]);
                        unsigned h, l;
                        sp2(a0 * g0, a1 * g1, h, l);
                        *(unsigned*)(Oh + base) = h;
                        *(unsigned*)(Ol + base) = l;
                    } else if (OP == 2) {
                        size_t base = (size_t)gr * ND + gcol;
                        float2 o2;
                        o2.x = extra[base] + v0;
                        o2.y = extra[base + 1] + v1;
                        *(float2*)(Of + base) = o2;
                    } else if (OP == 3) {
                        if (gr < cnt) {
                            size_t base = (size_t)(off + gr) * NF + gcol;
                            float2 o2;
                            o2.x = v0 + bias[e * NF + gcol];
                            o2.y = v1 + bias[e * NF + gcol + 1];
                            *(float2*)(Of + base) = o2;
                        }
                    } else if (OP == 4) {
                        if (gr < cnt) {
                            int t = g_perm[off + gr];
                            size_t bx = (size_t)t * ND + gcol;
                            float2 o2;
                            o2.x = 2.f * extra[bx] + rs * (v0 + bias[e * ND + gcol]);
                            o2.y = 2.f * extra[bx + 1] + rs * (v1 + bias[e * ND + gcol + 1]);
                            *(float2*)(Of + bx) = o2;
                        }
                    }
                }
            }
}

// ---------------- mma.sync flash attention ------------------------------------
__global__ void __launch_bounds__(128, 3) k_flash()
{
    extern __shared__ __align__(16) char fsm[];
    const int tid = threadIdx.x, lane = tid & 31, warpm = tid >> 5;
    const int bh = blockIdx.y, b = bh >> 4, h = bh & 15;
    const int row0 = blockIdx.x * 64;

    const __nv_bfloat16* Qh = g_qkvh;
    const __nv_bfloat16* Ql = g_qkvl;
    const __nv_bfloat16* Kh = g_qkvh + (size_t)NT * ND;
    const __nv_bfloat16* Kl = g_qkvl + (size_t)NT * ND;
    const __nv_bfloat16* Vh = g_qkvh + (size_t)2 * NT * ND;
    const __nv_bfloat16* Vl = g_qkvl + (size_t)2 * NT * ND;

    {
        int m = tid >> 1, half = tid & 1;
        float sc = g_scalef[bh * NS + row0 + m];
        const __nv_bfloat16* sh_ = Qh + (size_t)(b * NS + row0 + m) * ND + h * 64 + half * 32;
        const __nv_bfloat16* sl_ = Ql + (size_t)(b * NS + row0 + m) * ND + h * 64 + half * 32;
        char* dh = fsm + F_QH + m * 144 + half * 64;
        char* dl = fsm + F_QL + m * 144 + half * 64;
#pragma unroll
        for (int i = 0; i < 4; i++) {
            __nv_bfloat16 hb[8], lb[8], oh[8], ol[8];
            *(uint4*)hb = *(const uint4*)(sh_ + i * 8);
            *(uint4*)lb = *(const uint4*)(sl_ + i * 8);
#pragma unroll
            for (int j = 0; j < 8; j++) {
                float f = (__bfloat162float(hb[j]) + __bfloat162float(lb[j])) * sc;
                split2(f, oh[j], ol[j]);
            }
            *(uint4*)(dh + i * 16) = *(uint4*)oh;
            *(uint4*)(dl + i * 16) = *(uint4*)ol;
        }
    }

    const uint32_t ubase = s2u(fsm);
    const uint32_t uQh = ubase + F_QH, uQl = ubase + F_QL;
    const uint32_t uKh = ubase + F_KH, uKl = ubase + F_KL;
    const uint32_t uVh = ubase + F_VH, uVl = ubase + F_VL;

    const uint32_t qa_off = ((warpm * 16 + (lane & 15)) * F_STRIDE + ((lane >> 4) & 1) * 8) * 2;
    const uint32_t ka_off = (((lane & 7) + ((lane >> 4) << 3)) * F_STRIDE + ((lane >> 3) & 1) * 8) * 2;
    const uint32_t va_off = (((lane & 7) + ((lane >> 3) & 1) * 8) * F_STRIDE + ((lane >> 4) & 1) * 8) * 2;

    float oacc[8][4];
#pragma unroll
    for (int t = 0; t < 8; t++)
#pragma unroll
        for (int i = 0; i < 4; i++) oacc[t][i] = 0.f;
    float mi0 = -1e30f, mi1 = -1e30f, li0 = 0.f, li1 = 0.f;

    for (int jt = 0; jt < NS / 64; jt++) {
        __syncthreads();
        {
            int m = tid >> 1, half = tid & 1;
            size_t gsrc = (size_t)(b * NS + jt * 64 + m) * ND + h * 64 + half * 32;
            char* dkh = fsm + F_KH + m * 144 + half * 64;
            char* dkl = fsm + F_KL + m * 144 + half * 64;
            char* dvh = fsm + F_VH + m * 144 + half * 64;
            char* dvl = fsm + F_VL + m * 144 + half * 64;
#pragma unroll
            for (int i = 0; i < 4; i++) {
                *(uint4*)(dkh + i * 16) = *(const uint4*)((const char*)(Kh + gsrc) + i * 16);
                *(uint4*)(dkl + i * 16) = *(const uint4*)((const char*)(Kl + gsrc) + i * 16);
                *(uint4*)(dvh + i * 16) = *(const uint4*)((const char*)(Vh + gsrc) + i * 16);
                *(uint4*)(dvl + i * 16) = *(const uint4*)((const char*)(Vl + gsrc) + i * 16);
            }
        }
        __syncthreads();

        float sacc[8][4];
#pragma unroll
        for (int t = 0; t < 8; t++)
#pragma unroll
            for (int i = 0; i < 4; i++) sacc[t][i] = 0.f;
#pragma unroll
        for (int ks = 0; ks < 4; ks++) {
            unsigned qh4[4], ql4[4];
            ldm_x4(qh4, uQh + qa_off + ks * 32);
            ldm_x4(ql4, uQl + qa_off + ks * 32);
#pragma unroll
            for (int np = 0; np < 4; np++) {
                unsigned kh4[4], kl4[4];
                uint32_t o = ka_off + (uint32_t)(np * 16 * F_STRIDE + ks * 16) * 2;
                ldm_x4(kh4, uKh + o);
                ldm_x4(kl4, uKl + o);
                mma16816(sacc[2 * np],     qh4, kh4);
                mma16816(sacc[2 * np],     qh4, kl4);
                mma16816(sacc[2 * np],     ql4, kh4);
                mma16816(sacc[2 * np + 1], qh4, kh4 + 2);
                mma16816(sacc[2 * np + 1], qh4, kl4 + 2);
                mma16816(sacc[2 * np + 1], ql4, kh4 + 2);
            }
        }

        float rm0 = -1e30f, rm1 = -1e30f;
#pragma unroll
        for (int j = 0; j < 8; j++) {
            rm0 = fmaxf(rm0, fmaxf(sacc[j][0], sacc[j][1]));
            rm1 = fmaxf(rm1, fmaxf(sacc[j][2], sacc[j][3]));
        }
        rm0 = fmaxf(rm0, __shfl_xor_sync(0xffffffffu, rm0, 1));
        rm0 = fmaxf(rm0, __shfl_xor_sync(0xffffffffu, rm0, 2));
        rm1 = fmaxf(rm1, __shfl_xor_sync(0xffffffffu, rm1, 1));
        rm1 = fmaxf(rm1, __shfl_xor_sync(0xffffffffu, rm1, 2));
        float mn0 = fmaxf(mi0, rm0), mn1 = fmaxf(mi1, rm1);
        float al0 = expf(mi0 - mn0), al1 = expf(mi1 - mn1);
        float rs0 = 0.f, rs1 = 0.f;
#pragma unroll
        for (int j = 0; j < 8; j++) {
            sacc[j][0] = expf(sacc[j][0] - mn0); rs0 += sacc[j][0];
            sacc[j][1] = expf(sacc[j][1] - mn0); rs0 += sacc[j][1];
            sacc[j][2] = expf(sacc[j][2] - mn1); rs1 += sacc[j][2];
            sacc[j][3] = expf(sacc[j][3] - mn1); rs1 += sacc[j][3];
        }
        rs0 += __shfl_xor_sync(0xffffffffu, rs0, 1);
        rs0 += __shfl_xor_sync(0xffffffffu, rs0, 2);
        rs1 += __shfl_xor_sync(0xffffffffu, rs1, 1);
        rs1 += __shfl_xor_sync(0xffffffffu, rs1, 2);
        li0 = li0 * al0 + rs0; li1 = li1 * al1 + rs1;
        mi0 = mn0; mi1 = mn1;
#pragma unroll
        for (int t = 0; t < 8; t++) {
            oacc[t][0] *= al0; oacc[t][1] *= al0;
            oacc[t][2] *= al1; oacc[t][3] *= al1;
        }

#pragma unroll
        for (int kb = 0; kb < 4; kb++) {
            unsigned pah[4], pal[4];
            sp2(sacc[2 * kb][0],     sacc[2 * kb][1],     pah[0], pal[0]);
            sp2(sacc[2 * kb][2],     sacc[2 * kb][3],     pah[1], pal[1]);
            sp2(sacc[2 * kb + 1][0], sacc[2 * kb + 1][1], pah[2], pal[2]);
            sp2(sacc[2 * kb + 1][2], sacc[2 * kb + 1][3], pah[3], pal[3]);
#pragma unroll
            for (int ndp = 0; ndp < 4; ndp++) {
                unsigned vh4[4], vl4[4];
                uint32_t o = va_off + (uint32_t)(kb * 16 * F_STRIDE + ndp * 16) * 2;
                ldm_x4_t(vh4, uVh + o);
                ldm_x4_t(vl4, uVl + o);
                mma16816(oacc[2 * ndp],     pah, vh4);
                mma16816(oacc[2 * ndp],     pah, vl4);
                mma16816(oacc[2 * ndp],     pal, vh4);
                mma16816(oacc[2 * ndp + 1], pah, vh4 + 2);
                mma16816(oacc[2 * ndp + 1], pah, vl4 + 2);
                mma16816(oacc[2 * ndp + 1], pal, vh4 + 2);
            }
        }
    }

    float inv0 = 1.f / li0, inv1 = 1.f / li1;
    int r = row0 + warpm * 16 + (lane >> 2);
    int cbase = h * 64 + (lane & 3) * 2;
#pragma unroll
    for (int dt = 0; dt < 8; dt++) {
        unsigned ph, pl;
        sp2(oacc[dt][0] * inv0, oacc[dt][1] * inv0, ph, pl);
        size_t idx = (size_t)(b * NS + r) * ND + cbase + dt * 8;
        *(unsigned*)(g_ah + idx) = ph;
        *(unsigned*)(g_al + idx) = pl;
        sp2(oacc[dt][2] * inv1, oacc[dt][3] * inv1, ph, pl);
        idx += (size_t)8 * ND;
        *(unsigned*)(g_ah + idx) = ph;
        *(unsigned*)(g_al + idx) = pl;
    }
}

// ---------------- reductions --------------------------------------------------
__device__ __forceinline__ void blk_reduce2(float& s, float& q)
{
    __shared__ float ss[8], sq[8];
#pragma unroll
    for (int o = 16; o; o >>= 1) {
        s += __shfl_xor_sync(0xffffffffu, s, o);
        q += __shfl_xor_sync(0xffffffffu, q, o);
    }
    int w = threadIdx.x >> 5, l = threadIdx.x & 31;
    if (l == 0) { ss[w] = s; sq[w] = q; }
    __syncthreads();
    s = (l < 8) ? ss[l] : 0.f;
    q = (l < 8) ? sq[l] : 0.f;
#pragma unroll
    for (int o = 4; o; o >>= 1) {
        s += __shfl_xor_sync(0xffffffffu, s, o);
        q += __shfl_xor_sync(0xffffffffu, q, o);
    }
    s = __shfl_sync(0xffffffffu, s, 0);
    q = __shfl_sync(0xffffffffu, q, 0);
}

// ---------------- elementwise -------------------------------------------------
__global__ __launch_bounds__(256) void k_cvt(const float* __restrict__ in,
                                             __nv_bfloat16* __restrict__ oh,
                                             __nv_bfloat16* __restrict__ ol)
{
    size_t i = ((size_t)blockIdx.x * 256 + threadIdx.x) * 8;
    float4 a = *(const float4*)(in + i);
    float4 b = *(const float4*)(in + i + 4);
    unsigned h[4], l[4];
    sp2(a.x, a.y, h[0], l[0]);
    sp2(a.z, a.w, h[1], l[1]);
    sp2(b.x, b.y, h[2], l[2]);
    sp2(b.z, b.w, h[3], l[3]);
    *(uint4*)(oh + i) = *(uint4*)h;
    *(uint4*)(ol + i) = *(uint4*)l;
}

__global__ __launch_bounds__(256) void k_qscale(const float* __restrict__ sw)
{
    int wid = blockIdx.x * 8 + (threadIdx.x >> 5);
    int lane = threadIdx.x & 31;
    int h = wid & (NH - 1), t = wid >> 4;
    size_t i0 = (size_t)t * ND + h * 64 + lane;
    float q0 = __bfloat162float(g_qkvh[i0]) + __bfloat162float(g_qkvl[i0]);
    float q1 = __bfloat162float(g_qkvh[i0 + 32]) + __bfloat162float(g_qkvl[i0 + 32]);
    float s = q0 * sw[h * 64 + lane] + q1 * sw[h * 64 + lane + 32];
#pragma unroll
    for (int o = 16; o; o >>= 1) s += __shfl_xor_sync(0xffffffffu, s, o);
    if (lane == 0) {
        float sig = 1.f / (1.f + expf(-s));
        int b = t >> 10, si = t & (NS - 1);
        g_scalef[(b * NH + h) * NS + si] = 0.25f * sig;
    }
}

__global__ __launch_bounds__(256) void k_ln1(const float* __restrict__ g,
                                             const float* __restrict__ b)
{
    size_t r = blockIdx.x;
    const float* in = g_xres + r * ND;
    float x[4];
    float s = 0.f, q = 0.f;
#pragma unroll
    for (int l = 0; l < 4; l++) {
        x[l] = in[threadIdx.x + l * 256];
        s += x[l]; q += x[l] * x[l];
    }
    blk_reduce2(s, q);
    float mean = s * (1.f / ND);
    float var = q * (1.f / ND) - mean * mean;
    float rstd = rsqrtf(var + 1e-5f);
#pragma unroll
    for (int l = 0; l < 4; l++) {
        int c = threadIdx.x + l * 256;
        float v = (x[l] - mean) * rstd * g[c] + b[c];
        g_x[r * ND + c] = v;
        __nv_bfloat16 h, lo;
        split2(v, h, lo);
        g_xh[r * ND + c] = h; g_xl[r * ND + c] = lo;
    }
}

__global__ __launch_bounds__(256) void k_ln_out(const float* __restrict__ g,
                                                const float* __restrict__ b,
                                                float* __restrict__ out)
{
    size_t r = blockIdx.x;
    const float* in = g_z + r * ND;
    float x[4];
    float s = 0.f, q = 0.f;
#pragma unroll
    for (int l = 0; l < 4; l++) {
        x[l] = in[threadIdx.x + l * 256];
        s += x[l]; q += x[l] * x[l];
    }
    blk_reduce2(s, q);
    float mean = s * (1.f / ND);
    float var = q * (1.f / ND) - mean * mean;
    float rstd = rsqrtf(var + 1e-5f);
#pragma unroll
    for (int l = 0; l < 4; l++) {
        int c = threadIdx.x + l * 256;
        out[r * ND + c] = (x[l] - mean) * rstd * g[c] + b[c];
    }
}

__global__ __launch_bounds__(256) void k_route(const float* __restrict__ gw,
                                               const float* __restrict__ gb)
{
    __shared__ float lg[NE];
    int t = blockIdx.x;
    int w = threadIdx.x >> 5, lane = threadIdx.x & 31;
    const float* x = g_x + (size_t)t * ND;
    float s = 0.f;
    for (int d = lane; d < ND; d += 32) s += x[d] * gw[d * NE + w];
#pragma unroll
    for (int o = 16; o; o >>= 1) s += __shfl_xor_sync(0xffffffffu, s, o);
    if (lane == 0) lg[w] = s + gb[w];
    __syncthreads();
    if (threadIdx.x == 0) {
        int i1 = 0; float v1 = lg[0];
#pragma unroll
        for (int e = 1; e < NE; e++) if (lg[e] > v1) { v1 = lg[e]; i1 = e; }
        int i2 = -1; float v2 = -1e30f;
#pragma unroll
        for (int e = 0; e < NE; e++) if (e != i1 && lg[e] > v2) { v2 = lg[e]; i2 = e; }
        g_esel[t] = (i1 > i2) ? i1 : i2;
    }
}

__global__ void k_scatter()
{
    __shared__ int scnt[NE], soff[NE], scur[NE];
    int tid = threadIdx.x;
    if (tid < NE) scnt[tid] = 0;
    __syncthreads();
    for (int t = tid; t < NT; t += 1024) atomicAdd(&scnt[g_esel[t]], 1);
    __syncthreads();
    if (tid == 0) {
        int r = 0;
        for (int e = 0; e < NE; e++) { soff[e] = r; r += scnt[e]; }
    }
    __syncthreads();
    if (tid < NE) { scur[tid] = soff[tid]; g_off[tid] = soff[tid]; g_cnt[tid] = scnt[tid]; }
    __syncthreads();
    for (int t = tid; t < NT; t += 1024) {
        int e = g_esel[t];
        int pos = atomicAdd(&scur[e], 1);
        g_perm[pos] = t;
        g_eid[pos] = e;
    }
}

__global__ __launch_bounds__(256) void k_lngelu(const float* __restrict__ lng,
                                                const float* __restrict__ lnb)
{
    int row = blockIdx.x;
    int e = g_eid[row];
    const float* hp = g_h + (size_t)row * NF;
    float x[16];
    float s = 0.f, q = 0.f;
#pragma unroll
    for (int l = 0; l < 16; l++) {
        x[l] = hp[threadIdx.x + l * 256];
        s += x[l]; q += x[l] * x[l];
    }
    blk_reduce2(s, q);
    float mean = s * (1.f / NF);
    float var = q * (1.f / NF) - mean * mean;
    float rstd = rsqrtf(var + 1e-5f);
    const float* g = lng + (size_t)e * NF;
    const float* b = lnb + (size_t)e * NF;
#pragma unroll
    for (int l = 0; l < 16; l++) {
        int c = threadIdx.x + l * 256;
        float hn = (x[l] - mean) * rstd * g[c] + b[c];
        float gel = 0.5f * hn * (1.f + erff(hn * 0.70710678118654752f));
        __nv_bfloat16 hh, ll;
        split2(gel, hh, ll);
        g_hh[(size_t)row * NF + c] = hh;
        g_hl[(size_t)row * NF + c] = ll;
    }
}

// ---------------- launch ------------------------------------------------------
extern "C" void kernel_launch(void* const* d_in, const int* in_sizes, int n_in,
                              void* d_out, int out_size)
{
    (void)in_sizes; (void)n_in; (void)out_size;
    const float* src        = (const float*)d_in[0];
    const float* qw         = (const float*)d_in[1];
    const float* kw         = (const float*)d_in[2];
    const float* vw         = (const float*)d_in[3];
    const float* ow         = (const float*)d_in[4];
    const float* gate_w     = (const float*)d_in[5];
    const float* gate_b     = (const float*)d_in[6];
    const float* scale_w    = (const float*)d_in[7];
    const float* n1_g       = (const float*)d_in[8];
    const float* n1_b       = (const float*)d_in[9];
    const float* n2_g       = (const float*)d_in[10];
    const float* n2_b       = (const float*)d_in[11];
    const float* moe_gate_w = (const float*)d_in[12];
    const float* moe_gate_b = (const float*)d_in[13];
    const float* w1         = (const float*)d_in[14];
    const float* b1         = (const float*)d_in[15];
    const float* ln_g       = (const float*)d_in[16];
    const float* ln_b       = (const float*)d_in[17];
    const float* w2         = (const float*)d_in[18];
    const float* b2         = (const float*)d_in[19];
    const float* res_scale  = (const float*)d_in[20];
    float* out = (float*)d_out;

    cudaFuncSetAttribute((const void*)k_mm<0, 0>, cudaFuncAttributeMaxDynamicSharedMemorySize, GEMM_SMEM);
    cudaFuncSetAttribute((const void*)k_mm<1, 0>, cudaFuncAttributeMaxDynamicSharedMemorySize, GEMM_SMEM);
    cudaFuncSetAttribute((const void*)k_mm<2, 0>, cudaFuncAttributeMaxDynamicSharedMemorySize, GEMM_SMEM);
    cudaFuncSetAttribute((const void*)k_mm<3, 1>, cudaFuncAttributeMaxDynamicSharedMemorySize, GEMM_SMEM2);
    cudaFuncSetAttribute((const void*)k_mm<4, 1>, cudaFuncAttributeMaxDynamicSharedMemorySize, GEMM_SMEM2);
    cudaFuncSetAttribute((const void*)k_flash, cudaFuncAttributeMaxDynamicSharedMemorySize, FLASH_SMEM);

    __nv_bfloat16 *sh, *sl, *qkvh, *qkvl, *ah, *al, *gh, *gl, *xh, *xl, *hh, *hl;
    __nv_bfloat16 *wqkvh, *wqkvl, *wgh, *wgl, *woh, *wol;
    float *xres, *x, *z, *hbuf;
    cudaGetSymbolAddress((void**)&sh, g_sh);       cudaGetSymbolAddress((void**)&sl, g_sl);
    cudaGetSymbolAddress((void**)&qkvh, g_qkvh);   cudaGetSymbolAddress((void**)&qkvl, g_qkvl);
    cudaGetSymbolAddress((void**)&ah, g_ah);       cudaGetSymbolAddress((void**)&al, g_al);
    cudaGetSymbolAddress((void**)&gh, g_gh);       cudaGetSymbolAddress((void**)&gl, g_gl);
    cudaGetSymbolAddress((void**)&xh, g_xh);       cudaGetSymbolAddress((void**)&xl, g_xl);
    cudaGetSymbolAddress((void**)&hh, g_hh);       cudaGetSymbolAddress((void**)&hl, g_hl);
    cudaGetSymbolAddress((void**)&wqkvh, g_wqkvh); cudaGetSymbolAddress((void**)&wqkvl, g_wqkvl);
    cudaGetSymbolAddress((void**)&wgh, g_wgh);     cudaGetSymbolAddress((void**)&wgl, g_wgl);
    cudaGetSymbolAddress((void**)&woh, g_woh);     cudaGetSymbolAddress((void**)&wol, g_wol);
    cudaGetSymbolAddress((void**)&xres, g_xres);
    cudaGetSymbolAddress((void**)&x, g_x);
    cudaGetSymbolAddress((void**)&z, g_z);
    cudaGetSymbolAddress((void**)&hbuf, g_h);

    // pre-split conversions (small tensors only; w1/w2 converted in-kernel)
    k_cvt<<<NT * ND / 2048, 256>>>(src, sh, sl);
    k_cvt<<<ND * ND / 2048, 256>>>(qw, wqkvh, wqkvl);
    k_cvt<<<ND * ND / 2048, 256>>>(kw, wqkvh + ND * ND, wqkvl + ND * ND);
    k_cvt<<<ND * ND / 2048, 256>>>(vw, wqkvh + 2 * ND * ND, wqkvl + 2 * ND * ND);
    k_cvt<<<ND * ND / 2048, 256>>>(gate_w, wgh, wgl);
    k_cvt<<<ND * ND / 2048, 256>>>(ow, woh, wol);

    k_mm<0, 0><<<dim3(ND / TN, NT / TM, 3), 256, GEMM_SMEM>>>(sh, sl, wqkvh, wqkvl,
        nullptr, ND, ND, nullptr, nullptr, nullptr, qkvh, qkvl, nullptr);
    k_qscale<<<(NT * NH) / 8, 256>>>(scale_w);
    k_flash<<<dim3(NS / 64, NB * NH), 128, FLASH_SMEM>>>();
    k_mm<1, 0><<<dim3(ND / TN, NT / TM), 256, GEMM_SMEM>>>(ah, al, wgh, wgl,
        nullptr, ND, ND, gate_b, nullptr, nullptr, gh, gl, nullptr);
    k_mm<2, 0><<<dim3(ND / TN, NT / TM), 256, GEMM_SMEM>>>(gh, gl, woh, wol,
        nullptr, ND, ND, nullptr, src, nullptr, nullptr, nullptr, xres);
    k_ln1<<<NT, 256>>>(n1_g, n1_b);
    k_route<<<NT, 256>>>(moe_gate_w, moe_gate_b);
    k_scatter<<<1, 1024>>>();
    k_mm<3, 1><<<dim3(NF / TN, NT / TM, NE), 256, GEMM_SMEM2>>>(xh, xl, nullptr, nullptr,
        w1, ND, NF, b1, nullptr, nullptr, nullptr, nullptr, hbuf);
    k_lngelu<<<NT, 256>>>(ln_g, ln_b);
    k_mm<4, 1><<<dim3(ND / TN, NT / TM, NE), 256, GEMM_SMEM2>>>(hh, hl, nullptr, nullptr,
        w2, NF, ND, b2, x, res_scale, nullptr, nullptr, z);
    k_ln_out<<<NT, 256>>>(n2_g, n2_b, out);
}

// round 6
// speedup vs baseline: 2.9268x; 1.2598x over previous
#include <cuda_runtime.h>
#include <cuda_fp16.h>
#include <math.h>
#include <stdint.h>

#define NB 2
#define NS 1024
#define ND 1024
#define NH 16
#define NE 8
#define NF 4096
#define NT 2048

#define TM 128
#define TN 128
#define KC 32
#define A_STRIDE 40    // fp16 elems per A smem row (80B)
#define B_STRIDE 136   // fp16 elems per B smem row (272B)

// fp16-B variant (pre-split B): 3-stage
#define ST_AH 0
#define ST_AL 10240
#define ST_B  20480
#define STAGE_BYTES 29184
#define GEMM_SMEM (3 * STAGE_BYTES)

// fp32-B variant (in-kernel convert): 2-stage
#define S2_AH 0
#define S2_AL 10240
#define S2_B32 20480
#define S2_STAGE 36864
#define S2_B (2 * S2_STAGE)
#define GEMM_SMEM2 (S2_B + 8704)

#define F_STRIDE 72    // flash smem row stride (144B)
#define F_QH 0
#define F_QL 9216
#define F_K  18432
#define F_V  27648
#define FLASH_SMEM 36864

// ---------------- scratch ----------------------------------------------------
__device__ __half g_sh[NT * ND], g_sl[NT * ND];
__device__ __half g_qkv[3 * NT * ND];
__device__ __half g_ah[NT * ND], g_al[NT * ND];
__device__ __half g_gh[NT * ND], g_gl[NT * ND];
__device__ __half g_xh[NT * ND], g_xl[NT * ND];
__device__ __half g_hh[(size_t)NT * NF], g_hl[(size_t)NT * NF];
__device__ __half g_wqkv[3 * ND * ND];
__device__ __half g_wg[ND * ND];
__device__ __half g_wo[ND * ND];
__device__ float g_scalef[NB * NH * NS];
__device__ float g_xres[NT * ND];
__device__ float g_x[NT * ND];
__device__ float g_z[NT * ND];
__device__ float g_h[(size_t)NT * NF];
__device__ int g_esel[NT];
__device__ int g_perm[NT];
__device__ int g_eid[NT];
__device__ int g_off[NE];
__device__ int g_cnt[NE];

// ---------------- helpers ----------------------------------------------------
__device__ __forceinline__ uint32_t s2u(const void* p) {
    uint32_t a;
    asm("{ .reg .u64 t; cvta.to.shared.u64 t, %1; cvt.u32.u64 %0, t; }" : "=r"(a) : "l"(p));
    return a;
}
__device__ __forceinline__ void split2h(float x, __half& h, __half& l) {
    h = __float2half_rn(x);
    l = __float2half_rn(x - __half2float(h));
}
// split-pack two fp32 into fp16x2 hi + fp16x2 residual
__device__ __forceinline__ void sp2h(float a, float b, unsigned& h, unsigned& l) {
    __half2 hh = __floats2half2_rn(a, b);
    h = *reinterpret_cast<unsigned*>(&hh);
    float ra = a - __half2float(__low2half(hh));
    float rb = b - __half2float(__high2half(hh));
    __half2 ll = __floats2half2_rn(ra, rb);
    l = *reinterpret_cast<unsigned*>(&ll);
}
__device__ __forceinline__ unsigned pkh(float a, float b) {
    __half2 hh = __floats2half2_rn(a, b);
    return *reinterpret_cast<unsigned*>(&hh);
}
__device__ __forceinline__ void ldm_x4(unsigned* r, uint32_t addr) {
    asm volatile("ldmatrix.sync.aligned.m8n8.x4.shared.b16 {%0,%1,%2,%3}, [%4];"
        : "=r"(r[0]), "=r"(r[1]), "=r"(r[2]), "=r"(r[3]) : "r"(addr));
}
__device__ __forceinline__ void ldm_x4_t(unsigned* r, uint32_t addr) {
    asm volatile("ldmatrix.sync.aligned.m8n8.x4.trans.shared.b16 {%0,%1,%2,%3}, [%4];"
        : "=r"(r[0]), "=r"(r[1]), "=r"(r[2]), "=r"(r[3]) : "r"(addr));
}
__device__ __forceinline__ void mma16816(float* c, const unsigned* a, const unsigned* b) {
    asm volatile(
        "mma.sync.aligned.m16n8k16.row.col.f32.f16.f16.f32 "
        "{%0,%1,%2,%3}, {%4,%5,%6,%7}, {%8,%9}, {%0,%1,%2,%3};"
        : "+f"(c[0]), "+f"(c[1]), "+f"(c[2]), "+f"(c[3])
        : "r"(a[0]), "r"(a[1]), "r"(a[2]), "r"(a[3]), "r"(b[0]), "r"(b[1]));
}
__device__ __forceinline__ void cpa(uint32_t d, const void* s, int szvalid) {
    asm volatile("cp.async.cg.shared.global [%0], [%1], 16, %2;"
        :: "r"(d), "l"(__cvta_generic_to_global(s)), "r"(szvalid));
}

// ---------------- pipelined mma.sync fp16 2-term GEMM -------------------------
// C[128,128] = A[M,K] @ B[K,N]; A fp16 hi/lo (2 MMAs: ah*b + al*b).
// BF32==0: B pre-converted fp16 (3-stage).  BF32==1: B fp32, converted in-kernel (2-stage).
// OP: 0 merged QKV (fp16 out) | 1 gate | 2 ow (+src) | 3 ffn1 gather +b1 | 4 ffn2
template <int OP, int BF32>
__global__ void __launch_bounds__(256, 2) k_mm(
    const __half* __restrict__ Ah, const __half* __restrict__ Al,
    const __half* __restrict__ B16, const float* __restrict__ B32,
    int K, int ldB,
    const float* __restrict__ bias, const float* __restrict__ extra,
    const float* __restrict__ extra2,
    __half* __restrict__ Oh, __half* __restrict__ Ol,
    float* __restrict__ Of)
{
    extern __shared__ __align__(16) char sm[];
    __shared__ int rloc[TM];
    constexpr int NST = BF32 ? 2 : 3;
    constexpr int stageBytes = BF32 ? S2_STAGE : STAGE_BYTES;

    const int tid = threadIdx.x;
    const int lane = tid & 31, wid = tid >> 5;
    const int warp_m = wid >> 2, warp_n = wid & 3;
    const int row0 = blockIdx.y * TM, col0 = blockIdx.x * TN;
    const int e = blockIdx.z;
    int cnt = 0, off = 0;
    if (OP == 0) {
        B16 += (size_t)e * ND * ND;
        Oh += (size_t)e * NT * ND;
    }
    if (OP == 3 || OP == 4) {
        cnt = g_cnt[e]; off = g_off[e];
        if (row0 >= cnt) return;
        B32 += (size_t)e * K * ldB;
    }
    if (OP == 3) {
        if (tid < TM) {
            int gr = row0 + tid;
            rloc[tid] = (gr < cnt) ? g_perm[off + gr] : -1;
        }
        __syncthreads();
    }

    const int am = tid >> 1, ahalf = tid & 1;
    int arow;
    if (OP == 3) arow = rloc[am];
    else if (OP == 4) arow = min(off + row0 + am, NT - 1);
    else arow = row0 + am;
    const int apred = (arow >= 0) ? 16 : 0;
    const int arows = (arow >= 0) ? arow : 0;
    const char* gAh = (const char*)(Ah + (size_t)arows * K + ahalf * 16);
    const char* gAl = (const char*)(Al + (size_t)arows * K + ahalf * 16);
    const int bk = tid >> 3, bseg = tid & 7;
    const char* gB16 = nullptr;
    const char* gB32 = nullptr;
    if (BF32) gB32 = (const char*)(B32 + (size_t)bk * ldB + col0 + bseg * 16);
    else gB16 = (const char*)(B16 + (size_t)bk * ldB + col0 + bseg * 16);

    const uint32_t ub = s2u(sm);
    const uint32_t aDst = ub + am * 80 + ahalf * 32;
    const uint32_t bDst = BF32 ? (ub + S2_B32 + bk * 512 + bseg * 64)
                               : (ub + ST_B + bk * 272 + bseg * 32);

    auto issue = [&](int stage, int c) {
        uint32_t sb = stage * stageBytes;
        size_t ao = (size_t)c * KC * 2;
        cpa(aDst + sb,              gAh + ao,      apred);
        cpa(aDst + sb + 16,         gAh + ao + 16, apred);
        cpa(aDst + sb + ST_AL,      gAl + ao,      apred);
        cpa(aDst + sb + ST_AL + 16, gAl + ao + 16, apred);
        if (BF32) {
            size_t bo = (size_t)c * KC * ldB * 4;
#pragma unroll
            for (int i = 0; i < 4; i++)
                cpa(bDst + sb + i * 16, gB32 + bo + i * 16, 16);
        } else {
            size_t bo = (size_t)c * KC * ldB * 2;
            cpa(bDst + sb,      gB16 + bo,      16);
            cpa(bDst + sb + 16, gB16 + bo + 16, 16);
        }
        asm volatile("cp.async.commit_group;");
    };

    float acc[16][4];
#pragma unroll
    for (int t = 0; t < 16; t++)
#pragma unroll
        for (int i = 0; i < 4; i++) acc[t][i] = 0.f;

    const int nch = K / KC;
#pragma unroll
    for (int s = 0; s < NST; s++) issue(s, s);

    for (int c = 0; c < nch; c++) {
        if (BF32) asm volatile("cp.async.wait_group 1;");
        else      asm volatile("cp.async.wait_group 2;");
        __syncthreads();
        uint32_t sb = ub + (c % NST) * stageBytes;
        uint32_t uAh_ = sb + ST_AH, uAl_ = sb + ST_AL;
        uint32_t uB_;
        if (BF32) {
            const float* bsrc = (const float*)(sm + (c % NST) * S2_STAGE + S2_B32) + bk * 128 + bseg * 16;
            unsigned hh8[8];
#pragma unroll
            for (int j = 0; j < 8; j++) hh8[j] = pkh(bsrc[2 * j], bsrc[2 * j + 1]);
            char* db = sm + S2_B + bk * 272 + bseg * 32;
            *(uint4*)db = *(uint4*)hh8; *(uint4*)(db + 16) = *(uint4*)(hh8 + 4);
            __syncthreads();
            uB_ = ub + S2_B;
        } else {
            uB_ = sb + ST_B;
        }
#pragma unroll
        for (int ks = 0; ks < 2; ks++) {
            unsigned b_[2][4];
#pragma unroll
            for (int nt = 0; nt < 2; nt++) {
                int krow = ks * 16 + (lane & 7) + ((lane >> 3) & 1) * 8;
                int ncol = warp_n * 32 + nt * 16 + (lane >> 4) * 8;
                uint32_t o = (uint32_t)(krow * B_STRIDE + ncol) * 2;
                ldm_x4_t(b_[nt], uB_ + o);
            }
#pragma unroll
            for (int mt = 0; mt < 4; mt++) {
                unsigned ah_[4], al_[4];
                int mrow = warp_m * 64 + mt * 16 + (lane & 15);
                int kcol = ks * 16 + (lane >> 4) * 8;
                uint32_t o = (uint32_t)(mrow * A_STRIDE + kcol) * 2;
                ldm_x4(ah_, uAh_ + o);
                ldm_x4(al_, uAl_ + o);
#pragma unroll
                for (int nt = 0; nt < 2; nt++)
#pragma unroll
                    for (int j = 0; j < 2; j++) {
                        float* cc = acc[mt * 4 + nt * 2 + j];
                        mma16816(cc, ah_, b_[nt] + j * 2);
                        mma16816(cc, al_, b_[nt] + j * 2);
                    }
            }
        }
        __syncthreads();
        if (c + NST < nch) issue(c % NST, c + NST);
        else asm volatile("cp.async.commit_group;");
    }

    // ---- epilogue ----
    float rs = 0.f;
    if (OP == 4) rs = extra2[e];
#pragma unroll
    for (int mt = 0; mt < 4; mt++)
#pragma unroll
        for (int nt = 0; nt < 2; nt++)
#pragma unroll
            for (int j = 0; j < 2; j++) {
                float* cc = acc[mt * 4 + nt * 2 + j];
                int lcol = warp_n * 32 + nt * 16 + j * 8 + (lane & 3) * 2;
                int gcol = col0 + lcol;
#pragma unroll
                for (int half = 0; half < 2; half++) {
                    int lrow = warp_m * 64 + mt * 16 + (lane >> 2) + half * 8;
                    int gr = row0 + lrow;
                    float v0 = cc[half * 2], v1 = cc[half * 2 + 1];
                    if (OP == 0) {
                        size_t base = (size_t)gr * ND + gcol;
                        *(unsigned*)(Oh + base) = pkh(v0, v1);
                    } else if (OP == 1) {
                        size_t base = (size_t)gr * ND + gcol;
                        float g0 = 1.f / (1.f + expf(-(v0 + bias[gcol])));
                        float g1 = 1.f / (1.f + expf(-(v1 + bias[gcol + 1])));
                        float a0 = __half2float(Ah[base]) + __half2float(Al[base]);
                        float a1 = __half2float(Ah[base + 1]) + __half2float(Al[base + 1]);
                        unsigned h, l;
                        sp2h(a0 * g0, a1 * g1, h, l);
                        *(unsigned*)(Oh + base) = h;
                        *(unsigned*)(Ol + base) = l;
                    } else if (OP == 2) {
                        size_t base = (size_t)gr * ND + gcol;
                        float2 o2;
                        o2.x = extra[base] + v0;
                        o2.y = extra[base + 1] + v1;
                        *(float2*)(Of + base) = o2;
                    } else if (OP == 3) {
                        if (gr < cnt) {
                            size_t base = (size_t)(off + gr) * NF + gcol;
                            float2 o2;
                            o2.x = v0 + bias[e * NF + gcol];
                            o2.y = v1 + bias[e * NF + gcol + 1];
                            *(float2*)(Of + base) = o2;
                        }
                    } else if (OP == 4) {
                        if (gr < cnt) {
                            int t = g_perm[off + gr];
                            size_t bx = (size_t)t * ND + gcol;
                            float2 o2;
                            o2.x = 2.f * extra[bx] + rs * (v0 + bias[e * ND + gcol]);
                            o2.y = 2.f * extra[bx + 1] + rs * (v1 + bias[e * ND + gcol + 1]);
                            *(float2*)(Of + bx) = o2;
                        }
                    }
                }
            }
}

// ---------------- mma.sync flash attention (fp16) -----------------------------
// Q 2-term, K single, V single, P 2-term.
__global__ void __launch_bounds__(128, 4) k_flash()
{
    extern __shared__ __align__(16) char fsm[];
    const int tid = threadIdx.x, lane = tid & 31, warpm = tid >> 5;
    const int bh = blockIdx.y, b = bh >> 4, h = bh & 15;
    const int row0 = blockIdx.x * 64;

    const __half* Qg = g_qkv;
    const __half* Kg = g_qkv + (size_t)NT * ND;
    const __half* Vg = g_qkv + (size_t)2 * NT * ND;

    // Q tile: scale + split into hi/lo
    {
        int m = tid >> 1, half = tid & 1;
        float sc = g_scalef[bh * NS + row0 + m];
        const __half* src_ = Qg + (size_t)(b * NS + row0 + m) * ND + h * 64 + half * 32;
        char* dh = fsm + F_QH + m * 144 + half * 64;
        char* dl = fsm + F_QL + m * 144 + half * 64;
#pragma unroll
        for (int i = 0; i < 4; i++) {
            __half qb[8], oh[8], ol[8];
            *(uint4*)qb = *(const uint4*)(src_ + i * 8);
#pragma unroll
            for (int j = 0; j < 8; j++) {
                float f = __half2float(qb[j]) * sc;
                split2h(f, oh[j], ol[j]);
            }
            *(uint4*)(dh + i * 16) = *(uint4*)oh;
            *(uint4*)(dl + i * 16) = *(uint4*)ol;
        }
    }

    const uint32_t ubase = s2u(fsm);
    const uint32_t uQh = ubase + F_QH, uQl = ubase + F_QL;
    const uint32_t uK = ubase + F_K, uV = ubase + F_V;

    const uint32_t qa_off = ((warpm * 16 + (lane & 15)) * F_STRIDE + ((lane >> 4) & 1) * 8) * 2;
    const uint32_t ka_off = (((lane & 7) + ((lane >> 4) << 3)) * F_STRIDE + ((lane >> 3) & 1) * 8) * 2;
    const uint32_t va_off = (((lane & 7) + ((lane >> 3) & 1) * 8) * F_STRIDE + ((lane >> 4) & 1) * 8) * 2;

    float oacc[8][4];
#pragma unroll
    for (int t = 0; t < 8; t++)
#pragma unroll
        for (int i = 0; i < 4; i++) oacc[t][i] = 0.f;
    float mi0 = -1e30f, mi1 = -1e30f, li0 = 0.f, li1 = 0.f;

    for (int jt = 0; jt < NS / 64; jt++) {
        __syncthreads();
        {
            int m = tid >> 1, half = tid & 1;
            size_t gsrc = (size_t)(b * NS + jt * 64 + m) * ND + h * 64 + half * 32;
            char* dk = fsm + F_K + m * 144 + half * 64;
            char* dv = fsm + F_V + m * 144 + half * 64;
#pragma unroll
            for (int i = 0; i < 4; i++) {
                *(uint4*)(dk + i * 16) = *(const uint4*)((const char*)(Kg + gsrc) + i * 16);
                *(uint4*)(dv + i * 16) = *(const uint4*)((const char*)(Vg + gsrc) + i * 16);
            }
        }
        __syncthreads();

        float sacc[8][4];
#pragma unroll
        for (int t = 0; t < 8; t++)
#pragma unroll
            for (int i = 0; i < 4; i++) sacc[t][i] = 0.f;
#pragma unroll
        for (int ks = 0; ks < 4; ks++) {
            unsigned qh4[4], ql4[4];
            ldm_x4(qh4, uQh + qa_off + ks * 32);
            ldm_x4(ql4, uQl + qa_off + ks * 32);
#pragma unroll
            for (int np = 0; np < 4; np++) {
                unsigned k4[4];
                uint32_t o = ka_off + (uint32_t)(np * 16 * F_STRIDE + ks * 16) * 2;
                ldm_x4(k4, uK + o);
                mma16816(sacc[2 * np],     qh4, k4);
                mma16816(sacc[2 * np],     ql4, k4);
                mma16816(sacc[2 * np + 1], qh4, k4 + 2);
                mma16816(sacc[2 * np + 1], ql4, k4 + 2);
            }
        }

        float rm0 = -1e30f, rm1 = -1e30f;
#pragma unroll
        for (int j = 0; j < 8; j++) {
            rm0 = fmaxf(rm0, fmaxf(sacc[j][0], sacc[j][1]));
            rm1 = fmaxf(rm1, fmaxf(sacc[j][2], sacc[j][3]));
        }
        rm0 = fmaxf(rm0, __shfl_xor_sync(0xffffffffu, rm0, 1));
        rm0 = fmaxf(rm0, __shfl_xor_sync(0xffffffffu, rm0, 2));
        rm1 = fmaxf(rm1, __shfl_xor_sync(0xffffffffu, rm1, 1));
        rm1 = fmaxf(rm1, __shfl_xor_sync(0xffffffffu, rm1, 2));
        float mn0 = fmaxf(mi0, rm0), mn1 = fmaxf(mi1, rm1);
        float al0 = expf(mi0 - mn0), al1 = expf(mi1 - mn1);
        float rs0 = 0.f, rs1 = 0.f;
#pragma unroll
        for (int j = 0; j < 8; j++) {
            sacc[j][0] = expf(sacc[j][0] - mn0); rs0 += sacc[j][0];
            sacc[j][1] = expf(sacc[j][1] - mn0); rs0 += sacc[j][1];
            sacc[j][2] = expf(sacc[j][2] - mn1); rs1 += sacc[j][2];
            sacc[j][3] = expf(sacc[j][3] - mn1); rs1 += sacc[j][3];
        }
        rs0 += __shfl_xor_sync(0xffffffffu, rs0, 1);
        rs0 += __shfl_xor_sync(0xffffffffu, rs0, 2);
        rs1 += __shfl_xor_sync(0xffffffffu, rs1, 1);
        rs1 += __shfl_xor_sync(0xffffffffu, rs1, 2);
        li0 = li0 * al0 + rs0; li1 = li1 * al1 + rs1;
        mi0 = mn0; mi1 = mn1;
#pragma unroll
        for (int t = 0; t < 8; t++) {
            oacc[t][0] *= al0; oacc[t][1] *= al0;
            oacc[t][2] *= al1; oacc[t][3] *= al1;
        }

#pragma unroll
        for (int kb = 0; kb < 4; kb++) {
            unsigned pah[4], pal[4];
            sp2h(sacc[2 * kb][0],     sacc[2 * kb][1],     pah[0], pal[0]);
            sp2h(sacc[2 * kb][2],     sacc[2 * kb][3],     pah[1], pal[1]);
            sp2h(sacc[2 * kb + 1][0], sacc[2 * kb + 1][1], pah[2], pal[2]);
            sp2h(sacc[2 * kb + 1][2], sacc[2 * kb + 1][3], pah[3], pal[3]);
#pragma unroll
            for (int ndp = 0; ndp < 4; ndp++) {
                unsigned v4[4];
                uint32_t o = va_off + (uint32_t)(kb * 16 * F_STRIDE + ndp * 16) * 2;
                ldm_x4_t(v4, uV + o);
                mma16816(oacc[2 * ndp],     pah, v4);
                mma16816(oacc[2 * ndp],     pal, v4);
                mma16816(oacc[2 * ndp + 1], pah, v4 + 2);
                mma16816(oacc[2 * ndp + 1], pal, v4 + 2);
            }
        }
    }

    float inv0 = 1.f / li0, inv1 = 1.f / li1;
    int r = row0 + warpm * 16 + (lane >> 2);
    int cbase = h * 64 + (lane & 3) * 2;
#pragma unroll
    for (int dt = 0; dt < 8; dt++) {
        unsigned ph, pl;
        sp2h(oacc[dt][0] * inv0, oacc[dt][1] * inv0, ph, pl);
        size_t idx = (size_t)(b * NS + r) * ND + cbase + dt * 8;
        *(unsigned*)(g_ah + idx) = ph;
        *(unsigned*)(g_al + idx) = pl;
        sp2h(oacc[dt][2] * inv1, oacc[dt][3] * inv1, ph, pl);
        idx += (size_t)8 * ND;
        *(unsigned*)(g_ah + idx) = ph;
        *(unsigned*)(g_al + idx) = pl;
    }
}

// ---------------- reductions --------------------------------------------------
__device__ __forceinline__ void blk_reduce2(float& s, float& q)
{
    __shared__ float ss[8], sq[8];
#pragma unroll
    for (int o = 16; o; o >>= 1) {
        s += __shfl_xor_sync(0xffffffffu, s, o);
        q += __shfl_xor_sync(0xffffffffu, q, o);
    }
    int w = threadIdx.x >> 5, l = threadIdx.x & 31;
    if (l == 0) { ss[w] = s; sq[w] = q; }
    __syncthreads();
    s = (l < 8) ? ss[l] : 0.f;
    q = (l < 8) ? sq[l] : 0.f;
#pragma unroll
    for (int o = 4; o; o >>= 1) {
        s += __shfl_xor_sync(0xffffffffu, s, o);
        q += __shfl_xor_sync(0xffffffffu, q, o);
    }
    s = __shfl_sync(0xffffffffu, s, 0);
    q = __shfl_sync(0xffffffffu, q, 0);
}

// ---------------- elementwise -------------------------------------------------
__global__ __launch_bounds__(256) void k_cvt(const float* __restrict__ in,
                                             __half* __restrict__ oh,
                                             __half* __restrict__ ol)
{
    size_t i = ((size_t)blockIdx.x * 256 + threadIdx.x) * 8;
    float4 a = *(const float4*)(in + i);
    float4 b = *(const float4*)(in + i + 4);
    unsigned h[4], l[4];
    sp2h(a.x, a.y, h[0], l[0]);
    sp2h(a.z, a.w, h[1], l[1]);
    sp2h(b.x, b.y, h[2], l[2]);
    sp2h(b.z, b.w, h[3], l[3]);
    *(uint4*)(oh + i) = *(uint4*)h;
    *(uint4*)(ol + i) = *(uint4*)l;
}

__global__ __launch_bounds__(256) void k_cvtw(const float* __restrict__ in,
                                              __half* __restrict__ o)
{
    size_t i = ((size_t)blockIdx.x * 256 + threadIdx.x) * 8;
    float4 a = *(const float4*)(in + i);
    float4 b = *(const float4*)(in + i + 4);
    unsigned h[4];
    h[0] = pkh(a.x, a.y); h[1] = pkh(a.z, a.w);
    h[2] = pkh(b.x, b.y); h[3] = pkh(b.z, b.w);
    *(uint4*)(o + i) = *(uint4*)h;
}

__global__ __launch_bounds__(256) void k_qscale(const float* __restrict__ sw)
{
    int wid = blockIdx.x * 8 + (threadIdx.x >> 5);
    int lane = threadIdx.x & 31;
    int h = wid & (NH - 1), t = wid >> 4;
    size_t i0 = (size_t)t * ND + h * 64 + lane;
    float q0 = __half2float(g_qkv[i0]);
    float q1 = __half2float(g_qkv[i0 + 32]);
    float s = q0 * sw[h * 64 + lane] + q1 * sw[h * 64 + lane + 32];
#pragma unroll
    for (int o = 16; o; o >>= 1) s += __shfl_xor_sync(0xffffffffu, s, o);
    if (lane == 0) {
        float sig = 1.f / (1.f + expf(-s));
        int b = t >> 10, si = t & (NS - 1);
        g_scalef[(b * NH + h) * NS + si] = 0.25f * sig;
    }
}

__global__ __launch_bounds__(256) void k_ln1(const float* __restrict__ g,
                                             const float* __restrict__ b)
{
    size_t r = blockIdx.x;
    const float* in = g_xres + r * ND;
    float x[4];
    float s = 0.f, q = 0.f;
#pragma unroll
    for (int l = 0; l < 4; l++) {
        x[l] = in[threadIdx.x + l * 256];
        s += x[l]; q += x[l] * x[l];
    }
    blk_reduce2(s, q);
    float mean = s * (1.f / ND);
    float var = q * (1.f / ND) - mean * mean;
    float rstd = rsqrtf(var + 1e-5f);
#pragma unroll
    for (int l = 0; l < 4; l++) {
        int c = threadIdx.x + l * 256;
        float v = (x[l] - mean) * rstd * g[c] + b[c];
        g_x[r * ND + c] = v;
        __half h, lo;
        split2h(v, h, lo);
        g_xh[r * ND + c] = h; g_xl[r * ND + c] = lo;
    }
}

__global__ __launch_bounds__(256) void k_ln_out(const float* __restrict__ g,
                                                const float* __restrict__ b,
                                                float* __restrict__ out)
{
    size_t r = blockIdx.x;
    const float* in = g_z + r * ND;
    float x[4];
    float s = 0.f, q = 0.f;
#pragma unroll
    for (int l = 0; l < 4; l++) {
        x[l] = in[threadIdx.x + l * 256];
        s += x[l]; q += x[l] * x[l];
    }
    blk_reduce2(s, q);
    float mean = s * (1.f / ND);
    float var = q * (1.f / ND) - mean * mean;
    float rstd = rsqrtf(var + 1e-5f);
#pragma unroll
    for (int l = 0; l < 4; l++) {
        int c = threadIdx.x + l * 256;
        out[r * ND + c] = (x[l] - mean) * rstd * g[c] + b[c];
    }
}

__global__ __launch_bounds__(256) void k_route(const float* __restrict__ gw,
                                               const float* __restrict__ gb)
{
    __shared__ float lg[NE];
    int t = blockIdx.x;
    int w = threadIdx.x >> 5, lane = threadIdx.x & 31;
    const float* x = g_x + (size_t)t * ND;
    float s = 0.f;
    for (int d = lane; d < ND; d += 32) s += x[d] * gw[d * NE + w];
#pragma unroll
    for (int o = 16; o; o >>= 1) s += __shfl_xor_sync(0xffffffffu, s, o);
    if (lane == 0) lg[w] = s + gb[w];
    __syncthreads();
    if (threadIdx.x == 0) {
        int i1 = 0; float v1 = lg[0];
#pragma unroll
        for (int e = 1; e < NE; e++) if (lg[e] > v1) { v1 = lg[e]; i1 = e; }
        int i2 = -1; float v2 = -1e30f;
#pragma unroll
        for (int e = 0; e < NE; e++) if (e != i1 && lg[e] > v2) { v2 = lg[e]; i2 = e; }
        g_esel[t] = (i1 > i2) ? i1 : i2;
    }
}

__global__ void k_scatter()
{
    __shared__ int scnt[NE], soff[NE], scur[NE];
    int tid = threadIdx.x;
    if (tid < NE) scnt[tid] = 0;
    __syncthreads();
    for (int t = tid; t < NT; t += 1024) atomicAdd(&scnt[g_esel[t]], 1);
    __syncthreads();
    if (tid == 0) {
        int r = 0;
        for (int e = 0; e < NE; e++) { soff[e] = r; r += scnt[e]; }
    }
    __syncthreads();
    if (tid < NE) { scur[tid] = soff[tid]; g_off[tid] = soff[tid]; g_cnt[tid] = scnt[tid]; }
    __syncthreads();
    for (int t = tid; t < NT; t += 1024) {
        int e = g_esel[t];
        int pos = atomicAdd(&scur[e], 1);
        g_perm[pos] = t;
        g_eid[pos] = e;
    }
}

__global__ __launch_bounds__(256) void k_lngelu(const float* __restrict__ lng,
                                                const float* __restrict__ lnb)
{
    int row = blockIdx.x;
    int e = g_eid[row];
    const float* hp = g_h + (size_t)row * NF;
    float x[16];
    float s = 0.f, q = 0.f;
#pragma unroll
    for (int l = 0; l < 16; l++) {
        x[l] = hp[threadIdx.x + l * 256];
        s += x[l]; q += x[l] * x[l];
    }
    blk_reduce2(s, q);
    float mean = s * (1.f / NF);
    float var = q * (1.f / NF) - mean * mean;
    float rstd = rsqrtf(var + 1e-5f);
    const float* g = lng + (size_t)e * NF;
    const float* b = lnb + (size_t)e * NF;
#pragma unroll
    for (int l = 0; l < 16; l++) {
        int c = threadIdx.x + l * 256;
        float hn = (x[l] - mean) * rstd * g[c] + b[c];
        float gel = 0.5f * hn * (1.f + erff(hn * 0.70710678118654752f));
        __half hh, ll;
        split2h(gel, hh, ll);
        g_hh[(size_t)row * NF + c] = hh;
        g_hl[(size_t)row * NF + c] = ll;
    }
}

// ---------------- launch ------------------------------------------------------
extern "C" void kernel_launch(void* const* d_in, const int* in_sizes, int n_in,
                              void* d_out, int out_size)
{
    (void)in_sizes; (void)n_in; (void)out_size;
    const float* src        = (const float*)d_in[0];
    const float* qw         = (const float*)d_in[1];
    const float* kw         = (const float*)d_in[2];
    const float* vw         = (const float*)d_in[3];
    const float* ow         = (const float*)d_in[4];
    const float* gate_w     = (const float*)d_in[5];
    const float* gate_b     = (const float*)d_in[6];
    const float* scale_w    = (const float*)d_in[7];
    const float* n1_g       = (const float*)d_in[8];
    const float* n1_b       = (const float*)d_in[9];
    const float* n2_g       = (const float*)d_in[10];
    const float* n2_b       = (const float*)d_in[11];
    const float* moe_gate_w = (const float*)d_in[12];
    const float* moe_gate_b = (const float*)d_in[13];
    const float* w1         = (const float*)d_in[14];
    const float* b1         = (const float*)d_in[15];
    const float* ln_g       = (const float*)d_in[16];
    const float* ln_b       = (const float*)d_in[17];
    const float* w2         = (const float*)d_in[18];
    const float* b2         = (const float*)d_in[19];
    const float* res_scale  = (const float*)d_in[20];
    float* out = (float*)d_out;

    cudaFuncSetAttribute((const void*)k_mm<0, 0>, cudaFuncAttributeMaxDynamicSharedMemorySize, GEMM_SMEM);
    cudaFuncSetAttribute((const void*)k_mm<1, 0>, cudaFuncAttributeMaxDynamicSharedMemorySize, GEMM_SMEM);
    cudaFuncSetAttribute((const void*)k_mm<2, 0>, cudaFuncAttributeMaxDynamicSharedMemorySize, GEMM_SMEM);
    cudaFuncSetAttribute((const void*)k_mm<3, 1>, cudaFuncAttributeMaxDynamicSharedMemorySize, GEMM_SMEM2);
    cudaFuncSetAttribute((const void*)k_mm<4, 1>, cudaFuncAttributeMaxDynamicSharedMemorySize, GEMM_SMEM2);
    cudaFuncSetAttribute((const void*)k_flash, cudaFuncAttributeMaxDynamicSharedMemorySize, FLASH_SMEM);

    __half *sh, *sl, *qkv, *ah, *al, *gh, *gl, *xh, *xl, *hh, *hl;
    __half *wqkv, *wg, *wo;
    float *xres, *x, *z, *hbuf;
    cudaGetSymbolAddress((void**)&sh, g_sh);     cudaGetSymbolAddress((void**)&sl, g_sl);
    cudaGetSymbolAddress((void**)&qkv, g_qkv);
    cudaGetSymbolAddress((void**)&ah, g_ah);     cudaGetSymbolAddress((void**)&al, g_al);
    cudaGetSymbolAddress((void**)&gh, g_gh);     cudaGetSymbolAddress((void**)&gl, g_gl);
    cudaGetSymbolAddress((void**)&xh, g_xh);     cudaGetSymbolAddress((void**)&xl, g_xl);
    cudaGetSymbolAddress((void**)&hh, g_hh);     cudaGetSymbolAddress((void**)&hl, g_hl);
    cudaGetSymbolAddress((void**)&wqkv, g_wqkv);
    cudaGetSymbolAddress((void**)&wg, g_wg);     cudaGetSymbolAddress((void**)&wo, g_wo);
    cudaGetSymbolAddress((void**)&xres, g_xres);
    cudaGetSymbolAddress((void**)&x, g_x);
    cudaGetSymbolAddress((void**)&z, g_z);
    cudaGetSymbolAddress((void**)&hbuf, g_h);

    k_cvt<<<NT * ND / 2048, 256>>>(src, sh, sl);
    k_cvtw<<<ND * ND / 2048, 256>>>(qw, wqkv);
    k_cvtw<<<ND * ND / 2048, 256>>>(kw, wqkv + ND * ND);
    k_cvtw<<<ND * ND / 2048, 256>>>(vw, wqkv + 2 * ND * ND);
    k_cvtw<<<ND * ND / 2048, 256>>>(gate_w, wg);
    k_cvtw<<<ND * ND / 2048, 256>>>(ow, wo);

    k_mm<0, 0><<<dim3(ND / TN, NT / TM, 3), 256, GEMM_SMEM>>>(sh, sl, wqkv, nullptr,
        ND, ND, nullptr, nullptr, nullptr, qkv, nullptr, nullptr);
    k_qscale<<<(NT * NH) / 8, 256>>>(scale_w);
    k_flash<<<dim3(NS / 64, NB * NH), 128, FLASH_SMEM>>>();
    k_mm<1, 0><<<dim3(ND / TN, NT / TM), 256, GEMM_SMEM>>>(ah, al, wg, nullptr,
        ND, ND, gate_b, nullptr, nullptr, gh, gl, nullptr);
    k_mm<2, 0><<<dim3(ND / TN, NT / TM), 256, GEMM_SMEM>>>(gh, gl, wo, nullptr,
        ND, ND, nullptr, src, nullptr, nullptr, nullptr, xres);
    k_ln1<<<NT, 256>>>(n1_g, n1_b);
    k_route<<<NT, 256>>>(moe_gate_w, moe_gate_b);
    k_scatter<<<1, 1024>>>();
    k_mm<3, 1><<<dim3(NF / TN, NT / TM, NE), 256, GEMM_SMEM2>>>(xh, xl, nullptr, w1,
        ND, NF, b1, nullptr, nullptr, nullptr, nullptr, hbuf);
    k_lngelu<<<NT, 256>>>(ln_g, ln_b);
    k_mm<4, 1><<<dim3(ND / TN, NT / TM, NE), 256, GEMM_SMEM2>>>(hh, hl, nullptr, w2,
        NF, ND, b2, x, res_scale, nullptr, nullptr, z);
    k_ln_out<<<NT, 256>>>(n2_g, n2_b, out);
}

// round 8
// speedup vs baseline: 3.9331x; 1.3438x over previous
#include <cuda_runtime.h>
#include <cuda_fp16.h>
#include <math.h>
#include <stdint.h>

#define NB 2
#define NS 1024
#define ND 1024
#define NH 16
#define NE 8
#define NF 4096
#define NT 2048

#define TM 128
#define TN 128
#define KC 32
#define A_STRIDE 40    // fp16 elems per A smem row (80B)
#define B_STRIDE 136   // fp16 elems per B smem row (272B)

// fp16-B variant (pre-converted B): 4-stage
#define ST_A 0
#define ST_B 10240
#define STAGE_BYTES 18944
#define NST1 4
#define GEMM_SMEM (NST1 * STAGE_BYTES)

// fp32-B variant (in-kernel convert): 3-stage
#define S2_A 0
#define S2_B32 10240
#define S2_STAGE 26624
#define NST2 3
#define S2_B (NST2 * S2_STAGE)
#define GEMM_SMEM2 (S2_B + 8704)

#define F_STRIDE 72    // flash smem row stride (144B)
#define F_Q 0
#define F_K 9216
#define F_V 18432
#define FLASH_SMEM 27648

// ---------------- scratch ----------------------------------------------------
__device__ __half g_s16[NT * ND];
__device__ __half g_qkv[3 * NT * ND];
__device__ __half g_a16[NT * ND];
__device__ __half g_g16[NT * ND];
__device__ __half g_x16[NT * ND];
__device__ __half g_h16[(size_t)NT * NF];
__device__ __half g_wqkv[3 * ND * ND];
__device__ __half g_wg[ND * ND];
__device__ __half g_wo[ND * ND];
__device__ float g_scalef[NB * NH * NS];
__device__ float g_xres[NT * ND];
__device__ float g_x[NT * ND];
__device__ float g_z[NT * ND];
__device__ float g_h[(size_t)NT * NF];
__device__ int g_esel[NT];
__device__ int g_perm[NT];
__device__ int g_eid[NT];
__device__ int g_off[NE];
__device__ int g_cnt[NE];

// ---------------- helpers ----------------------------------------------------
__device__ __forceinline__ uint32_t s2u(const void* p) {
    uint32_t a;
    asm("{ .reg .u64 t; cvta.to.shared.u64 t, %1; cvt.u32.u64 %0, t; }" : "=r"(a) : "l"(p));
    return a;
}
__device__ __forceinline__ unsigned pkh(float a, float b) {
    __half2 hh = __floats2half2_rn(a, b);
    return *reinterpret_cast<unsigned*>(&hh);
}
__device__ __forceinline__ void ldm_x4(unsigned* r, uint32_t addr) {
    asm volatile("ldmatrix.sync.aligned.m8n8.x4.shared.b16 {%0,%1,%2,%3}, [%4];"
        : "=r"(r[0]), "=r"(r[1]), "=r"(r[2]), "=r"(r[3]) : "r"(addr));
}
__device__ __forceinline__ void ldm_x4_t(unsigned* r, uint32_t addr) {
    asm volatile("ldmatrix.sync.aligned.m8n8.x4.trans.shared.b16 {%0,%1,%2,%3}, [%4];"
        : "=r"(r[0]), "=r"(r[1]), "=r"(r[2]), "=r"(r[3]) : "r"(addr));
}
__device__ __forceinline__ void mma16816(float* c, const unsigned* a, const unsigned* b) {
    asm volatile(
        "mma.sync.aligned.m16n8k16.row.col.f32.f16.f16.f32 "
        "{%0,%1,%2,%3}, {%4,%5,%6,%7}, {%8,%9}, {%0,%1,%2,%3};"
        : "+f"(c[0]), "+f"(c[1]), "+f"(c[2]), "+f"(c[3])
        : "r"(a[0]), "r"(a[1]), "r"(a[2]), "r"(a[3]), "r"(b[0]), "r"(b[1]));
}
__device__ __forceinline__ void cpa(uint32_t d, const void* s, int szvalid) {
    asm volatile("cp.async.cg.shared.global [%0], [%1], 16, %2;"
        :: "r"(d), "l"(__cvta_generic_to_global(s)), "r"(szvalid));
}

// ---------------- pipelined mma.sync fp16 GEMM --------------------------------
// C[128,128] = A[M,K] @ B[K,N]; A fp16, B fp16 (BF32=0, 4-stage) or fp32
// converted in-kernel (BF32=1, 3-stage).
// OP: 0 merged QKV | 1 gate | 2 ow (+src) | 3 ffn1 gather +b1 | 4 ffn2
template <int OP, int BF32>
__global__ void __launch_bounds__(256, 2) k_mm(
    const __half* __restrict__ Ah,
    const __half* __restrict__ B16, const float* __restrict__ B32,
    int K, int ldB,
    const float* __restrict__ bias, const float* __restrict__ extra,
    const float* __restrict__ extra2,
    __half* __restrict__ Oh, float* __restrict__ Of)
{
    extern __shared__ __align__(16) char sm[];
    __shared__ int rloc[TM];
    constexpr int NST = BF32 ? NST2 : NST1;
    constexpr int stageBytes = BF32 ? S2_STAGE : STAGE_BYTES;

    const int tid = threadIdx.x;
    const int lane = tid & 31, wid = tid >> 5;
    const int warp_m = wid >> 2, warp_n = wid & 3;
    const int row0 = blockIdx.y * TM, col0 = blockIdx.x * TN;
    const int e = blockIdx.z;
    int cnt = 0, off = 0;
    if (OP == 0) {
        B16 += (size_t)e * ND * ND;
        Oh += (size_t)e * NT * ND;
    }
    if (OP == 3 || OP == 4) {
        cnt = g_cnt[e]; off = g_off[e];
        if (row0 >= cnt) return;
        B32 += (size_t)e * K * ldB;
    }
    if (OP == 3) {
        if (tid < TM) {
            int gr = row0 + tid;
            rloc[tid] = (gr < cnt) ? g_perm[off + gr] : -1;
        }
        __syncthreads();
    }

    const int am = tid >> 1, ahalf = tid & 1;
    int arow;
    if (OP == 3) arow = rloc[am];
    else if (OP == 4) arow = min(off + row0 + am, NT - 1);
    else arow = row0 + am;
    const int apred = (arow >= 0) ? 16 : 0;
    const int arows = (arow >= 0) ? arow : 0;
    const char* gA = (const char*)(Ah + (size_t)arows * K + ahalf * 16);
    const int bk = tid >> 3, bseg = tid & 7;
    const char* gB16 = nullptr;
    const char* gB32 = nullptr;
    if (BF32) gB32 = (const char*)(B32 + (size_t)bk * ldB + col0 + bseg * 16);
    else gB16 = (const char*)(B16 + (size_t)bk * ldB + col0 + bseg * 16);

    const uint32_t ub = s2u(sm);
    const uint32_t aDst = ub + ST_A + am * 80 + ahalf * 32;
    const uint32_t bDst = BF32 ? (ub + S2_B32 + bk * 512 + bseg * 64)
                               : (ub + ST_B + bk * 272 + bseg * 32);

    auto issue = [&](int stage, int c) {
        uint32_t sb = stage * stageBytes;
        size_t ao = (size_t)c * KC * 2;
        cpa(aDst + sb,      gA + ao,      apred);
        cpa(aDst + sb + 16, gA + ao + 16, apred);
        if (BF32) {
            size_t bo = (size_t)c * KC * ldB * 4;
#pragma unroll
            for (int i = 0; i < 4; i++)
                cpa(bDst + sb + i * 16, gB32 + bo + i * 16, 16);
        } else {
            size_t bo = (size_t)c * KC * ldB * 2;
            cpa(bDst + sb,      gB16 + bo,      16);
            cpa(bDst + sb + 16, gB16 + bo + 16, 16);
        }
        asm volatile("cp.async.commit_group;");
    };

    float acc[16][4];
#pragma unroll
    for (int t = 0; t < 16; t++)
#pragma unroll
        for (int i = 0; i < 4; i++) acc[t][i] = 0.f;

    const int nch = K / KC;
#pragma unroll
    for (int s = 0; s < NST; s++) issue(s, s);

    for (int c = 0; c < nch; c++) {
        asm volatile("cp.async.wait_group %0;" :: "n"(NST - 1));
        __syncthreads();
        uint32_t sb = ub + (c % NST) * stageBytes;
        uint32_t uA_ = sb + ST_A;
        uint32_t uB_;
        if (BF32) {
            const float* bsrc = (const float*)(sm + (c % NST) * S2_STAGE + S2_B32) + bk * 128 + bseg * 16;
            unsigned hh8[8];
#pragma unroll
            for (int j = 0; j < 8; j++) hh8[j] = pkh(bsrc[2 * j], bsrc[2 * j + 1]);
            char* db = sm + S2_B + bk * 272 + bseg * 32;
            *(uint4*)db = *(uint4*)hh8; *(uint4*)(db + 16) = *(uint4*)(hh8 + 4);
            __syncthreads();
            uB_ = ub + S2_B;
        } else {
            uB_ = sb + ST_B;
        }
#pragma unroll
        for (int ks = 0; ks < 2; ks++) {
            unsigned b_[2][4];
#pragma unroll
            for (int nt = 0; nt < 2; nt++) {
                int krow = ks * 16 + (lane & 7) + ((lane >> 3) & 1) * 8;
                int ncol = warp_n * 32 + nt * 16 + (lane >> 4) * 8;
                uint32_t o = (uint32_t)(krow * B_STRIDE + ncol) * 2;
                ldm_x4_t(b_[nt], uB_ + o);
            }
#pragma unroll
            for (int mt = 0; mt < 4; mt++) {
                unsigned a_[4];
                int mrow = warp_m * 64 + mt * 16 + (lane & 15);
                int kcol = ks * 16 + (lane >> 4) * 8;
                uint32_t o = (uint32_t)(mrow * A_STRIDE + kcol) * 2;
                ldm_x4(a_, uA_ + o);
#pragma unroll
                for (int nt = 0; nt < 2; nt++)
#pragma unroll
                    for (int j = 0; j < 2; j++)
                        mma16816(acc[mt * 4 + nt * 2 + j], a_, b_[nt] + j * 2);
            }
        }
        __syncthreads();
        if (c + NST < nch) issue(c % NST, c + NST);
        else asm volatile("cp.async.commit_group;");
    }

    // ---- epilogue ----
    float rs = 0.f;
    if (OP == 4) rs = extra2[e];
#pragma unroll
    for (int mt = 0; mt < 4; mt++)
#pragma unroll
        for (int nt = 0; nt < 2; nt++)
#pragma unroll
            for (int j = 0; j < 2; j++) {
                float* cc = acc[mt * 4 + nt * 2 + j];
                int lcol = warp_n * 32 + nt * 16 + j * 8 + (lane & 3) * 2;
                int gcol = col0 + lcol;
#pragma unroll
                for (int half = 0; half < 2; half++) {
                    int lrow = warp_m * 64 + mt * 16 + (lane >> 2) + half * 8;
                    int gr = row0 + lrow;
                    float v0 = cc[half * 2], v1 = cc[half * 2 + 1];
                    if (OP == 0) {
                        size_t base = (size_t)gr * ND + gcol;
                        *(unsigned*)(Oh + base) = pkh(v0, v1);
                    } else if (OP == 1) {
                        size_t base = (size_t)gr * ND + gcol;
                        float g0 = 1.f / (1.f + expf(-(v0 + bias[gcol])));
                        float g1 = 1.f / (1.f + expf(-(v1 + bias[gcol + 1])));
                        float a0 = __half2float(Ah[base]);
                        float a1 = __half2float(Ah[base + 1]);
                        *(unsigned*)(Oh + base) = pkh(a0 * g0, a1 * g1);
                    } else if (OP == 2) {
                        size_t base = (size_t)gr * ND + gcol;
                        float2 o2;
                        o2.x = extra[base] + v0;
                        o2.y = extra[base + 1] + v1;
                        *(float2*)(Of + base) = o2;
                    } else if (OP == 3) {
                        if (gr < cnt) {
                            size_t base = (size_t)(off + gr) * NF + gcol;
                            float2 o2;
                            o2.x = v0 + bias[e * NF + gcol];
                            o2.y = v1 + bias[e * NF + gcol + 1];
                            *(float2*)(Of + base) = o2;
                        }
                    } else if (OP == 4) {
                        if (gr < cnt) {
                            int t = g_perm[off + gr];
                            size_t bx = (size_t)t * ND + gcol;
                            float2 o2;
                            o2.x = 2.f * extra[bx] + rs * (v0 + bias[e * ND + gcol]);
                            o2.y = 2.f * extra[bx + 1] + rs * (v1 + bias[e * ND + gcol + 1]);
                            *(float2*)(Of + bx) = o2;
                        }
                    }
                }
            }
}

// ---------------- mma.sync flash attention (fp16 single) ----------------------
__global__ void __launch_bounds__(128, 4) k_flash()
{
    extern __shared__ __align__(16) char fsm[];
    const int tid = threadIdx.x, lane = tid & 31, warpm = tid >> 5;
    const int bh = blockIdx.y, b = bh >> 4, h = bh & 15;
    const int row0 = blockIdx.x * 64;

    const __half* Qg = g_qkv;
    const __half* Kg = g_qkv + (size_t)NT * ND;
    const __half* Vg = g_qkv + (size_t)2 * NT * ND;

    // Q tile: apply scale, store fp16
    {
        int m = tid >> 1, half = tid & 1;
        float sc = g_scalef[bh * NS + row0 + m];
        const __half* src_ = Qg + (size_t)(b * NS + row0 + m) * ND + h * 64 + half * 32;
        char* dq = fsm + F_Q + m * 144 + half * 64;
#pragma unroll
        for (int i = 0; i < 4; i++) {
            __half qb[8];
            *(uint4*)qb = *(const uint4*)(src_ + i * 8);
            unsigned o4[4];
#pragma unroll
            for (int j = 0; j < 4; j++)
                o4[j] = pkh(__half2float(qb[2 * j]) * sc, __half2float(qb[2 * j + 1]) * sc);
            *(uint4*)(dq + i * 16) = *(uint4*)o4;
        }
    }

    const uint32_t ubase = s2u(fsm);
    const uint32_t uQ = ubase + F_Q, uK = ubase + F_K, uV = ubase + F_V;

    const uint32_t qa_off = ((warpm * 16 + (lane & 15)) * F_STRIDE + ((lane >> 4) & 1) * 8) * 2;
    const uint32_t ka_off = (((lane & 7) + ((lane >> 4) << 3)) * F_STRIDE + ((lane >> 3) & 1) * 8) * 2;
    const uint32_t va_off = (((lane & 7) + ((lane >> 3) & 1) * 8) * F_STRIDE + ((lane >> 4) & 1) * 8) * 2;

    float oacc[8][4];
#pragma unroll
    for (int t = 0; t < 8; t++)
#pragma unroll
        for (int i = 0; i < 4; i++) oacc[t][i] = 0.f;
    float mi0 = -1e30f, mi1 = -1e30f, li0 = 0.f, li1 = 0.f;

    for (int jt = 0; jt < NS / 64; jt++) {
        __syncthreads();
        {
            int m = tid >> 1, half = tid & 1;
            size_t gsrc = (size_t)(b * NS + jt * 64 + m) * ND + h * 64 + half * 32;
            char* dk = fsm + F_K + m * 144 + half * 64;
            char* dv = fsm + F_V + m * 144 + half * 64;
#pragma unroll
            for (int i = 0; i < 4; i++) {
                *(uint4*)(dk + i * 16) = *(const uint4*)((const char*)(Kg + gsrc) + i * 16);
                *(uint4*)(dv + i * 16) = *(const uint4*)((const char*)(Vg + gsrc) + i * 16);
            }
        }
        __syncthreads();

        float sacc[8][4];
#pragma unroll
        for (int t = 0; t < 8; t++)
#pragma unroll
            for (int i = 0; i < 4; i++) sacc[t][i] = 0.f;
#pragma unroll
        for (int ks = 0; ks < 4; ks++) {
            unsigned q4[4];
            ldm_x4(q4, uQ + qa_off + ks * 32);
#pragma unroll
            for (int np = 0; np < 4; np++) {
                unsigned k4[4];
                uint32_t o = ka_off + (uint32_t)(np * 16 * F_STRIDE + ks * 16) * 2;
                ldm_x4(k4, uK + o);
                mma16816(sacc[2 * np],     q4, k4);
                mma16816(sacc[2 * np + 1], q4, k4 + 2);
            }
        }

        float rm0 = -1e30f, rm1 = -1e30f;
#pragma unroll
        for (int j = 0; j < 8; j++) {
            rm0 = fmaxf(rm0, fmaxf(sacc[j][0], sacc[j][1]));
            rm1 = fmaxf(rm1, fmaxf(sacc[j][2], sacc[j][3]));
        }
        rm0 = fmaxf(rm0, __shfl_xor_sync(0xffffffffu, rm0, 1));
        rm0 = fmaxf(rm0, __shfl_xor_sync(0xffffffffu, rm0, 2));
        rm1 = fmaxf(rm1, __shfl_xor_sync(0xffffffffu, rm1, 1));
        rm1 = fmaxf(rm1, __shfl_xor_sync(0xffffffffu, rm1, 2));
        float mn0 = fmaxf(mi0, rm0), mn1 = fmaxf(mi1, rm1);
        float al0 = expf(mi0 - mn0), al1 = expf(mi1 - mn1);
        float rs0 = 0.f, rs1 = 0.f;
#pragma unroll
        for (int j = 0; j < 8; j++) {
            sacc[j][0] = expf(sacc[j][0] - mn0); rs0 += sacc[j][0];
            sacc[j][1] = expf(sacc[j][1] - mn0); rs0 += sacc[j][1];
            sacc[j][2] = expf(sacc[j][2] - mn1); rs1 += sacc[j][2];
            sacc[j][3] = expf(sacc[j][3] - mn1); rs1 += sacc[j][3];
        }
        rs0 += __shfl_xor_sync(0xffffffffu, rs0, 1);
        rs0 += __shfl_xor_sync(0xffffffffu, rs0, 2);
        rs1 += __shfl_xor_sync(0xffffffffu, rs1, 1);
        rs1 += __shfl_xor_sync(0xffffffffu, rs1, 2);
        li0 = li0 * al0 + rs0; li1 = li1 * al1 + rs1;
        mi0 = mn0; mi1 = mn1;
#pragma unroll
        for (int t = 0; t < 8; t++) {
            oacc[t][0] *= al0; oacc[t][1] *= al0;
            oacc[t][2] *= al1; oacc[t][3] *= al1;
        }

#pragma unroll
        for (int kb = 0; kb < 4; kb++) {
            unsigned pa[4];
            pa[0] = pkh(sacc[2 * kb][0],     sacc[2 * kb][1]);
            pa[1] = pkh(sacc[2 * kb][2],     sacc[2 * kb][3]);
            pa[2] = pkh(sacc[2 * kb + 1][0], sacc[2 * kb + 1][1]);
            pa[3] = pkh(sacc[2 * kb + 1][2], sacc[2 * kb + 1][3]);
#pragma unroll
            for (int ndp = 0; ndp < 4; ndp++) {
                unsigned v4[4];
                uint32_t o = va_off + (uint32_t)(kb * 16 * F_STRIDE + ndp * 16) * 2;
                ldm_x4_t(v4, uV + o);
                mma16816(oacc[2 * ndp],     pa, v4);
                mma16816(oacc[2 * ndp + 1], pa, v4 + 2);
            }
        }
    }

    float inv0 = 1.f / li0, inv1 = 1.f / li1;
    int r = row0 + warpm * 16 + (lane >> 2);
    int cbase = h * 64 + (lane & 3) * 2;
#pragma unroll
    for (int dt = 0; dt < 8; dt++) {
        size_t idx = (size_t)(b * NS + r) * ND + cbase + dt * 8;
        *(unsigned*)(g_a16 + idx) = pkh(oacc[dt][0] * inv0, oacc[dt][1] * inv0);
        idx += (size_t)8 * ND;
        *(unsigned*)(g_a16 + idx) = pkh(oacc[dt][2] * inv1, oacc[dt][3] * inv1);
    }
}

// ---------------- reductions --------------------------------------------------
__device__ __forceinline__ void blk_reduce2(float& s, float& q)
{
    __shared__ float ss[8], sq[8];
#pragma unroll
    for (int o = 16; o; o >>= 1) {
        s += __shfl_xor_sync(0xffffffffu, s, o);
        q += __shfl_xor_sync(0xffffffffu, q, o);
    }
    int w = threadIdx.x >> 5, l = threadIdx.x & 31;
    if (l == 0) { ss[w] = s; sq[w] = q; }
    __syncthreads();
    s = (l < 8) ? ss[l] : 0.f;
    q = (l < 8) ? sq[l] : 0.f;
#pragma unroll
    for (int o = 4; o; o >>= 1) {
        s += __shfl_xor_sync(0xffffffffu, s, o);
        q += __shfl_xor_sync(0xffffffffu, q, o);
    }
    s = __shfl_sync(0xffffffffu, s, 0);
    q = __shfl_sync(0xffffffffu, q, 0);
}

// ---------------- elementwise -------------------------------------------------
__global__ __launch_bounds__(256) void k_cvtw(const float* __restrict__ in,
                                              __half* __restrict__ o)
{
    size_t i = ((size_t)blockIdx.x * 256 + threadIdx.x) * 8;
    float4 a = *(const float4*)(in + i);
    float4 b = *(const float4*)(in + i + 4);
    unsigned h[4];
    h[0] = pkh(a.x, a.y); h[1] = pkh(a.z, a.w);
    h[2] = pkh(b.x, b.y); h[3] = pkh(b.z, b.w);
    *(uint4*)(o + i) = *(uint4*)h;
}

__global__ __launch_bounds__(256) void k_qscale(const float* __restrict__ sw)
{
    int wid = blockIdx.x * 8 + (threadIdx.x >> 5);
    int lane = threadIdx.x & 31;
    int h = wid & (NH - 1), t = wid >> 4;
    size_t i0 = (size_t)t * ND + h * 64 + lane;
    float q0 = __half2float(g_qkv[i0]);
    float q1 = __half2float(g_qkv[i0 + 32]);
    float s = q0 * sw[h * 64 + lane] + q1 * sw[h * 64 + lane + 32];
#pragma unroll
    for (int o = 16; o; o >>= 1) s += __shfl_xor_sync(0xffffffffu, s, o);
    if (lane == 0) {
        float sig = 1.f / (1.f + expf(-s));
        int b = t >> 10, si = t & (NS - 1);
        g_scalef[(b * NH + h) * NS + si] = 0.25f * sig;
    }
}

__global__ __launch_bounds__(256) void k_ln1(const float* __restrict__ g,
                                             const float* __restrict__ b)
{
    size_t r = blockIdx.x;
    const float* in = g_xres + r * ND;
    float x[4];
    float s = 0.f, q = 0.f;
#pragma unroll
    for (int l = 0; l < 4; l++) {
        x[l] = in[threadIdx.x + l * 256];
        s += x[l]; q += x[l] * x[l];
    }
    blk_reduce2(s, q);
    float mean = s * (1.f / ND);
    float var = q * (1.f / ND) - mean * mean;
    float rstd = rsqrtf(var + 1e-5f);
#pragma unroll
    for (int l = 0; l < 4; l++) {
        int c = threadIdx.x + l * 256;
        float v = (x[l] - mean) * rstd * g[c] + b[c];
        g_x[r * ND + c] = v;
        g_x16[r * ND + c] = __float2half_rn(v);
    }
}

__global__ __launch_bounds__(256) void k_ln_out(const float* __restrict__ g,
                                                const float* __restrict__ b,
                                                float* __restrict__ out)
{
    size_t r = blockIdx.x;
    const float* in = g_z + r * ND;
    float x[4];
    float s = 0.f, q = 0.f;
#pragma unroll
    for (int l = 0; l < 4; l++) {
        x[l] = in[threadIdx.x + l * 256];
        s += x[l]; q += x[l] * x[l];
    }
    blk_reduce2(s, q);
    float mean = s * (1.f / ND);
    float var = q * (1.f / ND) - mean * mean;
    float rstd = rsqrtf(var + 1e-5f);
#pragma unroll
    for (int l = 0; l < 4; l++) {
        int c = threadIdx.x + l * 256;
        out[r * ND + c] = (x[l] - mean) * rstd * g[c] + b[c];
    }
}

__global__ __launch_bounds__(256) void k_route(const float* __restrict__ gw,
                                               const float* __restrict__ gb)
{
    __shared__ float lg[NE];
    int t = blockIdx.x;
    int w = threadIdx.x >> 5, lane = threadIdx.x & 31;
    const float* x = g_x + (size_t)t * ND;
    float s = 0.f;
    for (int d = lane; d < ND; d += 32) s += x[d] * gw[d * NE + w];
#pragma unroll
    for (int o = 16; o; o >>= 1) s += __shfl_xor_sync(0xffffffffu, s, o);
    if (lane == 0) lg[w] = s + gb[w];
    __syncthreads();
    if (threadIdx.x == 0) {
        int i1 = 0; float v1 = lg[0];
#pragma unroll
        for (int e = 1; e < NE; e++) if (lg[e] > v1) { v1 = lg[e]; i1 = e; }
        int i2 = -1; float v2 = -1e30f;
#pragma unroll
        for (int e = 0; e < NE; e++) if (e != i1 && lg[e] > v2) { v2 = lg[e]; i2 = e; }
        g_esel[t] = (i1 > i2) ? i1 : i2;
    }
}

__global__ void k_scatter()
{
    __shared__ int scnt[NE], soff[NE], scur[NE];
    int tid = threadIdx.x;
    if (tid < NE) scnt[tid] = 0;
    __syncthreads();
    for (int t = tid; t < NT; t += 1024) atomicAdd(&scnt[g_esel[t]], 1);
    __syncthreads();
    if (tid == 0) {
        int r = 0;
        for (int e = 0; e < NE; e++) { soff[e] = r; r += scnt[e]; }
    }
    __syncthreads();
    if (tid < NE) { scur[tid] = soff[tid]; g_off[tid] = soff[tid]; g_cnt[tid] = scnt[tid]; }
    __syncthreads();
    for (int t = tid; t < NT; t += 1024) {
        int e = g_esel[t];
        int pos = atomicAdd(&scur[e], 1);
        g_perm[pos] = t;
        g_eid[pos] = e;
    }
}

__global__ __launch_bounds__(256) void k_lngelu(const float* __restrict__ lng,
                                                const float* __restrict__ lnb)
{
    int row = blockIdx.x;
    int e = g_eid[row];
    const float* hp = g_h + (size_t)row * NF;
    float x[16];
    float s = 0.f, q = 0.f;
#pragma unroll
    for (int l = 0; l < 16; l++) {
        x[l] = hp[threadIdx.x + l * 256];
        s += x[l]; q += x[l] * x[l];
    }
    blk_reduce2(s, q);
    float mean = s * (1.f / NF);
    float var = q * (1.f / NF) - mean * mean;
    float rstd = rsqrtf(var + 1e-5f);
    const float* g = lng + (size_t)e * NF;
    const float* b = lnb + (size_t)e * NF;
#pragma unroll
    for (int l = 0; l < 16; l++) {
        int c = threadIdx.x + l * 256;
        float hn = (x[l] - mean) * rstd * g[c] + b[c];
        float gel = 0.5f * hn * (1.f + erff(hn * 0.70710678118654752f));
        g_h16[(size_t)row * NF + c] = __float2half_rn(gel);
    }
}

// ---------------- launch ------------------------------------------------------
extern "C" void kernel_launch(void* const* d_in, const int* in_sizes, int n_in,
                              void* d_out, int out_size)
{
    (void)in_sizes; (void)n_in; (void)out_size;
    const float* src        = (const float*)d_in[0];
    const float* qw         = (const float*)d_in[1];
    const float* kw         = (const float*)d_in[2];
    const float* vw         = (const float*)d_in[3];
    const float* ow         = (const float*)d_in[4];
    const float* gate_w     = (const float*)d_in[5];
    const float* gate_b     = (const float*)d_in[6];
    const float* scale_w    = (const float*)d_in[7];
    const float* n1_g       = (const float*)d_in[8];
    const float* n1_b       = (const float*)d_in[9];
    const float* n2_g       = (const float*)d_in[10];
    const float* n2_b       = (const float*)d_in[11];
    const float* moe_gate_w = (const float*)d_in[12];
    const float* moe_gate_b = (const float*)d_in[13];
    const float* w1         = (const float*)d_in[14];
    const float* b1         = (const float*)d_in[15];
    const float* ln_g       = (const float*)d_in[16];
    const float* ln_b       = (const float*)d_in[17];
    const float* w2         = (const float*)d_in[18];
    const float* b2         = (const float*)d_in[19];
    const float* res_scale  = (const float*)d_in[20];
    float* out = (float*)d_out;

    cudaFuncSetAttribute((const void*)k_mm<0, 0>, cudaFuncAttributeMaxDynamicSharedMemorySize, GEMM_SMEM);
    cudaFuncSetAttribute((const void*)k_mm<1, 0>, cudaFuncAttributeMaxDynamicSharedMemorySize, GEMM_SMEM);
    cudaFuncSetAttribute((const void*)k_mm<2, 0>, cudaFuncAttributeMaxDynamicSharedMemorySize, GEMM_SMEM);
    cudaFuncSetAttribute((const void*)k_mm<3, 1>, cudaFuncAttributeMaxDynamicSharedMemorySize, GEMM_SMEM2);
    cudaFuncSetAttribute((const void*)k_mm<4, 1>, cudaFuncAttributeMaxDynamicSharedMemorySize, GEMM_SMEM2);
    cudaFuncSetAttribute((const void*)k_flash, cudaFuncAttributeMaxDynamicSharedMemorySize, FLASH_SMEM);

    __half *s16, *qkv, *a16, *g16, *x16, *h16, *wqkv, *wg, *wo;
    float *xres, *x, *z, *hbuf;
    cudaGetSymbolAddress((void**)&s16, g_s16);
    cudaGetSymbolAddress((void**)&qkv, g_qkv);
    cudaGetSymbolAddress((void**)&a16, g_a16);
    cudaGetSymbolAddress((void**)&g16, g_g16);
    cudaGetSymbolAddress((void**)&x16, g_x16);
    cudaGetSymbolAddress((void**)&h16, g_h16);
    cudaGetSymbolAddress((void**)&wqkv, g_wqkv);
    cudaGetSymbolAddress((void**)&wg, g_wg);
    cudaGetSymbolAddress((void**)&wo, g_wo);
    cudaGetSymbolAddress((void**)&xres, g_xres);
    cudaGetSymbolAddress((void**)&x, g_x);
    cudaGetSymbolAddress((void**)&z, g_z);
    cudaGetSymbolAddress((void**)&hbuf, g_h);

    k_cvtw<<<NT * ND / 2048, 256>>>(src, s16);
    k_cvtw<<<ND * ND / 2048, 256>>>(qw, wqkv);
    k_cvtw<<<ND * ND / 2048, 256>>>(kw, wqkv + ND * ND);
    k_cvtw<<<ND * ND / 2048, 256>>>(vw, wqkv + 2 * ND * ND);
    k_cvtw<<<ND * ND / 2048, 256>>>(gate_w, wg);
    k_cvtw<<<ND * ND / 2048, 256>>>(ow, wo);

    k_mm<0, 0><<<dim3(ND / TN, NT / TM, 3), 256, GEMM_SMEM>>>(s16, wqkv, nullptr,
        ND, ND, nullptr, nullptr, nullptr, qkv, nullptr);
    k_qscale<<<(NT * NH) / 8, 256>>>(scale_w);
    k_flash<<<dim3(NS / 64, NB * NH), 128, FLASH_SMEM>>>();
    k_mm<1, 0><<<dim3(ND / TN, NT / TM), 256, GEMM_SMEM>>>(a16, wg, nullptr,
        ND, ND, gate_b, nullptr, nullptr, g16, nullptr);
    k_mm<2, 0><<<dim3(ND / TN, NT / TM), 256, GEMM_SMEM>>>(g16, wo, nullptr,
        ND, ND, nullptr, src, nullptr, nullptr, xres);
    k_ln1<<<NT, 256>>>(n1_g, n1_b);
    k_route<<<NT, 256>>>(moe_gate_w, moe_gate_b);
    k_scatter<<<1, 1024>>>();
    k_mm<3, 1><<<dim3(NF / TN, NT / TM, NE), 256, GEMM_SMEM2>>>(x16, nullptr, w1,
        ND, NF, b1, nullptr, nullptr, nullptr, hbuf);
    k_lngelu<<<NT, 256>>>(ln_g, ln_b);
    k_mm<4, 1><<<dim3(ND / TN, NT / TM, NE), 256, GEMM_SMEM2>>>(h16, nullptr, w2,
        NF, ND, b2, x, res_scale, nullptr, z);
    k_ln_out<<<NT, 256>>>(n2_g, n2_b, out);
}

// round 9
// speedup vs baseline: 4.8254x; 1.2268x over previous
#include <cuda_runtime.h>
#include <cuda_fp16.h>
#include <math.h>
#include <stdint.h>

#define NB 2
#define NS 1024
#define ND 1024
#define NH 16
#define NE 8
#define NF 4096
#define NT 2048

#define TM 128
#define TN 128
#define KC 32
#define A_STRIDE 40    // fp16 elems per A smem row (80B)
#define B_STRIDE 136   // fp16 elems per B smem row (272B)

// 4-stage fp16 pipeline
#define ST_A 0
#define ST_B 10240
#define STAGE_BYTES 18944
#define NST1 4
#define GEMM_SMEM (NST1 * STAGE_BYTES)

#define F_STRIDE 72    // flash smem row stride (144B)
#define F_Q 0
#define F_K 9216
#define F_V 18432
#define FLASH_SMEM 27648

// ---------------- scratch ----------------------------------------------------
__device__ __half g_s16[NT * ND];
__device__ __half g_qkv[3 * NT * ND];
__device__ __half g_a16[NT * ND];
__device__ __half g_g16[NT * ND];
__device__ __half g_x16[NT * ND];
__device__ __half g_h16[(size_t)NT * NF];
__device__ __half g_wqkv[3 * ND * ND];
__device__ __half g_wg[ND * ND];
__device__ __half g_wo[ND * ND];
__device__ __half g_w116[(size_t)NE * ND * NF];
__device__ __half g_w216[(size_t)NE * NF * ND];
__device__ float g_scalef[NB * NH * NS];
__device__ float g_xres[NT * ND];
__device__ float g_x[NT * ND];
__device__ float g_z[NT * ND];
__device__ float g_h[(size_t)NT * NF];
__device__ int g_esel[NT];
__device__ int g_perm[NT];
__device__ int g_eid[NT];
__device__ int g_off[NE];
__device__ int g_cnt[NE];

// ---------------- helpers ----------------------------------------------------
__device__ __forceinline__ uint32_t s2u(const void* p) {
    uint32_t a;
    asm("{ .reg .u64 t; cvta.to.shared.u64 t, %1; cvt.u32.u64 %0, t; }" : "=r"(a) : "l"(p));
    return a;
}
__device__ __forceinline__ unsigned pkh(float a, float b) {
    __half2 hh = __floats2half2_rn(a, b);
    return *reinterpret_cast<unsigned*>(&hh);
}
__device__ __forceinline__ void ldm_x4(unsigned* r, uint32_t addr) {
    asm volatile("ldmatrix.sync.aligned.m8n8.x4.shared.b16 {%0,%1,%2,%3}, [%4];"
        : "=r"(r[0]), "=r"(r[1]), "=r"(r[2]), "=r"(r[3]) : "r"(addr));
}
__device__ __forceinline__ void ldm_x4_t(unsigned* r, uint32_t addr) {
    asm volatile("ldmatrix.sync.aligned.m8n8.x4.trans.shared.b16 {%0,%1,%2,%3}, [%4];"
        : "=r"(r[0]), "=r"(r[1]), "=r"(r[2]), "=r"(r[3]) : "r"(addr));
}
__device__ __forceinline__ void mma16816(float* c, const unsigned* a, const unsigned* b) {
    asm volatile(
        "mma.sync.aligned.m16n8k16.row.col.f32.f16.f16.f32 "
        "{%0,%1,%2,%3}, {%4,%5,%6,%7}, {%8,%9}, {%0,%1,%2,%3};"
        : "+f"(c[0]), "+f"(c[1]), "+f"(c[2]), "+f"(c[3])
        : "r"(a[0]), "r"(a[1]), "r"(a[2]), "r"(a[3]), "r"(b[0]), "r"(b[1]));
}
__device__ __forceinline__ void cpa(uint32_t d, const void* s, int szvalid) {
    asm volatile("cp.async.cg.shared.global [%0], [%1], 16, %2;"
        :: "r"(d), "l"(__cvta_generic_to_global(s)), "r"(szvalid));
}

__device__ __forceinline__ void cvt8(const float* __restrict__ in, __half* __restrict__ o,
                                     size_t i)
{
    float4 a = *(const float4*)(in + i);
    float4 b = *(const float4*)(in + i + 4);
    unsigned h[4];
    h[0] = pkh(a.x, a.y); h[1] = pkh(a.z, a.w);
    h[2] = pkh(b.x, b.y); h[3] = pkh(b.z, b.w);
    *(uint4*)(o + i) = *(uint4*)h;
}

// ---------------- pipelined mma.sync fp16 GEMM (4-stage) ----------------------
// C[128,128] = A[M,K] @ B[K,N]; A fp16, B fp16.
// OP: 0 merged QKV | 1 gate | 2 ow (+src) | 3 ffn1 gather +b1 | 4 ffn2
template <int OP>
__global__ void __launch_bounds__(256, 2) k_mm(
    const __half* __restrict__ Ah, const __half* __restrict__ B16,
    int K, int ldB,
    const float* __restrict__ bias, const float* __restrict__ extra,
    const float* __restrict__ extra2,
    __half* __restrict__ Oh, float* __restrict__ Of)
{
    extern __shared__ __align__(16) char sm[];
    __shared__ int rloc[TM];

    const int tid = threadIdx.x;
    const int lane = tid & 31, wid = tid >> 5;
    const int warp_m = wid >> 2, warp_n = wid & 3;
    const int row0 = blockIdx.y * TM, col0 = blockIdx.x * TN;
    const int e = blockIdx.z;
    int cnt = 0, off = 0;
    if (OP == 0) {
        B16 += (size_t)e * ND * ND;
        Oh += (size_t)e * NT * ND;
    }
    if (OP == 3 || OP == 4) {
        cnt = g_cnt[e]; off = g_off[e];
        if (row0 >= cnt) return;
        B16 += (size_t)e * K * ldB;
    }
    if (OP == 3) {
        if (tid < TM) {
            int gr = row0 + tid;
            rloc[tid] = (gr < cnt) ? g_perm[off + gr] : -1;
        }
        __syncthreads();
    }

    const int am = tid >> 1, ahalf = tid & 1;
    int arow;
    if (OP == 3) arow = rloc[am];
    else if (OP == 4) arow = min(off + row0 + am, NT - 1);
    else arow = row0 + am;
    const int apred = (arow >= 0) ? 16 : 0;
    const int arows = (arow >= 0) ? arow : 0;
    const char* gA = (const char*)(Ah + (size_t)arows * K + ahalf * 16);
    const int bk = tid >> 3, bseg = tid & 7;
    const char* gB16 = (const char*)(B16 + (size_t)bk * ldB + col0 + bseg * 16);

    const uint32_t ub = s2u(sm);
    const uint32_t aDst = ub + ST_A + am * 80 + ahalf * 32;
    const uint32_t bDst = ub + ST_B + bk * 272 + bseg * 32;

    auto issue = [&](int stage, int c) {
        uint32_t sb = stage * STAGE_BYTES;
        size_t ao = (size_t)c * KC * 2;
        size_t bo = (size_t)c * KC * ldB * 2;
        cpa(aDst + sb,      gA + ao,      apred);
        cpa(aDst + sb + 16, gA + ao + 16, apred);
        cpa(bDst + sb,      gB16 + bo,      16);
        cpa(bDst + sb + 16, gB16 + bo + 16, 16);
        asm volatile("cp.async.commit_group;");
    };

    float acc[16][4];
#pragma unroll
    for (int t = 0; t < 16; t++)
#pragma unroll
        for (int i = 0; i < 4; i++) acc[t][i] = 0.f;

    const int nch = K / KC;
#pragma unroll
    for (int s = 0; s < NST1; s++) issue(s, s);

    for (int c = 0; c < nch; c++) {
        asm volatile("cp.async.wait_group %0;" :: "n"(NST1 - 1));
        __syncthreads();
        uint32_t sb = ub + (c % NST1) * STAGE_BYTES;
        uint32_t uA_ = sb + ST_A;
        uint32_t uB_ = sb + ST_B;
#pragma unroll
        for (int ks = 0; ks < 2; ks++) {
            unsigned b_[2][4];
#pragma unroll
            for (int nt = 0; nt < 2; nt++) {
                int krow = ks * 16 + (lane & 7) + ((lane >> 3) & 1) * 8;
                int ncol = warp_n * 32 + nt * 16 + (lane >> 4) * 8;
                uint32_t o = (uint32_t)(krow * B_STRIDE + ncol) * 2;
                ldm_x4_t(b_[nt], uB_ + o);
            }
#pragma unroll
            for (int mt = 0; mt < 4; mt++) {
                unsigned a_[4];
                int mrow = warp_m * 64 + mt * 16 + (lane & 15);
                int kcol = ks * 16 + (lane >> 4) * 8;
                uint32_t o = (uint32_t)(mrow * A_STRIDE + kcol) * 2;
                ldm_x4(a_, uA_ + o);
#pragma unroll
                for (int nt = 0; nt < 2; nt++)
#pragma unroll
                    for (int j = 0; j < 2; j++)
                        mma16816(acc[mt * 4 + nt * 2 + j], a_, b_[nt] + j * 2);
            }
        }
        __syncthreads();
        if (c + NST1 < nch) issue(c % NST1, c + NST1);
        else asm volatile("cp.async.commit_group;");
    }

    // ---- epilogue ----
    float rs = 0.f;
    if (OP == 4) rs = extra2[e];
#pragma unroll
    for (int mt = 0; mt < 4; mt++)
#pragma unroll
        for (int nt = 0; nt < 2; nt++)
#pragma unroll
            for (int j = 0; j < 2; j++) {
                float* cc = acc[mt * 4 + nt * 2 + j];
                int lcol = warp_n * 32 + nt * 16 + j * 8 + (lane & 3) * 2;
                int gcol = col0 + lcol;
#pragma unroll
                for (int half = 0; half < 2; half++) {
                    int lrow = warp_m * 64 + mt * 16 + (lane >> 2) + half * 8;
                    int gr = row0 + lrow;
                    float v0 = cc[half * 2], v1 = cc[half * 2 + 1];
                    if (OP == 0) {
                        size_t base = (size_t)gr * ND + gcol;
                        *(unsigned*)(Oh + base) = pkh(v0, v1);
                    } else if (OP == 1) {
                        size_t base = (size_t)gr * ND + gcol;
                        float g0 = 1.f / (1.f + expf(-(v0 + bias[gcol])));
                        float g1 = 1.f / (1.f + expf(-(v1 + bias[gcol + 1])));
                        float a0 = __half2float(Ah[base]);
                        float a1 = __half2float(Ah[base + 1]);
                        *(unsigned*)(Oh + base) = pkh(a0 * g0, a1 * g1);
                    } else if (OP == 2) {
                        size_t base = (size_t)gr * ND + gcol;
                        float2 o2;
                        o2.x = extra[base] + v0;
                        o2.y = extra[base + 1] + v1;
                        *(float2*)(Of + base) = o2;
                    } else if (OP == 3) {
                        if (gr < cnt) {
                            size_t base = (size_t)(off + gr) * NF + gcol;
                            float2 o2;
                            o2.x = v0 + bias[e * NF + gcol];
                            o2.y = v1 + bias[e * NF + gcol + 1];
                            *(float2*)(Of + base) = o2;
                        }
                    } else if (OP == 4) {
                        if (gr < cnt) {
                            int t = g_perm[off + gr];
                            size_t bx = (size_t)t * ND + gcol;
                            float2 o2;
                            o2.x = 2.f * extra[bx] + rs * (v0 + bias[e * ND + gcol]);
                            o2.y = 2.f * extra[bx + 1] + rs * (v1 + bias[e * ND + gcol + 1]);
                            *(float2*)(Of + bx) = o2;
                        }
                    }
                }
            }
}

// ---------------- mma.sync flash attention (fp16 single) ----------------------
__global__ void __launch_bounds__(128, 4) k_flash()
{
    extern __shared__ __align__(16) char fsm[];
    const int tid = threadIdx.x, lane = tid & 31, warpm = tid >> 5;
    const int bh = blockIdx.y, b = bh >> 4, h = bh & 15;
    const int row0 = blockIdx.x * 64;

    const __half* Qg = g_qkv;
    const __half* Kg = g_qkv + (size_t)NT * ND;
    const __half* Vg = g_qkv + (size_t)2 * NT * ND;

    {
        int m = tid >> 1, half = tid & 1;
        float sc = g_scalef[bh * NS + row0 + m];
        const __half* src_ = Qg + (size_t)(b * NS + row0 + m) * ND + h * 64 + half * 32;
        char* dq = fsm + F_Q + m * 144 + half * 64;
#pragma unroll
        for (int i = 0; i < 4; i++) {
            __half qb[8];
            *(uint4*)qb = *(const uint4*)(src_ + i * 8);
            unsigned o4[4];
#pragma unroll
            for (int j = 0; j < 4; j++)
                o4[j] = pkh(__half2float(qb[2 * j]) * sc, __half2float(qb[2 * j + 1]) * sc);
            *(uint4*)(dq + i * 16) = *(uint4*)o4;
        }
    }

    const uint32_t ubase = s2u(fsm);
    const uint32_t uQ = ubase + F_Q, uK = ubase + F_K, uV = ubase + F_V;

    const uint32_t qa_off = ((warpm * 16 + (lane & 15)) * F_STRIDE + ((lane >> 4) & 1) * 8) * 2;
    const uint32_t ka_off = (((lane & 7) + ((lane >> 4) << 3)) * F_STRIDE + ((lane >> 3) & 1) * 8) * 2;
    const uint32_t va_off = (((lane & 7) + ((lane >> 3) & 1) * 8) * F_STRIDE + ((lane >> 4) & 1) * 8) * 2;

    float oacc[8][4];
#pragma unroll
    for (int t = 0; t < 8; t++)
#pragma unroll
        for (int i = 0; i < 4; i++) oacc[t][i] = 0.f;
    float mi0 = -1e30f, mi1 = -1e30f, li0 = 0.f, li1 = 0.f;

    for (int jt = 0; jt < NS / 64; jt++) {
        __syncthreads();
        {
            int m = tid >> 1, half = tid & 1;
            size_t gsrc = (size_t)(b * NS + jt * 64 + m) * ND + h * 64 + half * 32;
            char* dk = fsm + F_K + m * 144 + half * 64;
            char* dv = fsm + F_V + m * 144 + half * 64;
#pragma unroll
            for (int i = 0; i < 4; i++) {
                *(uint4*)(dk + i * 16) = *(const uint4*)((const char*)(Kg + gsrc) + i * 16);
                *(uint4*)(dv + i * 16) = *(const uint4*)((const char*)(Vg + gsrc) + i * 16);
            }
        }
        __syncthreads();

        float sacc[8][4];
#pragma unroll
        for (int t = 0; t < 8; t++)
#pragma unroll
            for (int i = 0; i < 4; i++) sacc[t][i] = 0.f;
#pragma unroll
        for (int ks = 0; ks < 4; ks++) {
            unsigned q4[4];
            ldm_x4(q4, uQ + qa_off + ks * 32);
#pragma unroll
            for (int np = 0; np < 4; np++) {
                unsigned k4[4];
                uint32_t o = ka_off + (uint32_t)(np * 16 * F_STRIDE + ks * 16) * 2;
                ldm_x4(k4, uK + o);
                mma16816(sacc[2 * np],     q4, k4);
                mma16816(sacc[2 * np + 1], q4, k4 + 2);
            }
        }

        float rm0 = -1e30f, rm1 = -1e30f;
#pragma unroll
        for (int j = 0; j < 8; j++) {
            rm0 = fmaxf(rm0, fmaxf(sacc[j][0], sacc[j][1]));
            rm1 = fmaxf(rm1, fmaxf(sacc[j][2], sacc[j][3]));
        }
        rm0 = fmaxf(rm0, __shfl_xor_sync(0xffffffffu, rm0, 1));
        rm0 = fmaxf(rm0, __shfl_xor_sync(0xffffffffu, rm0, 2));
        rm1 = fmaxf(rm1, __shfl_xor_sync(0xffffffffu, rm1, 1));
        rm1 = fmaxf(rm1, __shfl_xor_sync(0xffffffffu, rm1, 2));
        float mn0 = fmaxf(mi0, rm0), mn1 = fmaxf(mi1, rm1);
        float al0 = expf(mi0 - mn0), al1 = expf(mi1 - mn1);
        float rs0 = 0.f, rs1 = 0.f;
#pragma unroll
        for (int j = 0; j < 8; j++) {
            sacc[j][0] = expf(sacc[j][0] - mn0); rs0 += sacc[j][0];
            sacc[j][1] = expf(sacc[j][1] - mn0); rs0 += sacc[j][1];
            sacc[j][2] = expf(sacc[j][2] - mn1); rs1 += sacc[j][2];
            sacc[j][3] = expf(sacc[j][3] - mn1); rs1 += sacc[j][3];
        }
        rs0 += __shfl_xor_sync(0xffffffffu, rs0, 1);
        rs0 += __shfl_xor_sync(0xffffffffu, rs0, 2);
        rs1 += __shfl_xor_sync(0xffffffffu, rs1, 1);
        rs1 += __shfl_xor_sync(0xffffffffu, rs1, 2);
        li0 = li0 * al0 + rs0; li1 = li1 * al1 + rs1;
        mi0 = mn0; mi1 = mn1;
#pragma unroll
        for (int t = 0; t < 8; t++) {
            oacc[t][0] *= al0; oacc[t][1] *= al0;
            oacc[t][2] *= al1; oacc[t][3] *= al1;
        }

#pragma unroll
        for (int kb = 0; kb < 4; kb++) {
            unsigned pa[4];
            pa[0] = pkh(sacc[2 * kb][0],     sacc[2 * kb][1]);
            pa[1] = pkh(sacc[2 * kb][2],     sacc[2 * kb][3]);
            pa[2] = pkh(sacc[2 * kb + 1][0], sacc[2 * kb + 1][1]);
            pa[3] = pkh(sacc[2 * kb + 1][2], sacc[2 * kb + 1][3]);
#pragma unroll
            for (int ndp = 0; ndp < 4; ndp++) {
                unsigned v4[4];
                uint32_t o = va_off + (uint32_t)(kb * 16 * F_STRIDE + ndp * 16) * 2;
                ldm_x4_t(v4, uV + o);
                mma16816(oacc[2 * ndp],     pa, v4);
                mma16816(oacc[2 * ndp + 1], pa, v4 + 2);
            }
        }
    }

    float inv0 = 1.f / li0, inv1 = 1.f / li1;
    int r = row0 + warpm * 16 + (lane >> 2);
    int cbase = h * 64 + (lane & 3) * 2;
#pragma unroll
    for (int dt = 0; dt < 8; dt++) {
        size_t idx = (size_t)(b * NS + r) * ND + cbase + dt * 8;
        *(unsigned*)(g_a16 + idx) = pkh(oacc[dt][0] * inv0, oacc[dt][1] * inv0);
        idx += (size_t)8 * ND;
        *(unsigned*)(g_a16 + idx) = pkh(oacc[dt][2] * inv1, oacc[dt][3] * inv1);
    }
}

// ---------------- reductions --------------------------------------------------
__device__ __forceinline__ void blk_reduce2(float& s, float& q)
{
    __shared__ float ss[8], sq[8];
#pragma unroll
    for (int o = 16; o; o >>= 1) {
        s += __shfl_xor_sync(0xffffffffu, s, o);
        q += __shfl_xor_sync(0xffffffffu, q, o);
    }
    int w = threadIdx.x >> 5, l = threadIdx.x & 31;
    if (l == 0) { ss[w] = s; sq[w] = q; }
    __syncthreads();
    s = (l < 8) ? ss[l] : 0.f;
    q = (l < 8) ? sq[l] : 0.f;
#pragma unroll
    for (int o = 4; o; o >>= 1) {
        s += __shfl_xor_sync(0xffffffffu, s, o);
        q += __shfl_xor_sync(0xffffffffu, q, o);
    }
    s = __shfl_sync(0xffffffffu, s, 0);
    q = __shfl_sync(0xffffffffu, q, 0);
}

// ---------------- conversions -------------------------------------------------
// small: src(2M) + qw/kw/vw(3M) + gate_w(1M) + ow(1M) = 7M elems
__global__ __launch_bounds__(256) void k_cvt_small(
    const float* __restrict__ src, const float* __restrict__ qw,
    const float* __restrict__ kw, const float* __restrict__ vw,
    const float* __restrict__ gw, const float* __restrict__ ow)
{
    size_t u = ((size_t)blockIdx.x * 256 + threadIdx.x) * 8;
    const size_t M = (size_t)ND * ND;  // 1M
    if (u < 2 * M) {
        cvt8(src, g_s16, u);
    } else if (u < 5 * M) {
        size_t v = u - 2 * M;
        if (v < M) cvt8(qw, g_wqkv, v);
        else if (v < 2 * M) cvt8(kw, g_wqkv + M, v - M);
        else cvt8(vw, g_wqkv + 2 * M, v - 2 * M);
    } else if (u < 6 * M) {
        cvt8(gw, g_wg, u - 5 * M);
    } else {
        cvt8(ow, g_wo, u - 6 * M);
    }
}

// big: w1 (32M) + w2 (32M), grid-stride
__global__ __launch_bounds__(256) void k_cvt_big(const float* __restrict__ w1,
                                                 const float* __restrict__ w2)
{
    const size_t W = (size_t)NE * ND * NF;  // 32M
    size_t stride = (size_t)gridDim.x * 256 * 8;
    for (size_t u = ((size_t)blockIdx.x * 256 + threadIdx.x) * 8; u < 2 * W; u += stride) {
        if (u < W) cvt8(w1, g_w116, u);
        else cvt8(w2, g_w216, u - W);
    }
}

// ---------------- elementwise -------------------------------------------------
__global__ __launch_bounds__(256) void k_qscale(const float* __restrict__ sw)
{
    int wid = blockIdx.x * 8 + (threadIdx.x >> 5);
    int lane = threadIdx.x & 31;
    int h = wid & (NH - 1), t = wid >> 4;
    size_t i0 = (size_t)t * ND + h * 64 + lane;
    float q0 = __half2float(g_qkv[i0]);
    float q1 = __half2float(g_qkv[i0 + 32]);
    float s = q0 * sw[h * 64 + lane] + q1 * sw[h * 64 + lane + 32];
#pragma unroll
    for (int o = 16; o; o >>= 1) s += __shfl_xor_sync(0xffffffffu, s, o);
    if (lane == 0) {
        float sig = 1.f / (1.f + expf(-s));
        int b = t >> 10, si = t & (NS - 1);
        g_scalef[(b * NH + h) * NS + si] = 0.25f * sig;
    }
}

__global__ __launch_bounds__(256) void k_ln1(const float* __restrict__ g,
                                             const float* __restrict__ b)
{
    size_t r = blockIdx.x;
    const float* in = g_xres + r * ND;
    float x[4];
    float s = 0.f, q = 0.f;
#pragma unroll
    for (int l = 0; l < 4; l++) {
        x[l] = in[threadIdx.x + l * 256];
        s += x[l]; q += x[l] * x[l];
    }
    blk_reduce2(s, q);
    float mean = s * (1.f / ND);
    float var = q * (1.f / ND) - mean * mean;
    float rstd = rsqrtf(var + 1e-5f);
#pragma unroll
    for (int l = 0; l < 4; l++) {
        int c = threadIdx.x + l * 256;
        float v = (x[l] - mean) * rstd * g[c] + b[c];
        g_x[r * ND + c] = v;
        g_x16[r * ND + c] = __float2half_rn(v);
    }
}

__global__ __launch_bounds__(256) void k_ln_out(const float* __restrict__ g,
                                                const float* __restrict__ b,
                                                float* __restrict__ out)
{
    size_t r = blockIdx.x;
    const float* in = g_z + r * ND;
    float x[4];
    float s = 0.f, q = 0.f;
#pragma unroll
    for (int l = 0; l < 4; l++) {
        x[l] = in[threadIdx.x + l * 256];
        s += x[l]; q += x[l] * x[l];
    }
    blk_reduce2(s, q);
    float mean = s * (1.f / ND);
    float var = q * (1.f / ND) - mean * mean;
    float rstd = rsqrtf(var + 1e-5f);
#pragma unroll
    for (int l = 0; l < 4; l++) {
        int c = threadIdx.x + l * 256;
        out[r * ND + c] = (x[l] - mean) * rstd * g[c] + b[c];
    }
}

__global__ __launch_bounds__(256) void k_route(const float* __restrict__ gw,
                                               const float* __restrict__ gb)
{
    __shared__ float lg[NE];
    int t = blockIdx.x;
    int w = threadIdx.x >> 5, lane = threadIdx.x & 31;
    const float* x = g_x + (size_t)t * ND;
    float s = 0.f;
    for (int d = lane; d < ND; d += 32) s += x[d] * gw[d * NE + w];
#pragma unroll
    for (int o = 16; o; o >>= 1) s += __shfl_xor_sync(0xffffffffu, s, o);
    if (lane == 0) lg[w] = s + gb[w];
    __syncthreads();
    if (threadIdx.x == 0) {
        int i1 = 0; float v1 = lg[0];
#pragma unroll
        for (int e = 1; e < NE; e++) if (lg[e] > v1) { v1 = lg[e]; i1 = e; }
        int i2 = -1; float v2 = -1e30f;
#pragma unroll
        for (int e = 0; e < NE; e++) if (e != i1 && lg[e] > v2) { v2 = lg[e]; i2 = e; }
        g_esel[t] = (i1 > i2) ? i1 : i2;
    }
}

__global__ void k_scatter()
{
    __shared__ int scnt[NE], soff[NE], scur[NE];
    int tid = threadIdx.x;
    if (tid < NE) scnt[tid] = 0;
    __syncthreads();
    for (int t = tid; t < NT; t += 1024) atomicAdd(&scnt[g_esel[t]], 1);
    __syncthreads();
    if (tid == 0) {
        int r = 0;
        for (int e = 0; e < NE; e++) { soff[e] = r; r += scnt[e]; }
    }
    __syncthreads();
    if (tid < NE) { scur[tid] = soff[tid]; g_off[tid] = soff[tid]; g_cnt[tid] = scnt[tid]; }
    __syncthreads();
    for (int t = tid; t < NT; t += 1024) {
        int e = g_esel[t];
        int pos = atomicAdd(&scur[e], 1);
        g_perm[pos] = t;
        g_eid[pos] = e;
    }
}

__global__ __launch_bounds__(256) void k_lngelu(const float* __restrict__ lng,
                                                const float* __restrict__ lnb)
{
    int row = blockIdx.x;
    int e = g_eid[row];
    const float* hp = g_h + (size_t)row * NF;
    float x[16];
    float s = 0.f, q = 0.f;
#pragma unroll
    for (int l = 0; l < 16; l++) {
        x[l] = hp[threadIdx.x + l * 256];
        s += x[l]; q += x[l] * x[l];
    }
    blk_reduce2(s, q);
    float mean = s * (1.f / NF);
    float var = q * (1.f / NF) - mean * mean;
    float rstd = rsqrtf(var + 1e-5f);
    const float* g = lng + (size_t)e * NF;
    const float* b = lnb + (size_t)e * NF;
#pragma unroll
    for (int l = 0; l < 16; l++) {
        int c = threadIdx.x + l * 256;
        float hn = (x[l] - mean) * rstd * g[c] + b[c];
        float gel = 0.5f * hn * (1.f + erff(hn * 0.70710678118654752f));
        g_h16[(size_t)row * NF + c] = __float2half_rn(gel);
    }
}

// ---------------- launch ------------------------------------------------------
extern "C" void kernel_launch(void* const* d_in, const int* in_sizes, int n_in,
                              void* d_out, int out_size)
{
    (void)in_sizes; (void)n_in; (void)out_size;
    const float* src        = (const float*)d_in[0];
    const float* qw         = (const float*)d_in[1];
    const float* kw         = (const float*)d_in[2];
    const float* vw         = (const float*)d_in[3];
    const float* ow         = (const float*)d_in[4];
    const float* gate_w     = (const float*)d_in[5];
    const float* gate_b     = (const float*)d_in[6];
    const float* scale_w    = (const float*)d_in[7];
    const float* n1_g       = (const float*)d_in[8];
    const float* n1_b       = (const float*)d_in[9];
    const float* n2_g       = (const float*)d_in[10];
    const float* n2_b       = (const float*)d_in[11];
    const float* moe_gate_w = (const float*)d_in[12];
    const float* moe_gate_b = (const float*)d_in[13];
    const float* w1         = (const float*)d_in[14];
    const float* b1         = (const float*)d_in[15];
    const float* ln_g       = (const float*)d_in[16];
    const float* ln_b       = (const float*)d_in[17];
    const float* w2         = (const float*)d_in[18];
    const float* b2         = (const float*)d_in[19];
    const float* res_scale  = (const float*)d_in[20];
    float* out = (float*)d_out;

    cudaFuncSetAttribute((const void*)k_mm<0>, cudaFuncAttributeMaxDynamicSharedMemorySize, GEMM_SMEM);
    cudaFuncSetAttribute((const void*)k_mm<1>, cudaFuncAttributeMaxDynamicSharedMemorySize, GEMM_SMEM);
    cudaFuncSetAttribute((const void*)k_mm<2>, cudaFuncAttributeMaxDynamicSharedMemorySize, GEMM_SMEM);
    cudaFuncSetAttribute((const void*)k_mm<3>, cudaFuncAttributeMaxDynamicSharedMemorySize, GEMM_SMEM);
    cudaFuncSetAttribute((const void*)k_mm<4>, cudaFuncAttributeMaxDynamicSharedMemorySize, GEMM_SMEM);
    cudaFuncSetAttribute((const void*)k_flash, cudaFuncAttributeMaxDynamicSharedMemorySize, FLASH_SMEM);

    __half *s16, *qkv, *a16, *g16, *x16, *h16, *wqkv, *wg, *wo, *w116, *w216;
    float *xres, *x, *z, *hbuf;
    cudaGetSymbolAddress((void**)&s16, g_s16);
    cudaGetSymbolAddress((void**)&qkv, g_qkv);
    cudaGetSymbolAddress((void**)&a16, g_a16);
    cudaGetSymbolAddress((void**)&g16, g_g16);
    cudaGetSymbolAddress((void**)&x16, g_x16);
    cudaGetSymbolAddress((void**)&h16, g_h16);
    cudaGetSymbolAddress((void**)&wqkv, g_wqkv);
    cudaGetSymbolAddress((void**)&wg, g_wg);
    cudaGetSymbolAddress((void**)&wo, g_wo);
    cudaGetSymbolAddress((void**)&w116, g_w116);
    cudaGetSymbolAddress((void**)&w216, g_w216);
    cudaGetSymbolAddress((void**)&xres, g_xres);
    cudaGetSymbolAddress((void**)&x, g_x);
    cudaGetSymbolAddress((void**)&z, g_z);
    cudaGetSymbolAddress((void**)&hbuf, g_h);

    // launch 0: small conversions (7M elems / 8 per thread / 256 per block)
    k_cvt_small<<<7 * 1024 * 1024 / 2048, 256>>>(src, qw, kw, vw, gate_w, ow);
    // launch 1: big conversions (w1+w2), grid-stride
    k_cvt_big<<<4096, 256>>>(w1, w2);

    k_mm<0><<<dim3(ND / TN, NT / TM, 3), 256, GEMM_SMEM>>>(s16, wqkv,
        ND, ND, nullptr, nullptr, nullptr, qkv, nullptr);
    k_qscale<<<(NT * NH) / 8, 256>>>(scale_w);
    k_flash<<<dim3(NS / 64, NB * NH), 128, FLASH_SMEM>>>();
    k_mm<1><<<dim3(ND / TN, NT / TM), 256, GEMM_SMEM>>>(a16, wg,
        ND, ND, gate_b, nullptr, nullptr, g16, nullptr);
    k_mm<2><<<dim3(ND / TN, NT / TM), 256, GEMM_SMEM>>>(g16, wo,
        ND, ND, nullptr, src, nullptr, nullptr, xres);
    k_ln1<<<NT, 256>>>(n1_g, n1_b);
    k_route<<<NT, 256>>>(moe_gate_w, moe_gate_b);
    k_scatter<<<1, 1024>>>();
    k_mm<3><<<dim3(NF / TN, NT / TM, NE), 256, GEMM_SMEM>>>(x16, w116,
        ND, NF, b1, nullptr, nullptr, nullptr, hbuf);
    k_lngelu<<<NT, 256>>>(ln_g, ln_b);
    k_mm<4><<<dim3(ND / TN, NT / TM, NE), 256, GEMM_SMEM>>>(h16, w216,
        NF, ND, b2, x, res_scale, nullptr, z);
    k_ln_out<<<NT, 256>>>(n2_g, n2_b, out);
}

// round 10
// speedup vs baseline: 5.0610x; 1.0488x over previous
#include <cuda_runtime.h>
#include <cuda_fp16.h>
#include <math.h>
#include <stdint.h>

#define NB 2
#define NS 1024
#define ND 1024
#define NH 16
#define NE 8
#define NF 4096
#define NT 2048

#define TM 128
#define TN 128
#define KC 32
#define A_STRIDE 40    // fp16 elems per A smem row (80B)
#define B_STRIDE 136   // fp16 elems per B smem row (272B)

// 4-stage fp16 pipeline
#define ST_A 0
#define ST_B 10240
#define STAGE_BYTES 18944
#define NST1 4
#define GEMM_SMEM (NST1 * STAGE_BYTES)

#define F_STRIDE 72    // flash smem row stride (144B)
#define F_Q 0
#define F_K 9216
#define F_V 18432
#define FLASH_SMEM 27648

#define WELEMS ((size_t)NE * ND * NF)   // 33.55M elems per ffn weight

// ---------------- scratch ----------------------------------------------------
__device__ __half g_s16[NT * ND];
__device__ __half g_qkv[3 * NT * ND];
__device__ __half g_a16[NT * ND];
__device__ __half g_g16[NT * ND];
__device__ __half g_x16[NT * ND];
__device__ __half g_h16[(size_t)NT * NF];
__device__ __half g_wqkv[3 * ND * ND];
__device__ __half g_wg[ND * ND];
__device__ __half g_wo[ND * ND];
__device__ __half g_w116[WELEMS];
__device__ __half g_w216[WELEMS];
__device__ float g_scalef[NB * NH * NS];
__device__ float g_xres[NT * ND];
__device__ float g_x[NT * ND];
__device__ float g_z[NT * ND];
__device__ float g_h[(size_t)NT * NF];
__device__ int g_esel[NT];
__device__ int g_perm[NT];
__device__ int g_eid[NT];
__device__ int g_off[NE];
__device__ int g_cnt[NE];

// ---------------- helpers ----------------------------------------------------
__device__ __forceinline__ uint32_t s2u(const void* p) {
    uint32_t a;
    asm("{ .reg .u64 t; cvta.to.shared.u64 t, %1; cvt.u32.u64 %0, t; }" : "=r"(a) : "l"(p));
    return a;
}
__device__ __forceinline__ unsigned pkh(float a, float b) {
    __half2 hh = __floats2half2_rn(a, b);
    return *reinterpret_cast<unsigned*>(&hh);
}
__device__ __forceinline__ void ldm_x4(unsigned* r, uint32_t addr) {
    asm volatile("ldmatrix.sync.aligned.m8n8.x4.shared.b16 {%0,%1,%2,%3}, [%4];"
        : "=r"(r[0]), "=r"(r[1]), "=r"(r[2]), "=r"(r[3]) : "r"(addr));
}
__device__ __forceinline__ void ldm_x4_t(unsigned* r, uint32_t addr) {
    asm volatile("ldmatrix.sync.aligned.m8n8.x4.trans.shared.b16 {%0,%1,%2,%3}, [%4];"
        : "=r"(r[0]), "=r"(r[1]), "=r"(r[2]), "=r"(r[3]) : "r"(addr));
}
__device__ __forceinline__ void mma16816(float* c, const unsigned* a, const unsigned* b) {
    asm volatile(
        "mma.sync.aligned.m16n8k16.row.col.f32.f16.f16.f32 "
        "{%0,%1,%2,%3}, {%4,%5,%6,%7}, {%8,%9}, {%0,%1,%2,%3};"
        : "+f"(c[0]), "+f"(c[1]), "+f"(c[2]), "+f"(c[3])
        : "r"(a[0]), "r"(a[1]), "r"(a[2]), "r"(a[3]), "r"(b[0]), "r"(b[1]));
}
__device__ __forceinline__ void cpa(uint32_t d, const void* s, int szvalid) {
    asm volatile("cp.async.cg.shared.global [%0], [%1], 16, %2;"
        :: "r"(d), "l"(__cvta_generic_to_global(s)), "r"(szvalid));
}

__device__ __forceinline__ void cvt8(const float* __restrict__ in, __half* __restrict__ o,
                                     size_t i)
{
    float4 a = *(const float4*)(in + i);
    float4 b = *(const float4*)(in + i + 4);
    unsigned h[4];
    h[0] = pkh(a.x, a.y); h[1] = pkh(a.z, a.w);
    h[2] = pkh(b.x, b.y); h[3] = pkh(b.z, b.w);
    *(uint4*)(o + i) = *(uint4*)h;
}

// ---------------- pipelined mma.sync fp16 GEMM (4-stage) ----------------------
// C[128,128] = A[M,K] @ B[K,N]; A fp16, B fp16.
// OP: 0 merged QKV (z=3 plane converts w1 via `extra`) | 1 gate | 2 ow (+src)
//     3 ffn1 gather +b1 | 4 ffn2
template <int OP>
__global__ void __launch_bounds__(256, 2) k_mm(
    const __half* __restrict__ Ah, const __half* __restrict__ B16,
    int K, int ldB,
    const float* __restrict__ bias, const float* __restrict__ extra,
    const float* __restrict__ extra2,
    __half* __restrict__ Oh, float* __restrict__ Of)
{
    // convert plane for merged QKV launch: stream w1 fp32 -> fp16
    if (OP == 0 && blockIdx.z == 3) {
        size_t base = (((size_t)blockIdx.y * 8 + blockIdx.x) * 256 + threadIdx.x) * 8;
        size_t stride = (size_t)128 * 256 * 8;
        for (size_t u = base; u < WELEMS; u += stride) cvt8(extra, g_w116, u);
        return;
    }

    extern __shared__ __align__(16) char sm[];
    __shared__ int rloc[TM];

    const int tid = threadIdx.x;
    const int lane = tid & 31, wid = tid >> 5;
    const int warp_m = wid >> 2, warp_n = wid & 3;
    const int row0 = blockIdx.y * TM, col0 = blockIdx.x * TN;
    const int e = blockIdx.z;
    int cnt = 0, off = 0;
    if (OP == 0) {
        B16 += (size_t)e * ND * ND;
        Oh += (size_t)e * NT * ND;
    }
    if (OP == 3 || OP == 4) {
        cnt = g_cnt[e]; off = g_off[e];
        if (row0 >= cnt) return;
        B16 += (size_t)e * K * ldB;
    }
    if (OP == 3) {
        if (tid < TM) {
            int gr = row0 + tid;
            rloc[tid] = (gr < cnt) ? g_perm[off + gr] : -1;
        }
        __syncthreads();
    }

    const int am = tid >> 1, ahalf = tid & 1;
    int arow;
    if (OP == 3) arow = rloc[am];
    else if (OP == 4) arow = min(off + row0 + am, NT - 1);
    else arow = row0 + am;
    const int apred = (arow >= 0) ? 16 : 0;
    const int arows = (arow >= 0) ? arow : 0;
    const char* gA = (const char*)(Ah + (size_t)arows * K + ahalf * 16);
    const int bk = tid >> 3, bseg = tid & 7;
    const char* gB16 = (const char*)(B16 + (size_t)bk * ldB + col0 + bseg * 16);

    const uint32_t ub = s2u(sm);
    const uint32_t aDst = ub + ST_A + am * 80 + ahalf * 32;
    const uint32_t bDst = ub + ST_B + bk * 272 + bseg * 32;

    auto issue = [&](int stage, int c) {
        uint32_t sb = stage * STAGE_BYTES;
        size_t ao = (size_t)c * KC * 2;
        size_t bo = (size_t)c * KC * ldB * 2;
        cpa(aDst + sb,      gA + ao,      apred);
        cpa(aDst + sb + 16, gA + ao + 16, apred);
        cpa(bDst + sb,      gB16 + bo,      16);
        cpa(bDst + sb + 16, gB16 + bo + 16, 16);
        asm volatile("cp.async.commit_group;");
    };

    float acc[16][4];
#pragma unroll
    for (int t = 0; t < 16; t++)
#pragma unroll
        for (int i = 0; i < 4; i++) acc[t][i] = 0.f;

    const int nch = K / KC;
#pragma unroll
    for (int s = 0; s < NST1; s++) issue(s, s);

    for (int c = 0; c < nch; c++) {
        asm volatile("cp.async.wait_group %0;" :: "n"(NST1 - 1));
        __syncthreads();
        uint32_t sb = ub + (c % NST1) * STAGE_BYTES;
        uint32_t uA_ = sb + ST_A;
        uint32_t uB_ = sb + ST_B;
#pragma unroll
        for (int ks = 0; ks < 2; ks++) {
            unsigned b_[2][4];
#pragma unroll
            for (int nt = 0; nt < 2; nt++) {
                int krow = ks * 16 + (lane & 7) + ((lane >> 3) & 1) * 8;
                int ncol = warp_n * 32 + nt * 16 + (lane >> 4) * 8;
                uint32_t o = (uint32_t)(krow * B_STRIDE + ncol) * 2;
                ldm_x4_t(b_[nt], uB_ + o);
            }
#pragma unroll
            for (int mt = 0; mt < 4; mt++) {
                unsigned a_[4];
                int mrow = warp_m * 64 + mt * 16 + (lane & 15);
                int kcol = ks * 16 + (lane >> 4) * 8;
                uint32_t o = (uint32_t)(mrow * A_STRIDE + kcol) * 2;
                ldm_x4(a_, uA_ + o);
#pragma unroll
                for (int nt = 0; nt < 2; nt++)
#pragma unroll
                    for (int j = 0; j < 2; j++)
                        mma16816(acc[mt * 4 + nt * 2 + j], a_, b_[nt] + j * 2);
            }
        }
        __syncthreads();
        if (c + NST1 < nch) issue(c % NST1, c + NST1);
        else asm volatile("cp.async.commit_group;");
    }

    // ---- epilogue ----
    float rs = 0.f;
    if (OP == 4) rs = extra2[e];
#pragma unroll
    for (int mt = 0; mt < 4; mt++)
#pragma unroll
        for (int nt = 0; nt < 2; nt++)
#pragma unroll
            for (int j = 0; j < 2; j++) {
                float* cc = acc[mt * 4 + nt * 2 + j];
                int lcol = warp_n * 32 + nt * 16 + j * 8 + (lane & 3) * 2;
                int gcol = col0 + lcol;
#pragma unroll
                for (int half = 0; half < 2; half++) {
                    int lrow = warp_m * 64 + mt * 16 + (lane >> 2) + half * 8;
                    int gr = row0 + lrow;
                    float v0 = cc[half * 2], v1 = cc[half * 2 + 1];
                    if (OP == 0) {
                        size_t base = (size_t)gr * ND + gcol;
                        *(unsigned*)(Oh + base) = pkh(v0, v1);
                    } else if (OP == 1) {
                        size_t base = (size_t)gr * ND + gcol;
                        float g0 = 1.f / (1.f + expf(-(v0 + bias[gcol])));
                        float g1 = 1.f / (1.f + expf(-(v1 + bias[gcol + 1])));
                        float a0 = __half2float(Ah[base]);
                        float a1 = __half2float(Ah[base + 1]);
                        *(unsigned*)(Oh + base) = pkh(a0 * g0, a1 * g1);
                    } else if (OP == 2) {
                        size_t base = (size_t)gr * ND + gcol;
                        float2 o2;
                        o2.x = extra[base] + v0;
                        o2.y = extra[base + 1] + v1;
                        *(float2*)(Of + base) = o2;
                    } else if (OP == 3) {
                        if (gr < cnt) {
                            size_t base = (size_t)(off + gr) * NF + gcol;
                            float2 o2;
                            o2.x = v0 + bias[e * NF + gcol];
                            o2.y = v1 + bias[e * NF + gcol + 1];
                            *(float2*)(Of + base) = o2;
                        }
                    } else if (OP == 4) {
                        if (gr < cnt) {
                            int t = g_perm[off + gr];
                            size_t bx = (size_t)t * ND + gcol;
                            float2 o2;
                            o2.x = 2.f * extra[bx] + rs * (v0 + bias[e * ND + gcol]);
                            o2.y = 2.f * extra[bx + 1] + rs * (v1 + bias[e * ND + gcol + 1]);
                            *(float2*)(Of + bx) = o2;
                        }
                    }
                }
            }
}

// ---------------- mma.sync flash attention (fp16 single) ----------------------
// z=0 plane: flash attention.  z=1 plane: stream-convert w2 fp32 -> fp16.
__global__ void __launch_bounds__(128, 4) k_flash(const float* __restrict__ w2src)
{
    if (blockIdx.z == 1) {
        size_t cid = (size_t)blockIdx.y * 16 + blockIdx.x;  // 512 CTAs
        size_t base = (cid * 128 + threadIdx.x) * 8;
        size_t stride = (size_t)512 * 128 * 8;
        for (size_t u = base; u < WELEMS; u += stride) cvt8(w2src, g_w216, u);
        return;
    }

    extern __shared__ __align__(16) char fsm[];
    const int tid = threadIdx.x, lane = tid & 31, warpm = tid >> 5;
    const int bh = blockIdx.y, b = bh >> 4, h = bh & 15;
    const int row0 = blockIdx.x * 64;

    const __half* Qg = g_qkv;
    const __half* Kg = g_qkv + (size_t)NT * ND;
    const __half* Vg = g_qkv + (size_t)2 * NT * ND;

    {
        int m = tid >> 1, half = tid & 1;
        float sc = g_scalef[bh * NS + row0 + m];
        const __half* src_ = Qg + (size_t)(b * NS + row0 + m) * ND + h * 64 + half * 32;
        char* dq = fsm + F_Q + m * 144 + half * 64;
#pragma unroll
        for (int i = 0; i < 4; i++) {
            __half qb[8];
            *(uint4*)qb = *(const uint4*)(src_ + i * 8);
            unsigned o4[4];
#pragma unroll
            for (int j = 0; j < 4; j++)
                o4[j] = pkh(__half2float(qb[2 * j]) * sc, __half2float(qb[2 * j + 1]) * sc);
            *(uint4*)(dq + i * 16) = *(uint4*)o4;
        }
    }

    const uint32_t ubase = s2u(fsm);
    const uint32_t uQ = ubase + F_Q, uK = ubase + F_K, uV = ubase + F_V;

    const uint32_t qa_off = ((warpm * 16 + (lane & 15)) * F_STRIDE + ((lane >> 4) & 1) * 8) * 2;
    const uint32_t ka_off = (((lane & 7) + ((lane >> 4) << 3)) * F_STRIDE + ((lane >> 3) & 1) * 8) * 2;
    const uint32_t va_off = (((lane & 7) + ((lane >> 3) & 1) * 8) * F_STRIDE + ((lane >> 4) & 1) * 8) * 2;

    float oacc[8][4];
#pragma unroll
    for (int t = 0; t < 8; t++)
#pragma unroll
        for (int i = 0; i < 4; i++) oacc[t][i] = 0.f;
    float mi0 = -1e30f, mi1 = -1e30f, li0 = 0.f, li1 = 0.f;

    for (int jt = 0; jt < NS / 64; jt++) {
        __syncthreads();
        {
            int m = tid >> 1, half = tid & 1;
            size_t gsrc = (size_t)(b * NS + jt * 64 + m) * ND + h * 64 + half * 32;
            char* dk = fsm + F_K + m * 144 + half * 64;
            char* dv = fsm + F_V + m * 144 + half * 64;
#pragma unroll
            for (int i = 0; i < 4; i++) {
                *(uint4*)(dk + i * 16) = *(const uint4*)((const char*)(Kg + gsrc) + i * 16);
                *(uint4*)(dv + i * 16) = *(const uint4*)((const char*)(Vg + gsrc) + i * 16);
            }
        }
        __syncthreads();

        float sacc[8][4];
#pragma unroll
        for (int t = 0; t < 8; t++)
#pragma unroll
            for (int i = 0; i < 4; i++) sacc[t][i] = 0.f;
#pragma unroll
        for (int ks = 0; ks < 4; ks++) {
            unsigned q4[4];
            ldm_x4(q4, uQ + qa_off + ks * 32);
#pragma unroll
            for (int np = 0; np < 4; np++) {
                unsigned k4[4];
                uint32_t o = ka_off + (uint32_t)(np * 16 * F_STRIDE + ks * 16) * 2;
                ldm_x4(k4, uK + o);
                mma16816(sacc[2 * np],     q4, k4);
                mma16816(sacc[2 * np + 1], q4, k4 + 2);
            }
        }

        float rm0 = -1e30f, rm1 = -1e30f;
#pragma unroll
        for (int j = 0; j < 8; j++) {
            rm0 = fmaxf(rm0, fmaxf(sacc[j][0], sacc[j][1]));
            rm1 = fmaxf(rm1, fmaxf(sacc[j][2], sacc[j][3]));
        }
        rm0 = fmaxf(rm0, __shfl_xor_sync(0xffffffffu, rm0, 1));
        rm0 = fmaxf(rm0, __shfl_xor_sync(0xffffffffu, rm0, 2));
        rm1 = fmaxf(rm1, __shfl_xor_sync(0xffffffffu, rm1, 1));
        rm1 = fmaxf(rm1, __shfl_xor_sync(0xffffffffu, rm1, 2));
        float mn0 = fmaxf(mi0, rm0), mn1 = fmaxf(mi1, rm1);
        float al0 = expf(mi0 - mn0), al1 = expf(mi1 - mn1);
        float rs0 = 0.f, rs1 = 0.f;
#pragma unroll
        for (int j = 0; j < 8; j++) {
            sacc[j][0] = expf(sacc[j][0] - mn0); rs0 += sacc[j][0];
            sacc[j][1] = expf(sacc[j][1] - mn0); rs0 += sacc[j][1];
            sacc[j][2] = expf(sacc[j][2] - mn1); rs1 += sacc[j][2];
            sacc[j][3] = expf(sacc[j][3] - mn1); rs1 += sacc[j][3];
        }
        rs0 += __shfl_xor_sync(0xffffffffu, rs0, 1);
        rs0 += __shfl_xor_sync(0xffffffffu, rs0, 2);
        rs1 += __shfl_xor_sync(0xffffffffu, rs1, 1);
        rs1 += __shfl_xor_sync(0xffffffffu, rs1, 2);
        li0 = li0 * al0 + rs0; li1 = li1 * al1 + rs1;
        mi0 = mn0; mi1 = mn1;
#pragma unroll
        for (int t = 0; t < 8; t++) {
            oacc[t][0] *= al0; oacc[t][1] *= al0;
            oacc[t][2] *= al1; oacc[t][3] *= al1;
        }

#pragma unroll
        for (int kb = 0; kb < 4; kb++) {
            unsigned pa[4];
            pa[0] = pkh(sacc[2 * kb][0],     sacc[2 * kb][1]);
            pa[1] = pkh(sacc[2 * kb][2],     sacc[2 * kb][3]);
            pa[2] = pkh(sacc[2 * kb + 1][0], sacc[2 * kb + 1][1]);
            pa[3] = pkh(sacc[2 * kb + 1][2], sacc[2 * kb + 1][3]);
#pragma unroll
            for (int ndp = 0; ndp < 4; ndp++) {
                unsigned v4[4];
                uint32_t o = va_off + (uint32_t)(kb * 16 * F_STRIDE + ndp * 16) * 2;
                ldm_x4_t(v4, uV + o);
                mma16816(oacc[2 * ndp],     pa, v4);
                mma16816(oacc[2 * ndp + 1], pa, v4 + 2);
            }
        }
    }

    float inv0 = 1.f / li0, inv1 = 1.f / li1;
    int r = row0 + warpm * 16 + (lane >> 2);
    int cbase = h * 64 + (lane & 3) * 2;
#pragma unroll
    for (int dt = 0; dt < 8; dt++) {
        size_t idx = (size_t)(b * NS + r) * ND + cbase + dt * 8;
        *(unsigned*)(g_a16 + idx) = pkh(oacc[dt][0] * inv0, oacc[dt][1] * inv0);
        idx += (size_t)8 * ND;
        *(unsigned*)(g_a16 + idx) = pkh(oacc[dt][2] * inv1, oacc[dt][3] * inv1);
    }
}

// ---------------- reductions --------------------------------------------------
__device__ __forceinline__ void blk_reduce2(float& s, float& q)
{
    __shared__ float ss[8], sq[8];
#pragma unroll
    for (int o = 16; o; o >>= 1) {
        s += __shfl_xor_sync(0xffffffffu, s, o);
        q += __shfl_xor_sync(0xffffffffu, q, o);
    }
    int w = threadIdx.x >> 5, l = threadIdx.x & 31;
    if (l == 0) { ss[w] = s; sq[w] = q; }
    __syncthreads();
    s = (l < 8) ? ss[l] : 0.f;
    q = (l < 8) ? sq[l] : 0.f;
#pragma unroll
    for (int o = 4; o; o >>= 1) {
        s += __shfl_xor_sync(0xffffffffu, s, o);
        q += __shfl_xor_sync(0xffffffffu, q, o);
    }
    s = __shfl_sync(0xffffffffu, s, 0);
    q = __shfl_sync(0xffffffffu, q, 0);
}

// ---------------- conversions -------------------------------------------------
// small: src(2M) + qw/kw/vw(3M) + gate_w(1M) + ow(1M) = 7M elems
__global__ __launch_bounds__(256) void k_cvt_small(
    const float* __restrict__ src, const float* __restrict__ qw,
    const float* __restrict__ kw, const float* __restrict__ vw,
    const float* __restrict__ gw, const float* __restrict__ ow)
{
    size_t u = ((size_t)blockIdx.x * 256 + threadIdx.x) * 8;
    const size_t M = (size_t)ND * ND;  // 1M
    if (u < 2 * M) {
        cvt8(src, g_s16, u);
    } else if (u < 5 * M) {
        size_t v = u - 2 * M;
        if (v < M) cvt8(qw, g_wqkv, v);
        else if (v < 2 * M) cvt8(kw, g_wqkv + M, v - M);
        else cvt8(vw, g_wqkv + 2 * M, v - 2 * M);
    } else if (u < 6 * M) {
        cvt8(gw, g_wg, u - 5 * M);
    } else {
        cvt8(ow, g_wo, u - 6 * M);
    }
}

// ---------------- elementwise -------------------------------------------------
__global__ __launch_bounds__(256) void k_qscale(const float* __restrict__ sw)
{
    int wid = blockIdx.x * 8 + (threadIdx.x >> 5);
    int lane = threadIdx.x & 31;
    int h = wid & (NH - 1), t = wid >> 4;
    size_t i0 = (size_t)t * ND + h * 64 + lane;
    float q0 = __half2float(g_qkv[i0]);
    float q1 = __half2float(g_qkv[i0 + 32]);
    float s = q0 * sw[h * 64 + lane] + q1 * sw[h * 64 + lane + 32];
#pragma unroll
    for (int o = 16; o; o >>= 1) s += __shfl_xor_sync(0xffffffffu, s, o);
    if (lane == 0) {
        float sig = 1.f / (1.f + expf(-s));
        int b = t >> 10, si = t & (NS - 1);
        g_scalef[(b * NH + h) * NS + si] = 0.25f * sig;
    }
}

__global__ __launch_bounds__(256) void k_ln1(const float* __restrict__ g,
                                             const float* __restrict__ b)
{
    size_t r = blockIdx.x;
    const float* in = g_xres + r * ND;
    float x[4];
    float s = 0.f, q = 0.f;
#pragma unroll
    for (int l = 0; l < 4; l++) {
        x[l] = in[threadIdx.x + l * 256];
        s += x[l]; q += x[l] * x[l];
    }
    blk_reduce2(s, q);
    float mean = s * (1.f / ND);
    float var = q * (1.f / ND) - mean * mean;
    float rstd = rsqrtf(var + 1e-5f);
#pragma unroll
    for (int l = 0; l < 4; l++) {
        int c = threadIdx.x + l * 256;
        float v = (x[l] - mean) * rstd * g[c] + b[c];
        g_x[r * ND + c] = v;
        g_x16[r * ND + c] = __float2half_rn(v);
    }
}

__global__ __launch_bounds__(256) void k_ln_out(const float* __restrict__ g,
                                                const float* __restrict__ b,
                                                float* __restrict__ out)
{
    size_t r = blockIdx.x;
    const float* in = g_z + r * ND;
    float x[4];
    float s = 0.f, q = 0.f;
#pragma unroll
    for (int l = 0; l < 4; l++) {
        x[l] = in[threadIdx.x + l * 256];
        s += x[l]; q += x[l] * x[l];
    }
    blk_reduce2(s, q);
    float mean = s * (1.f / ND);
    float var = q * (1.f / ND) - mean * mean;
    float rstd = rsqrtf(var + 1e-5f);
#pragma unroll
    for (int l = 0; l < 4; l++) {
        int c = threadIdx.x + l * 256;
        out[r * ND + c] = (x[l] - mean) * rstd * g[c] + b[c];
    }
}

__global__ __launch_bounds__(256) void k_route(const float* __restrict__ gw,
                                               const float* __restrict__ gb)
{
    __shared__ float lg[NE];
    int t = blockIdx.x;
    int w = threadIdx.x >> 5, lane = threadIdx.x & 31;
    const float* x = g_x + (size_t)t * ND;
    float s = 0.f;
    for (int d = lane; d < ND; d += 32) s += x[d] * gw[d * NE + w];
#pragma unroll
    for (int o = 16; o; o >>= 1) s += __shfl_xor_sync(0xffffffffu, s, o);
    if (lane == 0) lg[w] = s + gb[w];
    __syncthreads();
    if (threadIdx.x == 0) {
        int i1 = 0; float v1 = lg[0];
#pragma unroll
        for (int e = 1; e < NE; e++) if (lg[e] > v1) { v1 = lg[e]; i1 = e; }
        int i2 = -1; float v2 = -1e30f;
#pragma unroll
        for (int e = 0; e < NE; e++) if (e != i1 && lg[e] > v2) { v2 = lg[e]; i2 = e; }
        g_esel[t] = (i1 > i2) ? i1 : i2;
    }
}

__global__ void k_scatter()
{
    __shared__ int scnt[NE], soff[NE], scur[NE];
    int tid = threadIdx.x;
    if (tid < NE) scnt[tid] = 0;
    __syncthreads();
    for (int t = tid; t < NT; t += 1024) atomicAdd(&scnt[g_esel[t]], 1);
    __syncthreads();
    if (tid == 0) {
        int r = 0;
        for (int e = 0; e < NE; e++) { soff[e] = r; r += scnt[e]; }
    }
    __syncthreads();
    if (tid < NE) { scur[tid] = soff[tid]; g_off[tid] = soff[tid]; g_cnt[tid] = scnt[tid]; }
    __syncthreads();
    for (int t = tid; t < NT; t += 1024) {
        int e = g_esel[t];
        int pos = atomicAdd(&scur[e], 1);
        g_perm[pos] = t;
        g_eid[pos] = e;
    }
}

__global__ __launch_bounds__(256) void k_lngelu(const float* __restrict__ lng,
                                                const float* __restrict__ lnb)
{
    int row = blockIdx.x;
    int e = g_eid[row];
    const float* hp = g_h + (size_t)row * NF;
    float x[16];
    float s = 0.f, q = 0.f;
#pragma unroll
    for (int l = 0; l < 16; l++) {
        x[l] = hp[threadIdx.x + l * 256];
        s += x[l]; q += x[l] * x[l];
    }
    blk_reduce2(s, q);
    float mean = s * (1.f / NF);
    float var = q * (1.f / NF) - mean * mean;
    float rstd = rsqrtf(var + 1e-5f);
    const float* g = lng + (size_t)e * NF;
    const float* b = lnb + (size_t)e * NF;
#pragma unroll
    for (int l = 0; l < 16; l++) {
        int c = threadIdx.x + l * 256;
        float hn = (x[l] - mean) * rstd * g[c] + b[c];
        float gel = 0.5f * hn * (1.f + erff(hn * 0.70710678118654752f));
        g_h16[(size_t)row * NF + c] = __float2half_rn(gel);
    }
}

// ---------------- launch ------------------------------------------------------
extern "C" void kernel_launch(void* const* d_in, const int* in_sizes, int n_in,
                              void* d_out, int out_size)
{
    (void)in_sizes; (void)n_in; (void)out_size;
    const float* src        = (const float*)d_in[0];
    const float* qw         = (const float*)d_in[1];
    const float* kw         = (const float*)d_in[2];
    const float* vw         = (const float*)d_in[3];
    const float* ow         = (const float*)d_in[4];
    const float* gate_w     = (const float*)d_in[5];
    const float* gate_b     = (const float*)d_in[6];
    const float* scale_w    = (const float*)d_in[7];
    const float* n1_g       = (const float*)d_in[8];
    const float* n1_b       = (const float*)d_in[9];
    const float* n2_g       = (const float*)d_in[10];
    const float* n2_b       = (const float*)d_in[11];
    const float* moe_gate_w = (const float*)d_in[12];
    const float* moe_gate_b = (const float*)d_in[13];
    const float* w1         = (const float*)d_in[14];
    const float* b1         = (const float*)d_in[15];
    const float* ln_g       = (const float*)d_in[16];
    const float* ln_b       = (const float*)d_in[17];
    const float* w2         = (const float*)d_in[18];
    const float* b2         = (const float*)d_in[19];
    const float* res_scale  = (const float*)d_in[20];
    float* out = (float*)d_out;

    cudaFuncSetAttribute((const void*)k_mm<0>, cudaFuncAttributeMaxDynamicSharedMemorySize, GEMM_SMEM);
    cudaFuncSetAttribute((const void*)k_mm<1>, cudaFuncAttributeMaxDynamicSharedMemorySize, GEMM_SMEM);
    cudaFuncSetAttribute((const void*)k_mm<2>, cudaFuncAttributeMaxDynamicSharedMemorySize, GEMM_SMEM);
    cudaFuncSetAttribute((const void*)k_mm<3>, cudaFuncAttributeMaxDynamicSharedMemorySize, GEMM_SMEM);
    cudaFuncSetAttribute((const void*)k_mm<4>, cudaFuncAttributeMaxDynamicSharedMemorySize, GEMM_SMEM);
    cudaFuncSetAttribute((const void*)k_flash, cudaFuncAttributeMaxDynamicSharedMemorySize, FLASH_SMEM);

    __half *s16, *qkv, *a16, *g16, *x16, *h16, *wqkv, *wg, *wo, *w116, *w216;
    float *xres, *x, *z, *hbuf;
    cudaGetSymbolAddress((void**)&s16, g_s16);
    cudaGetSymbolAddress((void**)&qkv, g_qkv);
    cudaGetSymbolAddress((void**)&a16, g_a16);
    cudaGetSymbolAddress((void**)&g16, g_g16);
    cudaGetSymbolAddress((void**)&x16, g_x16);
    cudaGetSymbolAddress((void**)&h16, g_h16);
    cudaGetSymbolAddress((void**)&wqkv, g_wqkv);
    cudaGetSymbolAddress((void**)&wg, g_wg);
    cudaGetSymbolAddress((void**)&wo, g_wo);
    cudaGetSymbolAddress((void**)&w116, g_w116);
    cudaGetSymbolAddress((void**)&w216, g_w216);
    cudaGetSymbolAddress((void**)&xres, g_xres);
    cudaGetSymbolAddress((void**)&x, g_x);
    cudaGetSymbolAddress((void**)&z, g_z);
    cudaGetSymbolAddress((void**)&hbuf, g_h);

    // small conversions (src + attention weights)
    k_cvt_small<<<7 * 1024 * 1024 / 2048, 256>>>(src, qw, kw, vw, gate_w, ow);

    // merged QKV GEMM (z=0..2) + w1 convert plane (z=3, reads `extra`=w1)
    k_mm<0><<<dim3(ND / TN, NT / TM, 4), 256, GEMM_SMEM>>>(s16, wqkv,
        ND, ND, nullptr, w1, nullptr, qkv, nullptr);
    k_qscale<<<(NT * NH) / 8, 256>>>(scale_w);
    // flash (z=0) + w2 convert plane (z=1)
    k_flash<<<dim3(NS / 64, NB * NH, 2), 128, FLASH_SMEM>>>(w2);
    k_mm<1><<<dim3(ND / TN, NT / TM), 256, GEMM_SMEM>>>(a16, wg,
        ND, ND, gate_b, nullptr, nullptr, g16, nullptr);
    k_mm<2><<<dim3(ND / TN, NT / TM), 256, GEMM_SMEM>>>(g16, wo,
        ND, ND, nullptr, src, nullptr, nullptr, xres);
    k_ln1<<<NT, 256>>>(n1_g, n1_b);
    k_route<<<NT, 256>>>(moe_gate_w, moe_gate_b);
    k_scatter<<<1, 1024>>>();
    k_mm<3><<<dim3(NF / TN, NT / TM, NE), 256, GEMM_SMEM>>>(x16, w116,
        ND, NF, b1, nullptr, nullptr, nullptr, hbuf);
    k_lngelu<<<NT, 256>>>(ln_g, ln_b);
    k_mm<4><<<dim3(ND / TN, NT / TM, NE), 256, GEMM_SMEM>>>(h16, w216,
        NF, ND, b2, x, res_scale, nullptr, z);
    k_ln_out<<<NT, 256>>>(n2_g, n2_b, out);
}